// round 9
// baseline (speedup 1.0000x reference)
#include <cuda_runtime.h>
#include <cuda_bf16.h>
#include <cstdint>

// Problem constants
constexpr int NB   = 2;      // batch
constexpr int SEQ  = 2048;   // sequence
constexpr int HDIM = 2560;   // hidden
constexpr int NH   = 32;     // q heads
constexpr int NKV  = 8;      // kv heads
constexpr int HD   = 128;    // head dim
constexpr int GQ   = NH / NKV;
constexpr int MROWS = NB * SEQ;            // 4096
constexpr int NQKV  = (NH + 2 * NKV) * HD; // 6144
constexpr int KOFF  = NH * HD;             // 4096
constexpr int VOFF  = (NH + NKV) * HD;     // 5120
constexpr float SM_SCALE = 0.08838834764831845f;  // 1/sqrt(128)

// ---------------- device scratch (no allocation allowed) ----------------
__device__ __nv_bfloat16 g_hid_h [(size_t)MROWS * HDIM];
__device__ __nv_bfloat16 g_hid_l [(size_t)MROWS * HDIM];
__device__ __nv_bfloat16 g_wqkv_h[(size_t)NQKV * HDIM];
__device__ __nv_bfloat16 g_wqkv_l[(size_t)NQKV * HDIM];
__device__ __nv_bfloat16 g_wo_h  [(size_t)HDIM * NH * HD];
__device__ __nv_bfloat16 g_wo_l  [(size_t)HDIM * NH * HD];
__device__ __nv_bfloat16 g_ao_h  [(size_t)MROWS * NH * HD];
__device__ __nv_bfloat16 g_ao_l  [(size_t)MROWS * NH * HD];
__device__ float g_qkv[(size_t)MROWS * NQKV];       // 96MB
// bf16 hi/lo attention operands
__device__ __nv_bfloat16 g_qh[(size_t)NB * NH  * SEQ * HD];  // (b,H,s,D), pre-scaled
__device__ __nv_bfloat16 g_ql[(size_t)NB * NH  * SEQ * HD];
__device__ __nv_bfloat16 g_kh[(size_t)NB * NKV * SEQ * HD];  // (b,KV,s,D)
__device__ __nv_bfloat16 g_kl[(size_t)NB * NKV * SEQ * HD];
__device__ __nv_bfloat16 g_vh[(size_t)NB * NKV * HD * SEQ];  // (b,KV,D,s) transposed
__device__ __nv_bfloat16 g_vl[(size_t)NB * NKV * HD * SEQ];

// ---------------------------------------------------------------------------
// cp.async / ldmatrix helpers
// ---------------------------------------------------------------------------
__device__ __forceinline__ void cp16(uint32_t smem, const __nv_bfloat16* gmem)
{
    asm volatile("cp.async.cg.shared.global [%0], [%1], 16;\n" :: "r"(smem), "l"(gmem));
}
#define CP_COMMIT() asm volatile("cp.async.commit_group;\n" ::: "memory")
#define CP_WAIT(n)  asm volatile("cp.async.wait_group %0;\n" :: "n"(n) : "memory")

__device__ __forceinline__ void ldsm4(uint32_t* r, const __nv_bfloat16* p)
{
    uint32_t a = (uint32_t)__cvta_generic_to_shared(p);
    asm volatile("ldmatrix.sync.aligned.m8n8.x4.shared.b16 {%0,%1,%2,%3}, [%4];"
        : "=r"(r[0]), "=r"(r[1]), "=r"(r[2]), "=r"(r[3]) : "r"(a));
}

// ---------------------------------------------------------------------------
// fp32 -> bf16 hi/lo split
// ---------------------------------------------------------------------------
__global__ __launch_bounds__(256) void split_bf16(
    const float4* __restrict__ in, __nv_bfloat16* __restrict__ hi,
    __nv_bfloat16* __restrict__ lo)
{
    const size_t i = (size_t)blockIdx.x * 256 + threadIdx.x;
    float4 x = in[i];
    __nv_bfloat16 h[4], l[4];
    float xs[4] = {x.x, x.y, x.z, x.w};
#pragma unroll
    for (int j = 0; j < 4; j++) {
        h[j] = __float2bfloat16(xs[j]);
        l[j] = __float2bfloat16(xs[j] - __bfloat162float(h[j]));
    }
    *(uint2*)&hi[i * 4] = *(uint2*)h;
    *(uint2*)&lo[i * 4] = *(uint2*)l;
}

// ---------------------------------------------------------------------------
// mma.m16n8k16 bf16 wrapper
// ---------------------------------------------------------------------------
__device__ __forceinline__ void mma16816(float* c, const uint32_t* a, const uint32_t* b)
{
    asm volatile(
        "mma.sync.aligned.m16n8k16.row.col.f32.bf16.bf16.f32 "
        "{%0,%1,%2,%3}, {%4,%5,%6,%7}, {%8,%9}, {%0,%1,%2,%3};"
        : "+f"(c[0]), "+f"(c[1]), "+f"(c[2]), "+f"(c[3])
        : "r"(a[0]), "r"(a[1]), "r"(a[2]), "r"(a[3]), "r"(b[0]), "r"(b[1]));
}

__device__ __forceinline__ uint32_t pack_hilo(float x, float y, uint32_t& lo)
{
    __nv_bfloat162 h = __float22bfloat162_rn(make_float2(x, y));
    float rx = x - __bfloat162float(h.x);
    float ry = y - __bfloat162float(h.y);
    __nv_bfloat162 l = __float22bfloat162_rn(make_float2(rx, ry));
    lo = *(uint32_t*)&l;
    return *(uint32_t*)&h;
}

// ---------------------------------------------------------------------------
// bf16-split tensor-core GEMM: C[M,N] = A[M,K] @ B[N,K]^T   (fp32 accurate)
// CTA tile 256x128, BK=32, 2-stage cp.async pipeline, one sync/iteration.
// 256 threads = 8 warps (4 in M x 2 in N; 64x64 warp tile).
// ---------------------------------------------------------------------------
constexpr int GPAD  = 40;                     // smem row pitch (bf16): 80B, ldsm conflict-free
constexpr int GSA   = 256 * GPAD;             // A matrix bf16 per stage (10240)
constexpr int GSB   = 128 * GPAD;             // B matrix bf16 per stage (5120)
constexpr int GSTG  = 2 * GSA + 2 * GSB;      // stage size in bf16 (30720)
constexpr int GEMM_SMEM = 2 * GSTG * 2;       // 122880 bytes

__global__ __launch_bounds__(256, 1) void gemm_bf16x2(
    const __nv_bfloat16* __restrict__ Ah, const __nv_bfloat16* __restrict__ Al,
    const __nv_bfloat16* __restrict__ Bh, const __nv_bfloat16* __restrict__ Bl,
    float* __restrict__ C, int M, int N, int K)
{
    extern __shared__ __nv_bfloat16 sb[];

    const int tid = threadIdx.x;
    const int bm = blockIdx.y * 256;
    const int bn = blockIdx.x * 128;
    const int lane = tid & 31;
    const int wid  = tid >> 5;
    const int wm = (wid & 3) * 64;   // warp M offset (4 warps in M)
    const int wn = (wid >> 2) * 64;  // warp N offset (2 warps in N)
    const int grp = lane >> 2;
    const int tig = lane & 3;

    // ldmatrix lane->address components
    const int lrow  = lane & 15;
    const int lcoff = (lane >> 4) * 8;
    const int brow  = (lane & 7) + ((lane >> 4) << 3);
    const int bcoff = ((lane >> 3) & 1) * 8;

    // copy geometry: A 256x32 -> 1024 chunks (4/thread), B 128x32 -> 512 (2/thread)
    uint32_t soffA[4], soffB[2];
    int growA[4], gcolA[4], growB[2], gcolB[2];
#pragma unroll
    for (int j = 0; j < 4; j++) {
        int c = tid + j * 256;
        growA[j] = c >> 2;
        gcolA[j] = (c & 3) * 8;
        soffA[j] = (uint32_t)(growA[j] * GPAD + gcolA[j]);
    }
#pragma unroll
    for (int j = 0; j < 2; j++) {
        int c = tid + j * 256;
        growB[j] = c >> 2;
        gcolB[j] = (c & 3) * 8;
        soffB[j] = (uint32_t)(growB[j] * GPAD + gcolB[j]);
    }

    float acc[4][8][4];
#pragma unroll
    for (int mt = 0; mt < 4; mt++)
#pragma unroll
        for (int nt = 0; nt < 8; nt++)
#pragma unroll
            for (int e = 0; e < 4; e++) acc[mt][nt][e] = 0.f;

    uint32_t sbase = (uint32_t)__cvta_generic_to_shared(sb);
    const int nk = K / 32;

    // prologue: stage 0  (layout per stage: Ah | Al | Bh | Bl)
#pragma unroll
    for (int j = 0; j < 4; j++) {
        cp16(sbase + (0 * GSA + soffA[j]) * 2, Ah + (size_t)(bm + growA[j]) * K + gcolA[j]);
        cp16(sbase + (1 * GSA + soffA[j]) * 2, Al + (size_t)(bm + growA[j]) * K + gcolA[j]);
    }
#pragma unroll
    for (int j = 0; j < 2; j++) {
        cp16(sbase + (2 * GSA + 0 * GSB + soffB[j]) * 2, Bh + (size_t)(bn + growB[j]) * K + gcolB[j]);
        cp16(sbase + (2 * GSA + 1 * GSB + soffB[j]) * 2, Bl + (size_t)(bn + growB[j]) * K + gcolB[j]);
    }
    CP_COMMIT();

    for (int i = 0; i < nk; i++) {
        const __nv_bfloat16* cur = sb + (size_t)(i & 1) * GSTG;

        CP_WAIT(0);
        __syncthreads();

        if (i + 1 < nk) {
            const uint32_t nxt = sbase + (uint32_t)(((i + 1) & 1) * GSTG) * 2;
            const int k0 = (i + 1) * 32;
#pragma unroll
            for (int j = 0; j < 4; j++) {
                cp16(nxt + (0 * GSA + soffA[j]) * 2, Ah + (size_t)(bm + growA[j]) * K + k0 + gcolA[j]);
                cp16(nxt + (1 * GSA + soffA[j]) * 2, Al + (size_t)(bm + growA[j]) * K + k0 + gcolA[j]);
            }
#pragma unroll
            for (int j = 0; j < 2; j++) {
                cp16(nxt + (2 * GSA + 0 * GSB + soffB[j]) * 2, Bh + (size_t)(bn + growB[j]) * K + k0 + gcolB[j]);
                cp16(nxt + (2 * GSA + 1 * GSB + soffB[j]) * 2, Bl + (size_t)(bn + growB[j]) * K + k0 + gcolB[j]);
            }
            CP_COMMIT();
        }

        const __nv_bfloat16* sAh = cur;
        const __nv_bfloat16* sAl = cur + GSA;
        const __nv_bfloat16* sBh = cur + 2 * GSA;
        const __nv_bfloat16* sBl = cur + 2 * GSA + GSB;

#pragma unroll
        for (int kk = 0; kk < 32; kk += 16) {
            uint32_t afh[4][4], afl[4][4];
            const int acol = kk + lcoff;
#pragma unroll
            for (int mt = 0; mt < 4; mt++) {
                ldsm4(afh[mt], &sAh[(wm + mt * 16 + lrow) * GPAD + acol]);
                ldsm4(afl[mt], &sAl[(wm + mt * 16 + lrow) * GPAD + acol]);
            }
#pragma unroll
            for (int np = 0; np < 4; np++) {
                const int br = wn + np * 16 + brow;
                const int bc = kk + bcoff;
                uint32_t bh[4], bl[4];
                ldsm4(bh, &sBh[br * GPAD + bc]);
                ldsm4(bl, &sBl[br * GPAD + bc]);
#pragma unroll
                for (int mt = 0; mt < 4; mt++) {
                    mma16816(acc[mt][2 * np    ], afh[mt], bh);
                    mma16816(acc[mt][2 * np    ], afh[mt], bl);
                    mma16816(acc[mt][2 * np    ], afl[mt], bh);
                    mma16816(acc[mt][2 * np + 1], afh[mt], bh + 2);
                    mma16816(acc[mt][2 * np + 1], afh[mt], bl + 2);
                    mma16816(acc[mt][2 * np + 1], afl[mt], bh + 2);
                }
            }
        }
    }

#pragma unroll
    for (int mt = 0; mt < 4; mt++) {
        const int row = bm + wm + mt * 16 + grp;
#pragma unroll
        for (int nt = 0; nt < 8; nt++) {
            const int col = bn + wn + nt * 8 + tig * 2;
            *(float2*)&C[(size_t)row * N + col]       = make_float2(acc[mt][nt][0], acc[mt][nt][1]);
            *(float2*)&C[(size_t)(row + 8) * N + col] = make_float2(acc[mt][nt][2], acc[mt][nt][3]);
        }
    }
}

// ---------------------------------------------------------------------------
// RMSNorm + RoPE for Q: reads qkv fp32, writes bf16 hi/lo to (b,H,s,D),
// pre-scaled by 1/sqrt(D). One warp per row.
// ---------------------------------------------------------------------------
__global__ __launch_bounds__(256) void norm_rope_q(
    const float* __restrict__ qkv,
    __nv_bfloat16* __restrict__ oh, __nv_bfloat16* __restrict__ ol,
    const float* __restrict__ cs, const float* __restrict__ sn,
    const float* __restrict__ gamma)
{
    const int warp = (blockIdx.x * 256 + threadIdx.x) >> 5;
    const int lane = threadIdx.x & 31;
    const int h  = warp % NH;
    const int bs = warp / NH;
    const int sp = bs % SEQ;
    const int bi = bs / SEQ;

    const float* x = qkv + (size_t)bs * NQKV + h * HD;
    float e0 = x[lane], e1 = x[lane + 32], e2 = x[lane + 64], e3 = x[lane + 96];

    float ssq = e0 * e0 + e1 * e1 + e2 * e2 + e3 * e3;
#pragma unroll
    for (int o = 16; o; o >>= 1) ssq += __shfl_xor_sync(0xffffffffu, ssq, o);
    const float r = rsqrtf(ssq * (1.0f / HD) + 1e-6f);

    e0 *= r * gamma[lane];      e1 *= r * gamma[lane + 32];
    e2 *= r * gamma[lane + 64]; e3 *= r * gamma[lane + 96];

    const float* cp = cs + (size_t)bs * HD;
    const float* sg = sn + (size_t)bs * HD;
    float o4[4];
    o4[0] = (e0 * cp[lane]      - e2 * sg[lane])      * SM_SCALE;
    o4[1] = (e1 * cp[lane + 32] - e3 * sg[lane + 32]) * SM_SCALE;
    o4[2] = (e2 * cp[lane + 64] + e0 * sg[lane + 64]) * SM_SCALE;
    o4[3] = (e3 * cp[lane + 96] + e1 * sg[lane + 96]) * SM_SCALE;

    const size_t ob = (((size_t)bi * NH + h) * SEQ + sp) * HD;
#pragma unroll
    for (int j = 0; j < 4; j++) {
        __nv_bfloat16 hv = __float2bfloat16(o4[j]);
        oh[ob + lane + 32 * j] = hv;
        ol[ob + lane + 32 * j] = __float2bfloat16(o4[j] - __bfloat162float(hv));
    }
}

// ---------------------------------------------------------------------------
// RMSNorm + RoPE for K: writes fp32 (b,KV,s,D) into d_out AND bf16 hi/lo.
// ---------------------------------------------------------------------------
__global__ __launch_bounds__(256) void norm_rope_k(
    const float* __restrict__ qkv, float* __restrict__ kout,
    __nv_bfloat16* __restrict__ oh, __nv_bfloat16* __restrict__ ol,
    const float* __restrict__ cs, const float* __restrict__ sn,
    const float* __restrict__ gamma)
{
    const int warp = (blockIdx.x * 256 + threadIdx.x) >> 5;
    const int lane = threadIdx.x & 31;
    const int h  = warp % NKV;
    const int bs = warp / NKV;
    const int sp = bs % SEQ;
    const int bi = bs / SEQ;

    const float* x = qkv + (size_t)bs * NQKV + KOFF + h * HD;
    float e0 = x[lane], e1 = x[lane + 32], e2 = x[lane + 64], e3 = x[lane + 96];

    float ssq = e0 * e0 + e1 * e1 + e2 * e2 + e3 * e3;
#pragma unroll
    for (int o = 16; o; o >>= 1) ssq += __shfl_xor_sync(0xffffffffu, ssq, o);
    const float r = rsqrtf(ssq * (1.0f / HD) + 1e-6f);

    e0 *= r * gamma[lane];      e1 *= r * gamma[lane + 32];
    e2 *= r * gamma[lane + 64]; e3 *= r * gamma[lane + 96];

    const float* cp = cs + (size_t)bs * HD;
    const float* sg = sn + (size_t)bs * HD;
    float o4[4];
    o4[0] = e0 * cp[lane]      - e2 * sg[lane];
    o4[1] = e1 * cp[lane + 32] - e3 * sg[lane + 32];
    o4[2] = e2 * cp[lane + 64] + e0 * sg[lane + 64];
    o4[3] = e3 * cp[lane + 96] + e1 * sg[lane + 96];

    const size_t ob = (((size_t)bi * NKV + h) * SEQ + sp) * HD;
#pragma unroll
    for (int j = 0; j < 4; j++) {
        kout[ob + lane + 32 * j] = o4[j];
        __nv_bfloat16 hv = __float2bfloat16(o4[j]);
        oh[ob + lane + 32 * j] = hv;
        ol[ob + lane + 32 * j] = __float2bfloat16(o4[j] - __bfloat162float(hv));
    }
}

// ---------------------------------------------------------------------------
// V transpose (fp32): qkv V region -> (b,KV,s,D) in d_out
// ---------------------------------------------------------------------------
__global__ __launch_bounds__(256) void v_transpose(
    const float4* __restrict__ qkv4, float4* __restrict__ out)
{
    const size_t i = (size_t)blockIdx.x * 256 + threadIdx.x;
    const int d4 = (int)(i & 31);
    const int kh = (int)((i >> 5) & (NKV - 1));
    const int sp = (int)((i >> 8) & (SEQ - 1));
    const int bi = (int)(i >> 19);
    const size_t src = ((size_t)(bi * SEQ + sp) * NQKV + VOFF + kh * HD) / 4 + d4;
    const size_t dst = (((size_t)bi * NKV + kh) * SEQ + sp) * 32 + d4;
    out[dst] = qkv4[src];
}

// ---------------------------------------------------------------------------
// V transpose + split (bf16): qkv V region -> (b,KV,D,s) hi/lo
// ---------------------------------------------------------------------------
__global__ void vtrans_split(
    const float* __restrict__ qkv,
    __nv_bfloat16* __restrict__ vh, __nv_bfloat16* __restrict__ vl)
{
    __shared__ float t[32][33];
    const int s0 = blockIdx.x * 32, d0 = blockIdx.y * 32;
    const int bz = blockIdx.z;                 // bi*NKV + kh
    const int bi = bz / NKV, kh = bz % NKV;
    const int tx = threadIdx.x, ty = threadIdx.y;

#pragma unroll
    for (int j = 0; j < 4; j++) {
        int s = s0 + ty + j * 8;
        t[ty + j * 8][tx] =
            qkv[(size_t)(bi * SEQ + s) * NQKV + VOFF + kh * HD + d0 + tx];
    }
    __syncthreads();
#pragma unroll
    for (int j = 0; j < 4; j++) {
        int d = d0 + ty + j * 8;
        float v = t[tx][ty + j * 8];
        __nv_bfloat16 hv = __float2bfloat16(v);
        size_t idx = ((size_t)bz * HD + d) * SEQ + s0 + tx;
        vh[idx] = hv;
        vl[idx] = __float2bfloat16(v - __bfloat162float(hv));
    }
}

// ---------------------------------------------------------------------------
// Tensor-core causal flash attention, bf16 hi/lo split, ldmatrix loads.
// BM=128, BN=64, 256 threads (8 warps, 16 Q rows each). Halves K/V traffic.
// ---------------------------------------------------------------------------
constexpr int FQP = 136;  // pitch (bf16) for Q/K tiles
constexpr int FVP = 72;   // pitch (bf16) for Vt tiles
constexpr int FLASH_SMEM = (2 * 128 * FQP + 2 * 64 * FQP + 2 * 128 * FVP) * 2;  // 141312 B

__global__ __launch_bounds__(256, 1) void flash_mma(
    const __nv_bfloat16* __restrict__ Qh, const __nv_bfloat16* __restrict__ Ql,
    const __nv_bfloat16* __restrict__ Kh, const __nv_bfloat16* __restrict__ Kl,
    const __nv_bfloat16* __restrict__ Vh, const __nv_bfloat16* __restrict__ Vl,
    __nv_bfloat16* __restrict__ Oh, __nv_bfloat16* __restrict__ Ol)
{
    extern __shared__ __nv_bfloat16 sm[];
    __nv_bfloat16* sQh = sm;
    __nv_bfloat16* sQl = sQh + 128 * FQP;
    __nv_bfloat16* sKh = sQl + 128 * FQP;
    __nv_bfloat16* sKl = sKh + 64 * FQP;
    __nv_bfloat16* sVh = sKl + 64 * FQP;
    __nv_bfloat16* sVl = sVh + 128 * FVP;

    const int qtile = blockIdx.x;
    const int h     = blockIdx.y;
    const int bi    = blockIdx.z;
    const int kh    = h / GQ;
    const int tid   = threadIdx.x;
    const int lane  = tid & 31;
    const int wid   = tid >> 5;
    const int grp   = lane >> 2;
    const int tig   = lane & 3;
    const int q0    = qtile * 128;

    const int lrow  = lane & 15;
    const int lcoff = (lane >> 4) * 8;
    const int brow  = (lane & 7) + ((lane >> 4) << 3);
    const int bcoff = ((lane >> 3) & 1) * 8;

    {
        const __nv_bfloat16* qgh = Qh + (((size_t)bi * NH + h) * SEQ + q0) * HD;
        const __nv_bfloat16* qgl = Ql + (((size_t)bi * NH + h) * SEQ + q0) * HD;
        for (int i = tid; i < 128 * 16; i += 256) {
            int r = i >> 4, c = (i & 15) * 8;
            *(uint4*)&sQh[r * FQP + c] = *(const uint4*)&qgh[(size_t)r * HD + c];
            *(uint4*)&sQl[r * FQP + c] = *(const uint4*)&qgl[(size_t)r * HD + c];
        }
    }

    const __nv_bfloat16* kgh = Kh + (((size_t)bi * NKV + kh) * SEQ) * HD;
    const __nv_bfloat16* kgl = Kl + (((size_t)bi * NKV + kh) * SEQ) * HD;
    const __nv_bfloat16* vgh = Vh + (((size_t)bi * NKV + kh) * HD) * SEQ;
    const __nv_bfloat16* vgl = Vl + (((size_t)bi * NKV + kh) * HD) * SEQ;

    float o[16][4];
#pragma unroll
    for (int nt = 0; nt < 16; nt++)
#pragma unroll
        for (int e = 0; e < 4; e++) o[nt][e] = 0.f;
    float m0 = -1e30f, m1 = -1e30f, l0 = 0.f, l1 = 0.f;

    const int ntiles = 2 * qtile + 2;
    for (int t = 0; t < ntiles; ++t) {
        const int k0 = t * 64;
        __syncthreads();
        for (int i = tid; i < 64 * 16; i += 256) {
            int r = i >> 4, c = (i & 15) * 8;
            *(uint4*)&sKh[r * FQP + c] = *(const uint4*)&kgh[(size_t)(k0 + r) * HD + c];
            *(uint4*)&sKl[r * FQP + c] = *(const uint4*)&kgl[(size_t)(k0 + r) * HD + c];
        }
        for (int i = tid; i < 128 * 8; i += 256) {
            int r = i >> 3, c = (i & 7) * 8;
            *(uint4*)&sVh[r * FVP + c] = *(const uint4*)&vgh[(size_t)r * SEQ + k0 + c];
            *(uint4*)&sVl[r * FVP + c] = *(const uint4*)&vgl[(size_t)r * SEQ + k0 + c];
        }
        __syncthreads();

        float s[8][4];
#pragma unroll
        for (int nt = 0; nt < 8; nt++)
#pragma unroll
            for (int e = 0; e < 4; e++) s[nt][e] = 0.f;

#pragma unroll
        for (int kk = 0; kk < 128; kk += 16) {
            uint32_t ah[4], al[4];
            const int acol = kk + lcoff;
            ldsm4(ah, &sQh[(wid * 16 + lrow) * FQP + acol]);
            ldsm4(al, &sQl[(wid * 16 + lrow) * FQP + acol]);
#pragma unroll
            for (int np = 0; np < 4; np++) {
                const int br = np * 16 + brow;
                const int bc = kk + bcoff;
                uint32_t bh[4], bl[4];
                ldsm4(bh, &sKh[br * FQP + bc]);
                ldsm4(bl, &sKl[br * FQP + bc]);
                mma16816(s[2 * np    ], ah, bh);
                mma16816(s[2 * np    ], al, bh);
                mma16816(s[2 * np    ], ah, bl);
                mma16816(s[2 * np + 1], ah, bh + 2);
                mma16816(s[2 * np + 1], al, bh + 2);
                mma16816(s[2 * np + 1], ah, bl + 2);
            }
        }

        if (t >= ntiles - 2) {   // causal mask (last two tiles span the diagonal)
            const int r0 = q0 + wid * 16 + grp;
#pragma unroll
            for (int nt = 0; nt < 8; nt++) {
                const int c = k0 + nt * 8 + tig * 2;
                if (c     > r0)     s[nt][0] = -1e30f;
                if (c + 1 > r0)     s[nt][1] = -1e30f;
                if (c     > r0 + 8) s[nt][2] = -1e30f;
                if (c + 1 > r0 + 8) s[nt][3] = -1e30f;
            }
        }

        float mx0 = -1e30f, mx1 = -1e30f;
#pragma unroll
        for (int nt = 0; nt < 8; nt++) {
            mx0 = fmaxf(mx0, fmaxf(s[nt][0], s[nt][1]));
            mx1 = fmaxf(mx1, fmaxf(s[nt][2], s[nt][3]));
        }
        mx0 = fmaxf(mx0, __shfl_xor_sync(0xffffffffu, mx0, 1));
        mx0 = fmaxf(mx0, __shfl_xor_sync(0xffffffffu, mx0, 2));
        mx1 = fmaxf(mx1, __shfl_xor_sync(0xffffffffu, mx1, 1));
        mx1 = fmaxf(mx1, __shfl_xor_sync(0xffffffffu, mx1, 2));

        const float nm0 = fmaxf(m0, mx0);
        const float nm1 = fmaxf(m1, mx1);
        const float a0 = __expf(m0 - nm0);
        const float a1 = __expf(m1 - nm1);
        m0 = nm0; m1 = nm1;

        float rs0 = 0.f, rs1 = 0.f;
#pragma unroll
        for (int nt = 0; nt < 8; nt++) {
            s[nt][0] = __expf(s[nt][0] - m0);
            s[nt][1] = __expf(s[nt][1] - m0);
            s[nt][2] = __expf(s[nt][2] - m1);
            s[nt][3] = __expf(s[nt][3] - m1);
            rs0 += s[nt][0] + s[nt][1];
            rs1 += s[nt][2] + s[nt][3];
        }
        rs0 += __shfl_xor_sync(0xffffffffu, rs0, 1);
        rs0 += __shfl_xor_sync(0xffffffffu, rs0, 2);
        rs1 += __shfl_xor_sync(0xffffffffu, rs1, 1);
        rs1 += __shfl_xor_sync(0xffffffffu, rs1, 2);
        l0 = l0 * a0 + rs0;
        l1 = l1 * a1 + rs1;

#pragma unroll
        for (int nt = 0; nt < 16; nt++) {
            o[nt][0] *= a0; o[nt][1] *= a0;
            o[nt][2] *= a1; o[nt][3] *= a1;
        }

#pragma unroll
        for (int ks = 0; ks < 4; ks++) {
            uint32_t ph[4], pl[4];
            ph[0] = pack_hilo(s[2 * ks][0],     s[2 * ks][1],     pl[0]);
            ph[1] = pack_hilo(s[2 * ks][2],     s[2 * ks][3],     pl[1]);
            ph[2] = pack_hilo(s[2 * ks + 1][0], s[2 * ks + 1][1], pl[2]);
            ph[3] = pack_hilo(s[2 * ks + 1][2], s[2 * ks + 1][3], pl[3]);
            const int bc = ks * 16 + bcoff;
#pragma unroll
            for (int np = 0; np < 8; np++) {
                const int br = np * 16 + brow;
                uint32_t vh4[4], vl4[4];
                ldsm4(vh4, &sVh[br * FVP + bc]);
                ldsm4(vl4, &sVl[br * FVP + bc]);
                mma16816(o[2 * np    ], ph, vh4);
                mma16816(o[2 * np    ], pl, vh4);
                mma16816(o[2 * np    ], ph, vl4);
                mma16816(o[2 * np + 1], ph, vh4 + 2);
                mma16816(o[2 * np + 1], pl, vh4 + 2);
                mma16816(o[2 * np + 1], ph, vl4 + 2);
            }
        }
    }

    const float i0 = 1.0f / l0;
    const float i1 = 1.0f / l1;
    const size_t row0 = (size_t)bi * SEQ + q0 + wid * 16 + grp;
    const size_t row1 = row0 + 8;
    const int colb = h * HD + tig * 2;
#pragma unroll
    for (int nt = 0; nt < 16; nt++) {
        uint32_t lo;
        uint32_t hi = pack_hilo(o[nt][0] * i0, o[nt][1] * i0, lo);
        *(uint32_t*)&Oh[row0 * (NH * HD) + colb + nt * 8] = hi;
        *(uint32_t*)&Ol[row0 * (NH * HD) + colb + nt * 8] = lo;
        hi = pack_hilo(o[nt][2] * i1, o[nt][3] * i1, lo);
        *(uint32_t*)&Oh[row1 * (NH * HD) + colb + nt * 8] = hi;
        *(uint32_t*)&Ol[row1 * (NH * HD) + colb + nt * 8] = lo;
    }
}

// ---------------------------------------------------------------------------
// kernel_launch
// ---------------------------------------------------------------------------
extern "C" void kernel_launch(void* const* d_in, const int* in_sizes, int n_in,
                              void* d_out, int out_size)
{
    const float* hidden = (const float*)d_in[0];
    const float* cosb   = (const float*)d_in[1];
    const float* sinb   = (const float*)d_in[2];
    const float* wq     = (const float*)d_in[3];
    const float* wk     = (const float*)d_in[4];
    const float* wv     = (const float*)d_in[5];
    const float* wo     = (const float*)d_in[6];
    const float* qg     = (const float*)d_in[7];
    const float* kg     = (const float*)d_in[8];

    float* out  = (float*)d_out;
    float* kout = out  + (size_t)NB * SEQ * HDIM;
    float* vout = kout + (size_t)NB * NKV * SEQ * HD;

    __nv_bfloat16 *hidh, *hidl, *wqkvh, *wqkvl, *woh, *wol, *aoh, *aol;
    __nv_bfloat16 *qh, *ql, *kh, *kl, *vh, *vl;
    float *qkv;
    cudaGetSymbolAddress((void**)&hidh,  g_hid_h);
    cudaGetSymbolAddress((void**)&hidl,  g_hid_l);
    cudaGetSymbolAddress((void**)&wqkvh, g_wqkv_h);
    cudaGetSymbolAddress((void**)&wqkvl, g_wqkv_l);
    cudaGetSymbolAddress((void**)&woh,   g_wo_h);
    cudaGetSymbolAddress((void**)&wol,   g_wo_l);
    cudaGetSymbolAddress((void**)&aoh,   g_ao_h);
    cudaGetSymbolAddress((void**)&aol,   g_ao_l);
    cudaGetSymbolAddress((void**)&qkv,   g_qkv);
    cudaGetSymbolAddress((void**)&qh,    g_qh);
    cudaGetSymbolAddress((void**)&ql,    g_ql);
    cudaGetSymbolAddress((void**)&kh,    g_kh);
    cudaGetSymbolAddress((void**)&kl,    g_kl);
    cudaGetSymbolAddress((void**)&vh,    g_vh);
    cudaGetSymbolAddress((void**)&vl,    g_vl);

    cudaFuncSetAttribute(flash_mma, cudaFuncAttributeMaxDynamicSharedMemorySize, FLASH_SMEM);
    cudaFuncSetAttribute(gemm_bf16x2, cudaFuncAttributeMaxDynamicSharedMemorySize, GEMM_SMEM);

    // fp32 -> bf16 hi/lo splits
    const size_t nHid = (size_t)MROWS * HDIM;
    const size_t nWq  = (size_t)NH  * HD * HDIM;
    const size_t nWk  = (size_t)NKV * HD * HDIM;
    split_bf16<<<(int)(nHid / 1024), 256>>>((const float4*)hidden, hidh, hidl);
    split_bf16<<<(int)(nWq  / 1024), 256>>>((const float4*)wq, wqkvh, wqkvl);
    split_bf16<<<(int)(nWk  / 1024), 256>>>((const float4*)wk, wqkvh + nWq, wqkvl + nWq);
    split_bf16<<<(int)(nWk  / 1024), 256>>>((const float4*)wv, wqkvh + nWq + nWk, wqkvl + nWq + nWk);
    split_bf16<<<(int)(nWq  / 1024), 256>>>((const float4*)wo, woh, wol);

    // Fused QKV projection (256x128 tiles)
    gemm_bf16x2<<<dim3(NQKV / 128, MROWS / 256), 256, GEMM_SMEM>>>(
        hidh, hidl, wqkvh, wqkvl, qkv, MROWS, NQKV, HDIM);

    // RMSNorm + RoPE -> bf16 hi/lo operands (+ fp32 K into d_out)
    norm_rope_q<<<(MROWS * NH ) / 8, 256>>>(qkv, qh, ql, cosb, sinb, qg);
    norm_rope_k<<<(MROWS * NKV) / 8, 256>>>(qkv, kout, kh, kl, cosb, sinb, kg);

    // V: fp32 into d_out's new_v; bf16 hi/lo transposed (b,KV,D,s)
    v_transpose<<<(NB * SEQ * NKV * HD / 4) / 256, 256>>>((const float4*)qkv, (float4*)vout);
    vtrans_split<<<dim3(SEQ / 32, HD / 32, NB * NKV), dim3(32, 8)>>>(qkv, vh, vl);

    // Tensor-core causal GQA flash attention (BM=128) -> bf16 hi/lo O
    flash_mma<<<dim3(SEQ / 128, NH, NB), 256, FLASH_SMEM>>>(
        qh, ql, kh, kl, vh, vl, aoh, aol);

    // Output projection (256x128 tiles)
    gemm_bf16x2<<<dim3(HDIM / 128, MROWS / 256), 256, GEMM_SMEM>>>(
        aoh, aol, woh, wol, out, MROWS, HDIM, NH * HD);
}

// round 10
// speedup vs baseline: 1.2753x; 1.2753x over previous
#include <cuda_runtime.h>
#include <cuda_bf16.h>
#include <cstdint>

// Problem constants
constexpr int NB   = 2;      // batch
constexpr int SEQ  = 2048;   // sequence
constexpr int HDIM = 2560;   // hidden
constexpr int NH   = 32;     // q heads
constexpr int NKV  = 8;      // kv heads
constexpr int HD   = 128;    // head dim
constexpr int GQ   = NH / NKV;
constexpr int MROWS = NB * SEQ;            // 4096
constexpr int NQKV  = (NH + 2 * NKV) * HD; // 6144
constexpr int KOFF  = NH * HD;             // 4096
constexpr int VOFF  = (NH + NKV) * HD;     // 5120
constexpr float SM_SCALE = 0.08838834764831845f;  // 1/sqrt(128)

// ---------------- device scratch (no allocation allowed) ----------------
__device__ __nv_bfloat16 g_hid_h [(size_t)MROWS * HDIM];
__device__ __nv_bfloat16 g_hid_l [(size_t)MROWS * HDIM];
__device__ __nv_bfloat16 g_wqkv_h[(size_t)NQKV * HDIM];
__device__ __nv_bfloat16 g_wqkv_l[(size_t)NQKV * HDIM];
__device__ __nv_bfloat16 g_wo_h  [(size_t)HDIM * NH * HD];
__device__ __nv_bfloat16 g_wo_l  [(size_t)HDIM * NH * HD];
__device__ __nv_bfloat16 g_ao_h  [(size_t)MROWS * NH * HD];
__device__ __nv_bfloat16 g_ao_l  [(size_t)MROWS * NH * HD];
__device__ float g_qkv[(size_t)MROWS * NQKV];       // 96MB
// bf16 hi/lo attention operands
__device__ __nv_bfloat16 g_qh[(size_t)NB * NH  * SEQ * HD];  // (b,H,s,D), pre-scaled
__device__ __nv_bfloat16 g_ql[(size_t)NB * NH  * SEQ * HD];
__device__ __nv_bfloat16 g_kh[(size_t)NB * NKV * SEQ * HD];  // (b,KV,s,D)
__device__ __nv_bfloat16 g_kl[(size_t)NB * NKV * SEQ * HD];
__device__ __nv_bfloat16 g_vh[(size_t)NB * NKV * HD * SEQ];  // (b,KV,D,s) transposed
__device__ __nv_bfloat16 g_vl[(size_t)NB * NKV * HD * SEQ];

// ---------------------------------------------------------------------------
// cp.async / ldmatrix helpers
// ---------------------------------------------------------------------------
__device__ __forceinline__ void cp16(uint32_t smem, const __nv_bfloat16* gmem)
{
    asm volatile("cp.async.cg.shared.global [%0], [%1], 16;\n" :: "r"(smem), "l"(gmem));
}
#define CP_COMMIT() asm volatile("cp.async.commit_group;\n" ::: "memory")
#define CP_WAIT(n)  asm volatile("cp.async.wait_group %0;\n" :: "n"(n) : "memory")

__device__ __forceinline__ void ldsm4(uint32_t* r, const __nv_bfloat16* p)
{
    uint32_t a = (uint32_t)__cvta_generic_to_shared(p);
    asm volatile("ldmatrix.sync.aligned.m8n8.x4.shared.b16 {%0,%1,%2,%3}, [%4];"
        : "=r"(r[0]), "=r"(r[1]), "=r"(r[2]), "=r"(r[3]) : "r"(a));
}

// ---------------------------------------------------------------------------
// fp32 -> bf16 hi/lo split
// ---------------------------------------------------------------------------
__global__ __launch_bounds__(256) void split_bf16(
    const float4* __restrict__ in, __nv_bfloat16* __restrict__ hi,
    __nv_bfloat16* __restrict__ lo)
{
    const size_t i = (size_t)blockIdx.x * 256 + threadIdx.x;
    float4 x = in[i];
    __nv_bfloat16 h[4], l[4];
    float xs[4] = {x.x, x.y, x.z, x.w};
#pragma unroll
    for (int j = 0; j < 4; j++) {
        h[j] = __float2bfloat16(xs[j]);
        l[j] = __float2bfloat16(xs[j] - __bfloat162float(h[j]));
    }
    *(uint2*)&hi[i * 4] = *(uint2*)h;
    *(uint2*)&lo[i * 4] = *(uint2*)l;
}

// ---------------------------------------------------------------------------
// mma.m16n8k16 bf16 wrapper
// ---------------------------------------------------------------------------
__device__ __forceinline__ void mma16816(float* c, const uint32_t* a, const uint32_t* b)
{
    asm volatile(
        "mma.sync.aligned.m16n8k16.row.col.f32.bf16.bf16.f32 "
        "{%0,%1,%2,%3}, {%4,%5,%6,%7}, {%8,%9}, {%0,%1,%2,%3};"
        : "+f"(c[0]), "+f"(c[1]), "+f"(c[2]), "+f"(c[3])
        : "r"(a[0]), "r"(a[1]), "r"(a[2]), "r"(a[3]), "r"(b[0]), "r"(b[1]));
}

__device__ __forceinline__ uint32_t pack_hilo(float x, float y, uint32_t& lo)
{
    __nv_bfloat162 h = __float22bfloat162_rn(make_float2(x, y));
    float rx = x - __bfloat162float(h.x);
    float ry = y - __bfloat162float(h.y);
    __nv_bfloat162 l = __float22bfloat162_rn(make_float2(rx, ry));
    lo = *(uint32_t*)&l;
    return *(uint32_t*)&h;
}

// ---------------------------------------------------------------------------
// bf16-split tensor-core GEMM: C[M,N] = A[M,K] @ B[N,K]^T   (fp32 accurate)
// BK=32, 2-stage cp.async pipeline, ONE __syncthreads per iteration,
// 2 CTAs/SM. Block 128x128, 256 threads (8 warps, 32x64 warp tile).
// (R8 known-good version, reverted from the R9 256x128 spill regression.)
// ---------------------------------------------------------------------------
constexpr int GPAD = 40;                      // smem row pitch (bf16): 80B, ldsm conflict-free
constexpr int GSTG = 128 * GPAD;              // bf16 per matrix per stage (5120)
constexpr int GEMM_SMEM = 2 * 4 * GSTG * 2;   // 81920 bytes

__global__ __launch_bounds__(256, 2) void gemm_bf16x2(
    const __nv_bfloat16* __restrict__ Ah, const __nv_bfloat16* __restrict__ Al,
    const __nv_bfloat16* __restrict__ Bh, const __nv_bfloat16* __restrict__ Bl,
    float* __restrict__ C, int M, int N, int K)
{
    extern __shared__ __nv_bfloat16 sb[];

    const int tid = threadIdx.x;
    const int bm = blockIdx.y * 128;
    const int bn = blockIdx.x * 128;
    const int lane = tid & 31;
    const int wid  = tid >> 5;
    const int wm = (wid & 3) * 32;
    const int wn = (wid >> 2) * 64;
    const int grp = lane >> 2;
    const int tig = lane & 3;

    const int lrow  = lane & 15;
    const int lcoff = (lane >> 4) * 8;
    const int brow  = (lane & 7) + ((lane >> 4) << 3);
    const int bcoff = ((lane >> 3) & 1) * 8;

    uint32_t soff[2];
    int grow[2], gcol[2];
#pragma unroll
    for (int j = 0; j < 2; j++) {
        int c = tid + j * 256;
        grow[j] = c >> 2;
        gcol[j] = (c & 3) * 8;
        soff[j] = (uint32_t)(grow[j] * GPAD + gcol[j]);
    }

    float acc[2][8][4];
#pragma unroll
    for (int mt = 0; mt < 2; mt++)
#pragma unroll
        for (int nt = 0; nt < 8; nt++)
#pragma unroll
            for (int e = 0; e < 4; e++) acc[mt][nt][e] = 0.f;

    uint32_t sbase = (uint32_t)__cvta_generic_to_shared(sb);
    const int nk = K / 32;

#pragma unroll
    for (int j = 0; j < 2; j++) {
        cp16(sbase + (0 * GSTG + soff[j]) * 2, Ah + (size_t)(bm + grow[j]) * K + gcol[j]);
        cp16(sbase + (1 * GSTG + soff[j]) * 2, Al + (size_t)(bm + grow[j]) * K + gcol[j]);
        cp16(sbase + (2 * GSTG + soff[j]) * 2, Bh + (size_t)(bn + grow[j]) * K + gcol[j]);
        cp16(sbase + (3 * GSTG + soff[j]) * 2, Bl + (size_t)(bn + grow[j]) * K + gcol[j]);
    }
    CP_COMMIT();

    for (int i = 0; i < nk; i++) {
        const __nv_bfloat16* cur = sb + (size_t)(i & 1) * 4 * GSTG;

        CP_WAIT(0);
        __syncthreads();

        if (i + 1 < nk) {
            const uint32_t nxt = sbase + (uint32_t)(((i + 1) & 1) * 4 * GSTG) * 2;
            const int k0 = (i + 1) * 32;
#pragma unroll
            for (int j = 0; j < 2; j++) {
                cp16(nxt + (0 * GSTG + soff[j]) * 2, Ah + (size_t)(bm + grow[j]) * K + k0 + gcol[j]);
                cp16(nxt + (1 * GSTG + soff[j]) * 2, Al + (size_t)(bm + grow[j]) * K + k0 + gcol[j]);
                cp16(nxt + (2 * GSTG + soff[j]) * 2, Bh + (size_t)(bn + grow[j]) * K + k0 + gcol[j]);
                cp16(nxt + (3 * GSTG + soff[j]) * 2, Bl + (size_t)(bn + grow[j]) * K + k0 + gcol[j]);
            }
            CP_COMMIT();
        }

        const __nv_bfloat16* sAh = cur;
        const __nv_bfloat16* sAl = cur + 1 * GSTG;
        const __nv_bfloat16* sBh = cur + 2 * GSTG;
        const __nv_bfloat16* sBl = cur + 3 * GSTG;

#pragma unroll
        for (int kk = 0; kk < 32; kk += 16) {
            uint32_t afh[2][4], afl[2][4];
            const int acol = kk + lcoff;
            ldsm4(afh[0], &sAh[(wm + lrow     ) * GPAD + acol]);
            ldsm4(afh[1], &sAh[(wm + 16 + lrow) * GPAD + acol]);
            ldsm4(afl[0], &sAl[(wm + lrow     ) * GPAD + acol]);
            ldsm4(afl[1], &sAl[(wm + 16 + lrow) * GPAD + acol]);
#pragma unroll
            for (int np = 0; np < 4; np++) {
                const int br = wn + np * 16 + brow;
                const int bc = kk + bcoff;
                uint32_t bh[4], bl[4];
                ldsm4(bh, &sBh[br * GPAD + bc]);
                ldsm4(bl, &sBl[br * GPAD + bc]);
#pragma unroll
                for (int mt = 0; mt < 2; mt++) {
                    mma16816(acc[mt][2 * np    ], afh[mt], bh);
                    mma16816(acc[mt][2 * np    ], afh[mt], bl);
                    mma16816(acc[mt][2 * np    ], afl[mt], bh);
                    mma16816(acc[mt][2 * np + 1], afh[mt], bh + 2);
                    mma16816(acc[mt][2 * np + 1], afh[mt], bl + 2);
                    mma16816(acc[mt][2 * np + 1], afl[mt], bh + 2);
                }
            }
        }
    }

#pragma unroll
    for (int mt = 0; mt < 2; mt++) {
        const int row = bm + wm + mt * 16 + grp;
#pragma unroll
        for (int nt = 0; nt < 8; nt++) {
            const int col = bn + wn + nt * 8 + tig * 2;
            *(float2*)&C[(size_t)row * N + col]       = make_float2(acc[mt][nt][0], acc[mt][nt][1]);
            *(float2*)&C[(size_t)(row + 8) * N + col] = make_float2(acc[mt][nt][2], acc[mt][nt][3]);
        }
    }
}

// ---------------------------------------------------------------------------
// RMSNorm + RoPE for Q: reads qkv fp32, writes bf16 hi/lo to (b,H,s,D),
// pre-scaled by 1/sqrt(D). One warp per row.
// ---------------------------------------------------------------------------
__global__ __launch_bounds__(256) void norm_rope_q(
    const float* __restrict__ qkv,
    __nv_bfloat16* __restrict__ oh, __nv_bfloat16* __restrict__ ol,
    const float* __restrict__ cs, const float* __restrict__ sn,
    const float* __restrict__ gamma)
{
    const int warp = (blockIdx.x * 256 + threadIdx.x) >> 5;
    const int lane = threadIdx.x & 31;
    const int h  = warp % NH;
    const int bs = warp / NH;
    const int sp = bs % SEQ;
    const int bi = bs / SEQ;

    const float* x = qkv + (size_t)bs * NQKV + h * HD;
    float e0 = x[lane], e1 = x[lane + 32], e2 = x[lane + 64], e3 = x[lane + 96];

    float ssq = e0 * e0 + e1 * e1 + e2 * e2 + e3 * e3;
#pragma unroll
    for (int o = 16; o; o >>= 1) ssq += __shfl_xor_sync(0xffffffffu, ssq, o);
    const float r = rsqrtf(ssq * (1.0f / HD) + 1e-6f);

    e0 *= r * gamma[lane];      e1 *= r * gamma[lane + 32];
    e2 *= r * gamma[lane + 64]; e3 *= r * gamma[lane + 96];

    const float* cp = cs + (size_t)bs * HD;
    const float* sg = sn + (size_t)bs * HD;
    float o4[4];
    o4[0] = (e0 * cp[lane]      - e2 * sg[lane])      * SM_SCALE;
    o4[1] = (e1 * cp[lane + 32] - e3 * sg[lane + 32]) * SM_SCALE;
    o4[2] = (e2 * cp[lane + 64] + e0 * sg[lane + 64]) * SM_SCALE;
    o4[3] = (e3 * cp[lane + 96] + e1 * sg[lane + 96]) * SM_SCALE;

    const size_t ob = (((size_t)bi * NH + h) * SEQ + sp) * HD;
#pragma unroll
    for (int j = 0; j < 4; j++) {
        __nv_bfloat16 hv = __float2bfloat16(o4[j]);
        oh[ob + lane + 32 * j] = hv;
        ol[ob + lane + 32 * j] = __float2bfloat16(o4[j] - __bfloat162float(hv));
    }
}

// ---------------------------------------------------------------------------
// RMSNorm + RoPE for K: writes fp32 (b,KV,s,D) into d_out AND bf16 hi/lo.
// ---------------------------------------------------------------------------
__global__ __launch_bounds__(256) void norm_rope_k(
    const float* __restrict__ qkv, float* __restrict__ kout,
    __nv_bfloat16* __restrict__ oh, __nv_bfloat16* __restrict__ ol,
    const float* __restrict__ cs, const float* __restrict__ sn,
    const float* __restrict__ gamma)
{
    const int warp = (blockIdx.x * 256 + threadIdx.x) >> 5;
    const int lane = threadIdx.x & 31;
    const int h  = warp % NKV;
    const int bs = warp / NKV;
    const int sp = bs % SEQ;
    const int bi = bs / SEQ;

    const float* x = qkv + (size_t)bs * NQKV + KOFF + h * HD;
    float e0 = x[lane], e1 = x[lane + 32], e2 = x[lane + 64], e3 = x[lane + 96];

    float ssq = e0 * e0 + e1 * e1 + e2 * e2 + e3 * e3;
#pragma unroll
    for (int o = 16; o; o >>= 1) ssq += __shfl_xor_sync(0xffffffffu, ssq, o);
    const float r = rsqrtf(ssq * (1.0f / HD) + 1e-6f);

    e0 *= r * gamma[lane];      e1 *= r * gamma[lane + 32];
    e2 *= r * gamma[lane + 64]; e3 *= r * gamma[lane + 96];

    const float* cp = cs + (size_t)bs * HD;
    const float* sg = sn + (size_t)bs * HD;
    float o4[4];
    o4[0] = e0 * cp[lane]      - e2 * sg[lane];
    o4[1] = e1 * cp[lane + 32] - e3 * sg[lane + 32];
    o4[2] = e2 * cp[lane + 64] + e0 * sg[lane + 64];
    o4[3] = e3 * cp[lane + 96] + e1 * sg[lane + 96];

    const size_t ob = (((size_t)bi * NKV + h) * SEQ + sp) * HD;
#pragma unroll
    for (int j = 0; j < 4; j++) {
        kout[ob + lane + 32 * j] = o4[j];
        __nv_bfloat16 hv = __float2bfloat16(o4[j]);
        oh[ob + lane + 32 * j] = hv;
        ol[ob + lane + 32 * j] = __float2bfloat16(o4[j] - __bfloat162float(hv));
    }
}

// ---------------------------------------------------------------------------
// V transpose (fp32): qkv V region -> (b,KV,s,D) in d_out
// ---------------------------------------------------------------------------
__global__ __launch_bounds__(256) void v_transpose(
    const float4* __restrict__ qkv4, float4* __restrict__ out)
{
    const size_t i = (size_t)blockIdx.x * 256 + threadIdx.x;
    const int d4 = (int)(i & 31);
    const int kh = (int)((i >> 5) & (NKV - 1));
    const int sp = (int)((i >> 8) & (SEQ - 1));
    const int bi = (int)(i >> 19);
    const size_t src = ((size_t)(bi * SEQ + sp) * NQKV + VOFF + kh * HD) / 4 + d4;
    const size_t dst = (((size_t)bi * NKV + kh) * SEQ + sp) * 32 + d4;
    out[dst] = qkv4[src];
}

// ---------------------------------------------------------------------------
// V transpose + split (bf16): qkv V region -> (b,KV,D,s) hi/lo
// ---------------------------------------------------------------------------
__global__ void vtrans_split(
    const float* __restrict__ qkv,
    __nv_bfloat16* __restrict__ vh, __nv_bfloat16* __restrict__ vl)
{
    __shared__ float t[32][33];
    const int s0 = blockIdx.x * 32, d0 = blockIdx.y * 32;
    const int bz = blockIdx.z;                 // bi*NKV + kh
    const int bi = bz / NKV, kh = bz % NKV;
    const int tx = threadIdx.x, ty = threadIdx.y;

#pragma unroll
    for (int j = 0; j < 4; j++) {
        int s = s0 + ty + j * 8;
        t[ty + j * 8][tx] =
            qkv[(size_t)(bi * SEQ + s) * NQKV + VOFF + kh * HD + d0 + tx];
    }
    __syncthreads();
#pragma unroll
    for (int j = 0; j < 4; j++) {
        int d = d0 + ty + j * 8;
        float v = t[tx][ty + j * 8];
        __nv_bfloat16 hv = __float2bfloat16(v);
        size_t idx = ((size_t)bz * HD + d) * SEQ + s0 + tx;
        vh[idx] = hv;
        vl[idx] = __float2bfloat16(v - __bfloat162float(hv));
    }
}

// ---------------------------------------------------------------------------
// Tensor-core causal flash attention, bf16 hi/lo split, ldmatrix loads.
// BM=128, BN=64, 256 threads (8 warps, 16 Q rows each).
// K/V tiles double-buffered via cp.async (one sync per KV tile).
// ---------------------------------------------------------------------------
constexpr int FQP = 136;  // pitch (bf16) for Q/K tiles
constexpr int FVP = 72;   // pitch (bf16) for Vt tiles
constexpr int FKV = 2 * 64 * FQP + 2 * 128 * FVP;   // KV stage elems (35840)
constexpr int FLASH_SMEM = (2 * 128 * FQP + 2 * FKV) * 2;  // 213 KB

__global__ __launch_bounds__(256, 1) void flash_mma(
    const __nv_bfloat16* __restrict__ Qh, const __nv_bfloat16* __restrict__ Ql,
    const __nv_bfloat16* __restrict__ Kh, const __nv_bfloat16* __restrict__ Kl,
    const __nv_bfloat16* __restrict__ Vh, const __nv_bfloat16* __restrict__ Vl,
    __nv_bfloat16* __restrict__ Oh, __nv_bfloat16* __restrict__ Ol)
{
    extern __shared__ __nv_bfloat16 sm[];
    __nv_bfloat16* sQh = sm;
    __nv_bfloat16* sQl = sQh + 128 * FQP;
    __nv_bfloat16* sKV = sQl + 128 * FQP;    // 2 stages of [Kh|Kl|Vh|Vl]

    const int qtile = blockIdx.x;
    const int h     = blockIdx.y;
    const int bi    = blockIdx.z;
    const int kh    = h / GQ;
    const int tid   = threadIdx.x;
    const int lane  = tid & 31;
    const int wid   = tid >> 5;
    const int grp   = lane >> 2;
    const int tig   = lane & 3;
    const int q0    = qtile * 128;

    const int lrow  = lane & 15;
    const int lcoff = (lane >> 4) * 8;
    const int brow  = (lane & 7) + ((lane >> 4) << 3);
    const int bcoff = ((lane >> 3) & 1) * 8;

    const __nv_bfloat16* kgh = Kh + (((size_t)bi * NKV + kh) * SEQ) * HD;
    const __nv_bfloat16* kgl = Kl + (((size_t)bi * NKV + kh) * SEQ) * HD;
    const __nv_bfloat16* vgh = Vh + (((size_t)bi * NKV + kh) * HD) * SEQ;
    const __nv_bfloat16* vgl = Vl + (((size_t)bi * NKV + kh) * HD) * SEQ;
    const uint32_t skv = (uint32_t)__cvta_generic_to_shared(sKV);

    // per-thread cp.async geometry for one KV stage:
    // K: 64 rows x 16 chunks -> 1024 chunks, 4/thread; V: 128 rows x 8 -> 4/thread
    int kr[4], kc[4], vr[4], vc[4];
    uint32_t kso[4], vso[4];
#pragma unroll
    for (int j = 0; j < 4; j++) {
        int c = tid + j * 256;
        kr[j] = c >> 4; kc[j] = (c & 15) * 8;
        kso[j] = (uint32_t)(kr[j] * FQP + kc[j]);
        vr[j] = c >> 3; vc[j] = (c & 7) * 8;
        vso[j] = (uint32_t)(vr[j] * FVP + vc[j]);
    }

    // issue one KV stage's loads (stage s, kv tile base k0)
    auto issue_kv = [&](int s, int k0) {
        const uint32_t st = skv + (uint32_t)(s * FKV) * 2;
#pragma unroll
        for (int j = 0; j < 4; j++) {
            cp16(st + kso[j] * 2,                       kgh + (size_t)(k0 + kr[j]) * HD + kc[j]);
            cp16(st + (64 * FQP + kso[j]) * 2,          kgl + (size_t)(k0 + kr[j]) * HD + kc[j]);
            cp16(st + (2 * 64 * FQP + vso[j]) * 2,      vgh + (size_t)vr[j] * SEQ + k0 + vc[j]);
            cp16(st + (2 * 64 * FQP + 128 * FVP + vso[j]) * 2,
                                                        vgl + (size_t)vr[j] * SEQ + k0 + vc[j]);
        }
        CP_COMMIT();
    };

    // Q tile load (128 x 128, hi+lo) -- plain loads, once
    {
        const __nv_bfloat16* qgh = Qh + (((size_t)bi * NH + h) * SEQ + q0) * HD;
        const __nv_bfloat16* qgl = Ql + (((size_t)bi * NH + h) * SEQ + q0) * HD;
        for (int i = tid; i < 128 * 16; i += 256) {
            int r = i >> 4, c = (i & 15) * 8;
            *(uint4*)&sQh[r * FQP + c] = *(const uint4*)&qgh[(size_t)r * HD + c];
            *(uint4*)&sQl[r * FQP + c] = *(const uint4*)&qgl[(size_t)r * HD + c];
        }
    }

    float o[16][4];
#pragma unroll
    for (int nt = 0; nt < 16; nt++)
#pragma unroll
        for (int e = 0; e < 4; e++) o[nt][e] = 0.f;
    float m0 = -1e30f, m1 = -1e30f, l0 = 0.f, l1 = 0.f;

    const int ntiles = 2 * qtile + 2;

    issue_kv(0, 0);   // prologue

    for (int t = 0; t < ntiles; ++t) {
        const int k0 = t * 64;
        const __nv_bfloat16* cur = sKV + (size_t)(t & 1) * FKV;
        const __nv_bfloat16* sKh = cur;
        const __nv_bfloat16* sKl = cur + 64 * FQP;
        const __nv_bfloat16* sVh = cur + 2 * 64 * FQP;
        const __nv_bfloat16* sVl = cur + 2 * 64 * FQP + 128 * FVP;

        CP_WAIT(0);
        __syncthreads();

        if (t + 1 < ntiles) issue_kv((t + 1) & 1, (t + 1) * 64);

        float s[8][4];
#pragma unroll
        for (int nt = 0; nt < 8; nt++)
#pragma unroll
            for (int e = 0; e < 4; e++) s[nt][e] = 0.f;

#pragma unroll
        for (int kk = 0; kk < 128; kk += 16) {
            uint32_t ah[4], al[4];
            const int acol = kk + lcoff;
            ldsm4(ah, &sQh[(wid * 16 + lrow) * FQP + acol]);
            ldsm4(al, &sQl[(wid * 16 + lrow) * FQP + acol]);
#pragma unroll
            for (int np = 0; np < 4; np++) {
                const int br = np * 16 + brow;
                const int bc = kk + bcoff;
                uint32_t bh[4], bl[4];
                ldsm4(bh, &sKh[br * FQP + bc]);
                ldsm4(bl, &sKl[br * FQP + bc]);
                mma16816(s[2 * np    ], ah, bh);
                mma16816(s[2 * np    ], al, bh);
                mma16816(s[2 * np    ], ah, bl);
                mma16816(s[2 * np + 1], ah, bh + 2);
                mma16816(s[2 * np + 1], al, bh + 2);
                mma16816(s[2 * np + 1], ah, bl + 2);
            }
        }

        if (t >= ntiles - 2) {   // causal mask (last two tiles span the diagonal)
            const int r0 = q0 + wid * 16 + grp;
#pragma unroll
            for (int nt = 0; nt < 8; nt++) {
                const int c = k0 + nt * 8 + tig * 2;
                if (c     > r0)     s[nt][0] = -1e30f;
                if (c + 1 > r0)     s[nt][1] = -1e30f;
                if (c     > r0 + 8) s[nt][2] = -1e30f;
                if (c + 1 > r0 + 8) s[nt][3] = -1e30f;
            }
        }

        float mx0 = -1e30f, mx1 = -1e30f;
#pragma unroll
        for (int nt = 0; nt < 8; nt++) {
            mx0 = fmaxf(mx0, fmaxf(s[nt][0], s[nt][1]));
            mx1 = fmaxf(mx1, fmaxf(s[nt][2], s[nt][3]));
        }
        mx0 = fmaxf(mx0, __shfl_xor_sync(0xffffffffu, mx0, 1));
        mx0 = fmaxf(mx0, __shfl_xor_sync(0xffffffffu, mx0, 2));
        mx1 = fmaxf(mx1, __shfl_xor_sync(0xffffffffu, mx1, 1));
        mx1 = fmaxf(mx1, __shfl_xor_sync(0xffffffffu, mx1, 2));

        const float nm0 = fmaxf(m0, mx0);
        const float nm1 = fmaxf(m1, mx1);
        const float a0 = __expf(m0 - nm0);
        const float a1 = __expf(m1 - nm1);
        m0 = nm0; m1 = nm1;

        float rs0 = 0.f, rs1 = 0.f;
#pragma unroll
        for (int nt = 0; nt < 8; nt++) {
            s[nt][0] = __expf(s[nt][0] - m0);
            s[nt][1] = __expf(s[nt][1] - m0);
            s[nt][2] = __expf(s[nt][2] - m1);
            s[nt][3] = __expf(s[nt][3] - m1);
            rs0 += s[nt][0] + s[nt][1];
            rs1 += s[nt][2] + s[nt][3];
        }
        rs0 += __shfl_xor_sync(0xffffffffu, rs0, 1);
        rs0 += __shfl_xor_sync(0xffffffffu, rs0, 2);
        rs1 += __shfl_xor_sync(0xffffffffu, rs1, 1);
        rs1 += __shfl_xor_sync(0xffffffffu, rs1, 2);
        l0 = l0 * a0 + rs0;
        l1 = l1 * a1 + rs1;

#pragma unroll
        for (int nt = 0; nt < 16; nt++) {
            o[nt][0] *= a0; o[nt][1] *= a0;
            o[nt][2] *= a1; o[nt][3] *= a1;
        }

#pragma unroll
        for (int ks = 0; ks < 4; ks++) {
            uint32_t ph[4], pl[4];
            ph[0] = pack_hilo(s[2 * ks][0],     s[2 * ks][1],     pl[0]);
            ph[1] = pack_hilo(s[2 * ks][2],     s[2 * ks][3],     pl[1]);
            ph[2] = pack_hilo(s[2 * ks + 1][0], s[2 * ks + 1][1], pl[2]);
            ph[3] = pack_hilo(s[2 * ks + 1][2], s[2 * ks + 1][3], pl[3]);
            const int bc = ks * 16 + bcoff;
#pragma unroll
            for (int np = 0; np < 8; np++) {
                const int br = np * 16 + brow;
                uint32_t vh4[4], vl4[4];
                ldsm4(vh4, &sVh[br * FVP + bc]);
                ldsm4(vl4, &sVl[br * FVP + bc]);
                mma16816(o[2 * np    ], ph, vh4);
                mma16816(o[2 * np    ], pl, vh4);
                mma16816(o[2 * np    ], ph, vl4);
                mma16816(o[2 * np + 1], ph, vh4 + 2);
                mma16816(o[2 * np + 1], pl, vh4 + 2);
                mma16816(o[2 * np + 1], ph, vl4 + 2);
            }
        }
    }

    const float i0 = 1.0f / l0;
    const float i1 = 1.0f / l1;
    const size_t row0 = (size_t)bi * SEQ + q0 + wid * 16 + grp;
    const size_t row1 = row0 + 8;
    const int colb = h * HD + tig * 2;
#pragma unroll
    for (int nt = 0; nt < 16; nt++) {
        uint32_t lo;
        uint32_t hi = pack_hilo(o[nt][0] * i0, o[nt][1] * i0, lo);
        *(uint32_t*)&Oh[row0 * (NH * HD) + colb + nt * 8] = hi;
        *(uint32_t*)&Ol[row0 * (NH * HD) + colb + nt * 8] = lo;
        hi = pack_hilo(o[nt][2] * i1, o[nt][3] * i1, lo);
        *(uint32_t*)&Oh[row1 * (NH * HD) + colb + nt * 8] = hi;
        *(uint32_t*)&Ol[row1 * (NH * HD) + colb + nt * 8] = lo;
    }
}

// ---------------------------------------------------------------------------
// kernel_launch
// ---------------------------------------------------------------------------
extern "C" void kernel_launch(void* const* d_in, const int* in_sizes, int n_in,
                              void* d_out, int out_size)
{
    const float* hidden = (const float*)d_in[0];
    const float* cosb   = (const float*)d_in[1];
    const float* sinb   = (const float*)d_in[2];
    const float* wq     = (const float*)d_in[3];
    const float* wk     = (const float*)d_in[4];
    const float* wv     = (const float*)d_in[5];
    const float* wo     = (const float*)d_in[6];
    const float* qg     = (const float*)d_in[7];
    const float* kg     = (const float*)d_in[8];

    float* out  = (float*)d_out;
    float* kout = out  + (size_t)NB * SEQ * HDIM;
    float* vout = kout + (size_t)NB * NKV * SEQ * HD;

    __nv_bfloat16 *hidh, *hidl, *wqkvh, *wqkvl, *woh, *wol, *aoh, *aol;
    __nv_bfloat16 *qh, *ql, *kh, *kl, *vh, *vl;
    float *qkv;
    cudaGetSymbolAddress((void**)&hidh,  g_hid_h);
    cudaGetSymbolAddress((void**)&hidl,  g_hid_l);
    cudaGetSymbolAddress((void**)&wqkvh, g_wqkv_h);
    cudaGetSymbolAddress((void**)&wqkvl, g_wqkv_l);
    cudaGetSymbolAddress((void**)&woh,   g_wo_h);
    cudaGetSymbolAddress((void**)&wol,   g_wo_l);
    cudaGetSymbolAddress((void**)&aoh,   g_ao_h);
    cudaGetSymbolAddress((void**)&aol,   g_ao_l);
    cudaGetSymbolAddress((void**)&qkv,   g_qkv);
    cudaGetSymbolAddress((void**)&qh,    g_qh);
    cudaGetSymbolAddress((void**)&ql,    g_ql);
    cudaGetSymbolAddress((void**)&kh,    g_kh);
    cudaGetSymbolAddress((void**)&kl,    g_kl);
    cudaGetSymbolAddress((void**)&vh,    g_vh);
    cudaGetSymbolAddress((void**)&vl,    g_vl);

    cudaFuncSetAttribute(flash_mma, cudaFuncAttributeMaxDynamicSharedMemorySize, FLASH_SMEM);
    cudaFuncSetAttribute(gemm_bf16x2, cudaFuncAttributeMaxDynamicSharedMemorySize, GEMM_SMEM);

    // fp32 -> bf16 hi/lo splits
    const size_t nHid = (size_t)MROWS * HDIM;
    const size_t nWq  = (size_t)NH  * HD * HDIM;
    const size_t nWk  = (size_t)NKV * HD * HDIM;
    split_bf16<<<(int)(nHid / 1024), 256>>>((const float4*)hidden, hidh, hidl);
    split_bf16<<<(int)(nWq  / 1024), 256>>>((const float4*)wq, wqkvh, wqkvl);
    split_bf16<<<(int)(nWk  / 1024), 256>>>((const float4*)wk, wqkvh + nWq, wqkvl + nWq);
    split_bf16<<<(int)(nWk  / 1024), 256>>>((const float4*)wv, wqkvh + nWq + nWk, wqkvl + nWq + nWk);
    split_bf16<<<(int)(nWq  / 1024), 256>>>((const float4*)wo, woh, wol);

    // Fused QKV projection
    gemm_bf16x2<<<dim3(NQKV / 128, MROWS / 128), 256, GEMM_SMEM>>>(
        hidh, hidl, wqkvh, wqkvl, qkv, MROWS, NQKV, HDIM);

    // RMSNorm + RoPE -> bf16 hi/lo operands (+ fp32 K into d_out)
    norm_rope_q<<<(MROWS * NH ) / 8, 256>>>(qkv, qh, ql, cosb, sinb, qg);
    norm_rope_k<<<(MROWS * NKV) / 8, 256>>>(qkv, kout, kh, kl, cosb, sinb, kg);

    // V: fp32 into d_out's new_v; bf16 hi/lo transposed (b,KV,D,s)
    v_transpose<<<(NB * SEQ * NKV * HD / 4) / 256, 256>>>((const float4*)qkv, (float4*)vout);
    vtrans_split<<<dim3(SEQ / 32, HD / 32, NB * NKV), dim3(32, 8)>>>(qkv, vh, vl);

    // Tensor-core causal GQA flash attention (BM=128, cp.async KV) -> bf16 hi/lo O
    flash_mma<<<dim3(SEQ / 128, NH, NB), 256, FLASH_SMEM>>>(
        qh, ql, kh, kl, vh, vl, aoh, aol);

    // Output projection
    gemm_bf16x2<<<dim3(HDIM / 128, MROWS / 128), 256, GEMM_SMEM>>>(
        aoh, aol, woh, wol, out, MROWS, HDIM, NH * HD);
}

// round 11
// speedup vs baseline: 1.2761x; 1.0006x over previous
#include <cuda_runtime.h>
#include <cuda_bf16.h>
#include <cstdint>

// Problem constants
constexpr int NB   = 2;      // batch
constexpr int SEQ  = 2048;   // sequence
constexpr int HDIM = 2560;   // hidden
constexpr int NH   = 32;     // q heads
constexpr int NKV  = 8;      // kv heads
constexpr int HD   = 128;    // head dim
constexpr int GQ   = NH / NKV;
constexpr int MROWS = NB * SEQ;            // 4096
constexpr int NQKV  = (NH + 2 * NKV) * HD; // 6144
constexpr int KOFF  = NH * HD;             // 4096
constexpr int VOFF  = (NH + NKV) * HD;     // 5120
constexpr float SM_SCALE = 0.08838834764831845f;  // 1/sqrt(128)

// ---------------- device scratch (no allocation allowed) ----------------
__device__ __nv_bfloat16 g_hid_h [(size_t)MROWS * HDIM];
__device__ __nv_bfloat16 g_hid_l [(size_t)MROWS * HDIM];
__device__ __nv_bfloat16 g_wqkv_h[(size_t)NQKV * HDIM];
__device__ __nv_bfloat16 g_wqkv_l[(size_t)NQKV * HDIM];
__device__ __nv_bfloat16 g_wo_h  [(size_t)HDIM * NH * HD];
__device__ __nv_bfloat16 g_wo_l  [(size_t)HDIM * NH * HD];
__device__ __nv_bfloat16 g_ao_h  [(size_t)MROWS * NH * HD];
__device__ __nv_bfloat16 g_ao_l  [(size_t)MROWS * NH * HD];
__device__ float g_qkv[(size_t)MROWS * NQKV];       // 96MB
// bf16 hi/lo attention operands
__device__ __nv_bfloat16 g_qh[(size_t)NB * NH  * SEQ * HD];  // (b,H,s,D), pre-scaled
__device__ __nv_bfloat16 g_ql[(size_t)NB * NH  * SEQ * HD];
__device__ __nv_bfloat16 g_kh[(size_t)NB * NKV * SEQ * HD];  // (b,KV,s,D)
__device__ __nv_bfloat16 g_kl[(size_t)NB * NKV * SEQ * HD];
__device__ __nv_bfloat16 g_vh[(size_t)NB * NKV * HD * SEQ];  // (b,KV,D,s) transposed
__device__ __nv_bfloat16 g_vl[(size_t)NB * NKV * HD * SEQ];

// ---------------------------------------------------------------------------
// cp.async / ldmatrix helpers
// ---------------------------------------------------------------------------
__device__ __forceinline__ void cp16(uint32_t smem, const __nv_bfloat16* gmem)
{
    asm volatile("cp.async.cg.shared.global [%0], [%1], 16;\n" :: "r"(smem), "l"(gmem));
}
#define CP_COMMIT() asm volatile("cp.async.commit_group;\n" ::: "memory")
#define CP_WAIT(n)  asm volatile("cp.async.wait_group %0;\n" :: "n"(n) : "memory")

__device__ __forceinline__ void ldsm4(uint32_t* r, const __nv_bfloat16* p)
{
    uint32_t a = (uint32_t)__cvta_generic_to_shared(p);
    asm volatile("ldmatrix.sync.aligned.m8n8.x4.shared.b16 {%0,%1,%2,%3}, [%4];"
        : "=r"(r[0]), "=r"(r[1]), "=r"(r[2]), "=r"(r[3]) : "r"(a));
}

// ---------------------------------------------------------------------------
// fp32 -> bf16 hi/lo split
// ---------------------------------------------------------------------------
__global__ __launch_bounds__(256) void split_bf16(
    const float4* __restrict__ in, __nv_bfloat16* __restrict__ hi,
    __nv_bfloat16* __restrict__ lo)
{
    const size_t i = (size_t)blockIdx.x * 256 + threadIdx.x;
    float4 x = in[i];
    __nv_bfloat16 h[4], l[4];
    float xs[4] = {x.x, x.y, x.z, x.w};
#pragma unroll
    for (int j = 0; j < 4; j++) {
        h[j] = __float2bfloat16(xs[j]);
        l[j] = __float2bfloat16(xs[j] - __bfloat162float(h[j]));
    }
    *(uint2*)&hi[i * 4] = *(uint2*)h;
    *(uint2*)&lo[i * 4] = *(uint2*)l;
}

// ---------------------------------------------------------------------------
// mma.m16n8k16 bf16 wrapper
// ---------------------------------------------------------------------------
__device__ __forceinline__ void mma16816(float* c, const uint32_t* a, const uint32_t* b)
{
    asm volatile(
        "mma.sync.aligned.m16n8k16.row.col.f32.bf16.bf16.f32 "
        "{%0,%1,%2,%3}, {%4,%5,%6,%7}, {%8,%9}, {%0,%1,%2,%3};"
        : "+f"(c[0]), "+f"(c[1]), "+f"(c[2]), "+f"(c[3])
        : "r"(a[0]), "r"(a[1]), "r"(a[2]), "r"(a[3]), "r"(b[0]), "r"(b[1]));
}

__device__ __forceinline__ uint32_t pack_hilo(float x, float y, uint32_t& lo)
{
    __nv_bfloat162 h = __float22bfloat162_rn(make_float2(x, y));
    float rx = x - __bfloat162float(h.x);
    float ry = y - __bfloat162float(h.y);
    __nv_bfloat162 l = __float22bfloat162_rn(make_float2(rx, ry));
    lo = *(uint32_t*)&l;
    return *(uint32_t*)&h;
}

// ---------------------------------------------------------------------------
// bf16-split tensor-core GEMM: C[M,N] = A[M,K] @ B[N,K]^T   (fp32 accurate)
// BK=32, 2-stage cp.async pipeline, ONE __syncthreads per iteration,
// 2 CTAs/SM. Block 128x128, 256 threads (8 warps, 32x64 warp tile).
// MMA issue round-robins across the 4 accumulators per np (distance-4
// dependency chains instead of distance-1).
// ---------------------------------------------------------------------------
constexpr int GPAD = 40;                      // smem row pitch (bf16): 80B, ldsm conflict-free
constexpr int GSTG = 128 * GPAD;              // bf16 per matrix per stage (5120)
constexpr int GEMM_SMEM = 2 * 4 * GSTG * 2;   // 81920 bytes

__global__ __launch_bounds__(256, 2) void gemm_bf16x2(
    const __nv_bfloat16* __restrict__ Ah, const __nv_bfloat16* __restrict__ Al,
    const __nv_bfloat16* __restrict__ Bh, const __nv_bfloat16* __restrict__ Bl,
    float* __restrict__ C, int M, int N, int K)
{
    extern __shared__ __nv_bfloat16 sb[];

    const int tid = threadIdx.x;
    const int bm = blockIdx.y * 128;
    const int bn = blockIdx.x * 128;
    const int lane = tid & 31;
    const int wid  = tid >> 5;
    const int wm = (wid & 3) * 32;
    const int wn = (wid >> 2) * 64;
    const int grp = lane >> 2;
    const int tig = lane & 3;

    const int lrow  = lane & 15;
    const int lcoff = (lane >> 4) * 8;
    const int brow  = (lane & 7) + ((lane >> 4) << 3);
    const int bcoff = ((lane >> 3) & 1) * 8;

    uint32_t soff[2];
    int grow[2], gcol[2];
#pragma unroll
    for (int j = 0; j < 2; j++) {
        int c = tid + j * 256;
        grow[j] = c >> 2;
        gcol[j] = (c & 3) * 8;
        soff[j] = (uint32_t)(grow[j] * GPAD + gcol[j]);
    }

    float acc[2][8][4];
#pragma unroll
    for (int mt = 0; mt < 2; mt++)
#pragma unroll
        for (int nt = 0; nt < 8; nt++)
#pragma unroll
            for (int e = 0; e < 4; e++) acc[mt][nt][e] = 0.f;

    uint32_t sbase = (uint32_t)__cvta_generic_to_shared(sb);
    const int nk = K / 32;

#pragma unroll
    for (int j = 0; j < 2; j++) {
        cp16(sbase + (0 * GSTG + soff[j]) * 2, Ah + (size_t)(bm + grow[j]) * K + gcol[j]);
        cp16(sbase + (1 * GSTG + soff[j]) * 2, Al + (size_t)(bm + grow[j]) * K + gcol[j]);
        cp16(sbase + (2 * GSTG + soff[j]) * 2, Bh + (size_t)(bn + grow[j]) * K + gcol[j]);
        cp16(sbase + (3 * GSTG + soff[j]) * 2, Bl + (size_t)(bn + grow[j]) * K + gcol[j]);
    }
    CP_COMMIT();

    for (int i = 0; i < nk; i++) {
        const __nv_bfloat16* cur = sb + (size_t)(i & 1) * 4 * GSTG;

        CP_WAIT(0);
        __syncthreads();

        if (i + 1 < nk) {
            const uint32_t nxt = sbase + (uint32_t)(((i + 1) & 1) * 4 * GSTG) * 2;
            const int k0 = (i + 1) * 32;
#pragma unroll
            for (int j = 0; j < 2; j++) {
                cp16(nxt + (0 * GSTG + soff[j]) * 2, Ah + (size_t)(bm + grow[j]) * K + k0 + gcol[j]);
                cp16(nxt + (1 * GSTG + soff[j]) * 2, Al + (size_t)(bm + grow[j]) * K + k0 + gcol[j]);
                cp16(nxt + (2 * GSTG + soff[j]) * 2, Bh + (size_t)(bn + grow[j]) * K + k0 + gcol[j]);
                cp16(nxt + (3 * GSTG + soff[j]) * 2, Bl + (size_t)(bn + grow[j]) * K + k0 + gcol[j]);
            }
            CP_COMMIT();
        }

        const __nv_bfloat16* sAh = cur;
        const __nv_bfloat16* sAl = cur + 1 * GSTG;
        const __nv_bfloat16* sBh = cur + 2 * GSTG;
        const __nv_bfloat16* sBl = cur + 3 * GSTG;

#pragma unroll
        for (int kk = 0; kk < 32; kk += 16) {
            uint32_t afh[2][4], afl[2][4];
            const int acol = kk + lcoff;
            ldsm4(afh[0], &sAh[(wm + lrow     ) * GPAD + acol]);
            ldsm4(afh[1], &sAh[(wm + 16 + lrow) * GPAD + acol]);
            ldsm4(afl[0], &sAl[(wm + lrow     ) * GPAD + acol]);
            ldsm4(afl[1], &sAl[(wm + 16 + lrow) * GPAD + acol]);
#pragma unroll
            for (int np = 0; np < 4; np++) {
                const int br = wn + np * 16 + brow;
                const int bc = kk + bcoff;
                uint32_t bh[4], bl[4];
                ldsm4(bh, &sBh[br * GPAD + bc]);
                ldsm4(bl, &sBl[br * GPAD + bc]);
                // round-robin across the 4 accumulators: chain distance 4
                mma16816(acc[0][2 * np    ], afh[0], bh);
                mma16816(acc[1][2 * np    ], afh[1], bh);
                mma16816(acc[0][2 * np + 1], afh[0], bh + 2);
                mma16816(acc[1][2 * np + 1], afh[1], bh + 2);
                mma16816(acc[0][2 * np    ], afh[0], bl);
                mma16816(acc[1][2 * np    ], afh[1], bl);
                mma16816(acc[0][2 * np + 1], afh[0], bl + 2);
                mma16816(acc[1][2 * np + 1], afh[1], bl + 2);
                mma16816(acc[0][2 * np    ], afl[0], bh);
                mma16816(acc[1][2 * np    ], afl[1], bh);
                mma16816(acc[0][2 * np + 1], afl[0], bh + 2);
                mma16816(acc[1][2 * np + 1], afl[1], bh + 2);
            }
        }
    }

#pragma unroll
    for (int mt = 0; mt < 2; mt++) {
        const int row = bm + wm + mt * 16 + grp;
#pragma unroll
        for (int nt = 0; nt < 8; nt++) {
            const int col = bn + wn + nt * 8 + tig * 2;
            *(float2*)&C[(size_t)row * N + col]       = make_float2(acc[mt][nt][0], acc[mt][nt][1]);
            *(float2*)&C[(size_t)(row + 8) * N + col] = make_float2(acc[mt][nt][2], acc[mt][nt][3]);
        }
    }
}

// ---------------------------------------------------------------------------
// RMSNorm + RoPE for Q: reads qkv fp32, writes bf16 hi/lo to (b,H,s,D),
// pre-scaled by 1/sqrt(D). One warp per row.
// ---------------------------------------------------------------------------
__global__ __launch_bounds__(256) void norm_rope_q(
    const float* __restrict__ qkv,
    __nv_bfloat16* __restrict__ oh, __nv_bfloat16* __restrict__ ol,
    const float* __restrict__ cs, const float* __restrict__ sn,
    const float* __restrict__ gamma)
{
    const int warp = (blockIdx.x * 256 + threadIdx.x) >> 5;
    const int lane = threadIdx.x & 31;
    const int h  = warp % NH;
    const int bs = warp / NH;
    const int sp = bs % SEQ;
    const int bi = bs / SEQ;

    const float* x = qkv + (size_t)bs * NQKV + h * HD;
    float e0 = x[lane], e1 = x[lane + 32], e2 = x[lane + 64], e3 = x[lane + 96];

    float ssq = e0 * e0 + e1 * e1 + e2 * e2 + e3 * e3;
#pragma unroll
    for (int o = 16; o; o >>= 1) ssq += __shfl_xor_sync(0xffffffffu, ssq, o);
    const float r = rsqrtf(ssq * (1.0f / HD) + 1e-6f);

    e0 *= r * gamma[lane];      e1 *= r * gamma[lane + 32];
    e2 *= r * gamma[lane + 64]; e3 *= r * gamma[lane + 96];

    const float* cp = cs + (size_t)bs * HD;
    const float* sg = sn + (size_t)bs * HD;
    float o4[4];
    o4[0] = (e0 * cp[lane]      - e2 * sg[lane])      * SM_SCALE;
    o4[1] = (e1 * cp[lane + 32] - e3 * sg[lane + 32]) * SM_SCALE;
    o4[2] = (e2 * cp[lane + 64] + e0 * sg[lane + 64]) * SM_SCALE;
    o4[3] = (e3 * cp[lane + 96] + e1 * sg[lane + 96]) * SM_SCALE;

    const size_t ob = (((size_t)bi * NH + h) * SEQ + sp) * HD;
#pragma unroll
    for (int j = 0; j < 4; j++) {
        __nv_bfloat16 hv = __float2bfloat16(o4[j]);
        oh[ob + lane + 32 * j] = hv;
        ol[ob + lane + 32 * j] = __float2bfloat16(o4[j] - __bfloat162float(hv));
    }
}

// ---------------------------------------------------------------------------
// RMSNorm + RoPE for K: writes fp32 (b,KV,s,D) into d_out AND bf16 hi/lo.
// ---------------------------------------------------------------------------
__global__ __launch_bounds__(256) void norm_rope_k(
    const float* __restrict__ qkv, float* __restrict__ kout,
    __nv_bfloat16* __restrict__ oh, __nv_bfloat16* __restrict__ ol,
    const float* __restrict__ cs, const float* __restrict__ sn,
    const float* __restrict__ gamma)
{
    const int warp = (blockIdx.x * 256 + threadIdx.x) >> 5;
    const int lane = threadIdx.x & 31;
    const int h  = warp % NKV;
    const int bs = warp / NKV;
    const int sp = bs % SEQ;
    const int bi = bs / SEQ;

    const float* x = qkv + (size_t)bs * NQKV + KOFF + h * HD;
    float e0 = x[lane], e1 = x[lane + 32], e2 = x[lane + 64], e3 = x[lane + 96];

    float ssq = e0 * e0 + e1 * e1 + e2 * e2 + e3 * e3;
#pragma unroll
    for (int o = 16; o; o >>= 1) ssq += __shfl_xor_sync(0xffffffffu, ssq, o);
    const float r = rsqrtf(ssq * (1.0f / HD) + 1e-6f);

    e0 *= r * gamma[lane];      e1 *= r * gamma[lane + 32];
    e2 *= r * gamma[lane + 64]; e3 *= r * gamma[lane + 96];

    const float* cp = cs + (size_t)bs * HD;
    const float* sg = sn + (size_t)bs * HD;
    float o4[4];
    o4[0] = e0 * cp[lane]      - e2 * sg[lane];
    o4[1] = e1 * cp[lane + 32] - e3 * sg[lane + 32];
    o4[2] = e2 * cp[lane + 64] + e0 * sg[lane + 64];
    o4[3] = e3 * cp[lane + 96] + e1 * sg[lane + 96];

    const size_t ob = (((size_t)bi * NKV + h) * SEQ + sp) * HD;
#pragma unroll
    for (int j = 0; j < 4; j++) {
        kout[ob + lane + 32 * j] = o4[j];
        __nv_bfloat16 hv = __float2bfloat16(o4[j]);
        oh[ob + lane + 32 * j] = hv;
        ol[ob + lane + 32 * j] = __float2bfloat16(o4[j] - __bfloat162float(hv));
    }
}

// ---------------------------------------------------------------------------
// V transpose (fp32): qkv V region -> (b,KV,s,D) in d_out
// ---------------------------------------------------------------------------
__global__ __launch_bounds__(256) void v_transpose(
    const float4* __restrict__ qkv4, float4* __restrict__ out)
{
    const size_t i = (size_t)blockIdx.x * 256 + threadIdx.x;
    const int d4 = (int)(i & 31);
    const int kh = (int)((i >> 5) & (NKV - 1));
    const int sp = (int)((i >> 8) & (SEQ - 1));
    const int bi = (int)(i >> 19);
    const size_t src = ((size_t)(bi * SEQ + sp) * NQKV + VOFF + kh * HD) / 4 + d4;
    const size_t dst = (((size_t)bi * NKV + kh) * SEQ + sp) * 32 + d4;
    out[dst] = qkv4[src];
}

// ---------------------------------------------------------------------------
// V transpose + split (bf16): qkv V region -> (b,KV,D,s) hi/lo
// ---------------------------------------------------------------------------
__global__ void vtrans_split(
    const float* __restrict__ qkv,
    __nv_bfloat16* __restrict__ vh, __nv_bfloat16* __restrict__ vl)
{
    __shared__ float t[32][33];
    const int s0 = blockIdx.x * 32, d0 = blockIdx.y * 32;
    const int bz = blockIdx.z;                 // bi*NKV + kh
    const int bi = bz / NKV, kh = bz % NKV;
    const int tx = threadIdx.x, ty = threadIdx.y;

#pragma unroll
    for (int j = 0; j < 4; j++) {
        int s = s0 + ty + j * 8;
        t[ty + j * 8][tx] =
            qkv[(size_t)(bi * SEQ + s) * NQKV + VOFF + kh * HD + d0 + tx];
    }
    __syncthreads();
#pragma unroll
    for (int j = 0; j < 4; j++) {
        int d = d0 + ty + j * 8;
        float v = t[tx][ty + j * 8];
        __nv_bfloat16 hv = __float2bfloat16(v);
        size_t idx = ((size_t)bz * HD + d) * SEQ + s0 + tx;
        vh[idx] = hv;
        vl[idx] = __float2bfloat16(v - __bfloat162float(hv));
    }
}

// ---------------------------------------------------------------------------
// Tensor-core causal flash attention, bf16 hi/lo split, ldmatrix loads.
// BM=128, BN=64, 256 threads (8 warps, 16 Q rows each).
// K/V tiles double-buffered via cp.async. MMA issue interleaved across
// accumulator pairs (distance-2 chains).
// ---------------------------------------------------------------------------
constexpr int FQP = 136;  // pitch (bf16) for Q/K tiles
constexpr int FVP = 72;   // pitch (bf16) for Vt tiles
constexpr int FKV = 2 * 64 * FQP + 2 * 128 * FVP;   // KV stage elems (35840)
constexpr int FLASH_SMEM = (2 * 128 * FQP + 2 * FKV) * 2;  // 213 KB

__global__ __launch_bounds__(256, 1) void flash_mma(
    const __nv_bfloat16* __restrict__ Qh, const __nv_bfloat16* __restrict__ Ql,
    const __nv_bfloat16* __restrict__ Kh, const __nv_bfloat16* __restrict__ Kl,
    const __nv_bfloat16* __restrict__ Vh, const __nv_bfloat16* __restrict__ Vl,
    __nv_bfloat16* __restrict__ Oh, __nv_bfloat16* __restrict__ Ol)
{
    extern __shared__ __nv_bfloat16 sm[];
    __nv_bfloat16* sQh = sm;
    __nv_bfloat16* sQl = sQh + 128 * FQP;
    __nv_bfloat16* sKV = sQl + 128 * FQP;    // 2 stages of [Kh|Kl|Vh|Vl]

    const int qtile = blockIdx.x;
    const int h     = blockIdx.y;
    const int bi    = blockIdx.z;
    const int kh    = h / GQ;
    const int tid   = threadIdx.x;
    const int lane  = tid & 31;
    const int wid   = tid >> 5;
    const int grp   = lane >> 2;
    const int tig   = lane & 3;
    const int q0    = qtile * 128;

    const int lrow  = lane & 15;
    const int lcoff = (lane >> 4) * 8;
    const int brow  = (lane & 7) + ((lane >> 4) << 3);
    const int bcoff = ((lane >> 3) & 1) * 8;

    const __nv_bfloat16* kgh = Kh + (((size_t)bi * NKV + kh) * SEQ) * HD;
    const __nv_bfloat16* kgl = Kl + (((size_t)bi * NKV + kh) * SEQ) * HD;
    const __nv_bfloat16* vgh = Vh + (((size_t)bi * NKV + kh) * HD) * SEQ;
    const __nv_bfloat16* vgl = Vl + (((size_t)bi * NKV + kh) * HD) * SEQ;
    const uint32_t skv = (uint32_t)__cvta_generic_to_shared(sKV);

    int kr[4], kc[4], vr[4], vc[4];
    uint32_t kso[4], vso[4];
#pragma unroll
    for (int j = 0; j < 4; j++) {
        int c = tid + j * 256;
        kr[j] = c >> 4; kc[j] = (c & 15) * 8;
        kso[j] = (uint32_t)(kr[j] * FQP + kc[j]);
        vr[j] = c >> 3; vc[j] = (c & 7) * 8;
        vso[j] = (uint32_t)(vr[j] * FVP + vc[j]);
    }

    auto issue_kv = [&](int s, int k0) {
        const uint32_t st = skv + (uint32_t)(s * FKV) * 2;
#pragma unroll
        for (int j = 0; j < 4; j++) {
            cp16(st + kso[j] * 2,                       kgh + (size_t)(k0 + kr[j]) * HD + kc[j]);
            cp16(st + (64 * FQP + kso[j]) * 2,          kgl + (size_t)(k0 + kr[j]) * HD + kc[j]);
            cp16(st + (2 * 64 * FQP + vso[j]) * 2,      vgh + (size_t)vr[j] * SEQ + k0 + vc[j]);
            cp16(st + (2 * 64 * FQP + 128 * FVP + vso[j]) * 2,
                                                        vgl + (size_t)vr[j] * SEQ + k0 + vc[j]);
        }
        CP_COMMIT();
    };

    // Q tile load (128 x 128, hi+lo) -- plain loads, once
    {
        const __nv_bfloat16* qgh = Qh + (((size_t)bi * NH + h) * SEQ + q0) * HD;
        const __nv_bfloat16* qgl = Ql + (((size_t)bi * NH + h) * SEQ + q0) * HD;
        for (int i = tid; i < 128 * 16; i += 256) {
            int r = i >> 4, c = (i & 15) * 8;
            *(uint4*)&sQh[r * FQP + c] = *(const uint4*)&qgh[(size_t)r * HD + c];
            *(uint4*)&sQl[r * FQP + c] = *(const uint4*)&qgl[(size_t)r * HD + c];
        }
    }

    float o[16][4];
#pragma unroll
    for (int nt = 0; nt < 16; nt++)
#pragma unroll
        for (int e = 0; e < 4; e++) o[nt][e] = 0.f;
    float m0 = -1e30f, m1 = -1e30f, l0 = 0.f, l1 = 0.f;

    const int ntiles = 2 * qtile + 2;

    issue_kv(0, 0);   // prologue

    for (int t = 0; t < ntiles; ++t) {
        const int k0 = t * 64;
        const __nv_bfloat16* cur = sKV + (size_t)(t & 1) * FKV;
        const __nv_bfloat16* sKh = cur;
        const __nv_bfloat16* sKl = cur + 64 * FQP;
        const __nv_bfloat16* sVh = cur + 2 * 64 * FQP;
        const __nv_bfloat16* sVl = cur + 2 * 64 * FQP + 128 * FVP;

        CP_WAIT(0);
        __syncthreads();

        if (t + 1 < ntiles) issue_kv((t + 1) & 1, (t + 1) * 64);

        float s[8][4];
#pragma unroll
        for (int nt = 0; nt < 8; nt++)
#pragma unroll
            for (int e = 0; e < 4; e++) s[nt][e] = 0.f;

#pragma unroll
        for (int kk = 0; kk < 128; kk += 16) {
            uint32_t ah[4], al[4];
            const int acol = kk + lcoff;
            ldsm4(ah, &sQh[(wid * 16 + lrow) * FQP + acol]);
            ldsm4(al, &sQl[(wid * 16 + lrow) * FQP + acol]);
#pragma unroll
            for (int np = 0; np < 4; np++) {
                const int br = np * 16 + brow;
                const int bc = kk + bcoff;
                uint32_t bh[4], bl[4];
                ldsm4(bh, &sKh[br * FQP + bc]);
                ldsm4(bl, &sKl[br * FQP + bc]);
                // interleaved: distance-2 chains
                mma16816(s[2 * np    ], ah, bh);
                mma16816(s[2 * np + 1], ah, bh + 2);
                mma16816(s[2 * np    ], al, bh);
                mma16816(s[2 * np + 1], al, bh + 2);
                mma16816(s[2 * np    ], ah, bl);
                mma16816(s[2 * np + 1], ah, bl + 2);
            }
        }

        if (t >= ntiles - 2) {   // causal mask (last two tiles span the diagonal)
            const int r0 = q0 + wid * 16 + grp;
#pragma unroll
            for (int nt = 0; nt < 8; nt++) {
                const int c = k0 + nt * 8 + tig * 2;
                if (c     > r0)     s[nt][0] = -1e30f;
                if (c + 1 > r0)     s[nt][1] = -1e30f;
                if (c     > r0 + 8) s[nt][2] = -1e30f;
                if (c + 1 > r0 + 8) s[nt][3] = -1e30f;
            }
        }

        float mx0 = -1e30f, mx1 = -1e30f;
#pragma unroll
        for (int nt = 0; nt < 8; nt++) {
            mx0 = fmaxf(mx0, fmaxf(s[nt][0], s[nt][1]));
            mx1 = fmaxf(mx1, fmaxf(s[nt][2], s[nt][3]));
        }
        mx0 = fmaxf(mx0, __shfl_xor_sync(0xffffffffu, mx0, 1));
        mx0 = fmaxf(mx0, __shfl_xor_sync(0xffffffffu, mx0, 2));
        mx1 = fmaxf(mx1, __shfl_xor_sync(0xffffffffu, mx1, 1));
        mx1 = fmaxf(mx1, __shfl_xor_sync(0xffffffffu, mx1, 2));

        const float nm0 = fmaxf(m0, mx0);
        const float nm1 = fmaxf(m1, mx1);
        const float a0 = __expf(m0 - nm0);
        const float a1 = __expf(m1 - nm1);
        m0 = nm0; m1 = nm1;

        float rs0 = 0.f, rs1 = 0.f;
#pragma unroll
        for (int nt = 0; nt < 8; nt++) {
            s[nt][0] = __expf(s[nt][0] - m0);
            s[nt][1] = __expf(s[nt][1] - m0);
            s[nt][2] = __expf(s[nt][2] - m1);
            s[nt][3] = __expf(s[nt][3] - m1);
            rs0 += s[nt][0] + s[nt][1];
            rs1 += s[nt][2] + s[nt][3];
        }
        rs0 += __shfl_xor_sync(0xffffffffu, rs0, 1);
        rs0 += __shfl_xor_sync(0xffffffffu, rs0, 2);
        rs1 += __shfl_xor_sync(0xffffffffu, rs1, 1);
        rs1 += __shfl_xor_sync(0xffffffffu, rs1, 2);
        l0 = l0 * a0 + rs0;
        l1 = l1 * a1 + rs1;

#pragma unroll
        for (int nt = 0; nt < 16; nt++) {
            o[nt][0] *= a0; o[nt][1] *= a0;
            o[nt][2] *= a1; o[nt][3] *= a1;
        }

#pragma unroll
        for (int ks = 0; ks < 4; ks++) {
            uint32_t ph[4], pl[4];
            ph[0] = pack_hilo(s[2 * ks][0],     s[2 * ks][1],     pl[0]);
            ph[1] = pack_hilo(s[2 * ks][2],     s[2 * ks][3],     pl[1]);
            ph[2] = pack_hilo(s[2 * ks + 1][0], s[2 * ks + 1][1], pl[2]);
            ph[3] = pack_hilo(s[2 * ks + 1][2], s[2 * ks + 1][3], pl[3]);
            const int bc = ks * 16 + bcoff;
#pragma unroll
            for (int np = 0; np < 8; np++) {
                const int br = np * 16 + brow;
                uint32_t vh4[4], vl4[4];
                ldsm4(vh4, &sVh[br * FVP + bc]);
                ldsm4(vl4, &sVl[br * FVP + bc]);
                // interleaved: distance-2 chains
                mma16816(o[2 * np    ], ph, vh4);
                mma16816(o[2 * np + 1], ph, vh4 + 2);
                mma16816(o[2 * np    ], pl, vh4);
                mma16816(o[2 * np + 1], pl, vh4 + 2);
                mma16816(o[2 * np    ], ph, vl4);
                mma16816(o[2 * np + 1], ph, vl4 + 2);
            }
        }
    }

    const float i0 = 1.0f / l0;
    const float i1 = 1.0f / l1;
    const size_t row0 = (size_t)bi * SEQ + q0 + wid * 16 + grp;
    const size_t row1 = row0 + 8;
    const int colb = h * HD + tig * 2;
#pragma unroll
    for (int nt = 0; nt < 16; nt++) {
        uint32_t lo;
        uint32_t hi = pack_hilo(o[nt][0] * i0, o[nt][1] * i0, lo);
        *(uint32_t*)&Oh[row0 * (NH * HD) + colb + nt * 8] = hi;
        *(uint32_t*)&Ol[row0 * (NH * HD) + colb + nt * 8] = lo;
        hi = pack_hilo(o[nt][2] * i1, o[nt][3] * i1, lo);
        *(uint32_t*)&Oh[row1 * (NH * HD) + colb + nt * 8] = hi;
        *(uint32_t*)&Ol[row1 * (NH * HD) + colb + nt * 8] = lo;
    }
}

// ---------------------------------------------------------------------------
// kernel_launch
// ---------------------------------------------------------------------------
extern "C" void kernel_launch(void* const* d_in, const int* in_sizes, int n_in,
                              void* d_out, int out_size)
{
    const float* hidden = (const float*)d_in[0];
    const float* cosb   = (const float*)d_in[1];
    const float* sinb   = (const float*)d_in[2];
    const float* wq     = (const float*)d_in[3];
    const float* wk     = (const float*)d_in[4];
    const float* wv     = (const float*)d_in[5];
    const float* wo     = (const float*)d_in[6];
    const float* qg     = (const float*)d_in[7];
    const float* kg     = (const float*)d_in[8];

    float* out  = (float*)d_out;
    float* kout = out  + (size_t)NB * SEQ * HDIM;
    float* vout = kout + (size_t)NB * NKV * SEQ * HD;

    __nv_bfloat16 *hidh, *hidl, *wqkvh, *wqkvl, *woh, *wol, *aoh, *aol;
    __nv_bfloat16 *qh, *ql, *kh, *kl, *vh, *vl;
    float *qkv;
    cudaGetSymbolAddress((void**)&hidh,  g_hid_h);
    cudaGetSymbolAddress((void**)&hidl,  g_hid_l);
    cudaGetSymbolAddress((void**)&wqkvh, g_wqkv_h);
    cudaGetSymbolAddress((void**)&wqkvl, g_wqkv_l);
    cudaGetSymbolAddress((void**)&woh,   g_wo_h);
    cudaGetSymbolAddress((void**)&wol,   g_wo_l);
    cudaGetSymbolAddress((void**)&aoh,   g_ao_h);
    cudaGetSymbolAddress((void**)&aol,   g_ao_l);
    cudaGetSymbolAddress((void**)&qkv,   g_qkv);
    cudaGetSymbolAddress((void**)&qh,    g_qh);
    cudaGetSymbolAddress((void**)&ql,    g_ql);
    cudaGetSymbolAddress((void**)&kh,    g_kh);
    cudaGetSymbolAddress((void**)&kl,    g_kl);
    cudaGetSymbolAddress((void**)&vh,    g_vh);
    cudaGetSymbolAddress((void**)&vl,    g_vl);

    cudaFuncSetAttribute(flash_mma, cudaFuncAttributeMaxDynamicSharedMemorySize, FLASH_SMEM);
    cudaFuncSetAttribute(gemm_bf16x2, cudaFuncAttributeMaxDynamicSharedMemorySize, GEMM_SMEM);

    // fp32 -> bf16 hi/lo splits
    const size_t nHid = (size_t)MROWS * HDIM;
    const size_t nWq  = (size_t)NH  * HD * HDIM;
    const size_t nWk  = (size_t)NKV * HD * HDIM;
    split_bf16<<<(int)(nHid / 1024), 256>>>((const float4*)hidden, hidh, hidl);
    split_bf16<<<(int)(nWq  / 1024), 256>>>((const float4*)wq, wqkvh, wqkvl);
    split_bf16<<<(int)(nWk  / 1024), 256>>>((const float4*)wk, wqkvh + nWq, wqkvl + nWq);
    split_bf16<<<(int)(nWk  / 1024), 256>>>((const float4*)wv, wqkvh + nWq + nWk, wqkvl + nWq + nWk);
    split_bf16<<<(int)(nWq  / 1024), 256>>>((const float4*)wo, woh, wol);

    // Fused QKV projection
    gemm_bf16x2<<<dim3(NQKV / 128, MROWS / 128), 256, GEMM_SMEM>>>(
        hidh, hidl, wqkvh, wqkvl, qkv, MROWS, NQKV, HDIM);

    // RMSNorm + RoPE -> bf16 hi/lo operands (+ fp32 K into d_out)
    norm_rope_q<<<(MROWS * NH ) / 8, 256>>>(qkv, qh, ql, cosb, sinb, qg);
    norm_rope_k<<<(MROWS * NKV) / 8, 256>>>(qkv, kout, kh, kl, cosb, sinb, kg);

    // V: fp32 into d_out's new_v; bf16 hi/lo transposed (b,KV,D,s)
    v_transpose<<<(NB * SEQ * NKV * HD / 4) / 256, 256>>>((const float4*)qkv, (float4*)vout);
    vtrans_split<<<dim3(SEQ / 32, HD / 32, NB * NKV), dim3(32, 8)>>>(qkv, vh, vl);

    // Tensor-core causal GQA flash attention (BM=128, cp.async KV) -> bf16 hi/lo O
    flash_mma<<<dim3(SEQ / 128, NH, NB), 256, FLASH_SMEM>>>(
        qh, ql, kh, kl, vh, vl, aoh, aol);

    // Output projection
    gemm_bf16x2<<<dim3(HDIM / 128, MROWS / 128), 256, GEMM_SMEM>>>(
        aoh, aol, woh, wol, out, MROWS, HDIM, NH * HD);
}

// round 12
// speedup vs baseline: 1.7962x; 1.4076x over previous
#include <cuda_runtime.h>
#include <cuda_fp16.h>
#include <cstdint>

// Problem constants
constexpr int NB   = 2;      // batch
constexpr int SEQ  = 2048;   // sequence
constexpr int HDIM = 2560;   // hidden
constexpr int NH   = 32;     // q heads
constexpr int NKV  = 8;      // kv heads
constexpr int HD   = 128;    // head dim
constexpr int GQ   = NH / NKV;
constexpr int MROWS = NB * SEQ;            // 4096
constexpr int NQKV  = (NH + 2 * NKV) * HD; // 6144
constexpr int KOFF  = NH * HD;             // 4096
constexpr int VOFF  = (NH + NKV) * HD;     // 5120
constexpr float SM_SCALE = 0.08838834764831845f;  // 1/sqrt(128)

// ---------------- device scratch (no allocation allowed) ----------------
__device__ __half g_hid_h [(size_t)MROWS * HDIM];
__device__ __half g_hid_l [(size_t)MROWS * HDIM];
__device__ __half g_wqkv  [(size_t)NQKV * HDIM];        // single fp16
__device__ __half g_wo    [(size_t)HDIM * NH * HD];     // single fp16
__device__ __half g_ao_h  [(size_t)MROWS * NH * HD];
__device__ __half g_ao_l  [(size_t)MROWS * NH * HD];
__device__ float g_qkv[(size_t)MROWS * NQKV];           // 96MB
// fp16 attention operands
__device__ __half g_qh[(size_t)NB * NH  * SEQ * HD];    // (b,H,s,D), pre-scaled, hi
__device__ __half g_ql[(size_t)NB * NH  * SEQ * HD];    // lo
__device__ __half g_kf[(size_t)NB * NKV * SEQ * HD];    // (b,KV,s,D) single
__device__ __half g_vf[(size_t)NB * NKV * HD * SEQ];    // (b,KV,D,s) transposed single

// ---------------------------------------------------------------------------
// cp.async / ldmatrix helpers
// ---------------------------------------------------------------------------
__device__ __forceinline__ void cp16(uint32_t smem, const void* gmem)
{
    asm volatile("cp.async.cg.shared.global [%0], [%1], 16;\n" :: "r"(smem), "l"(gmem));
}
#define CP_COMMIT() asm volatile("cp.async.commit_group;\n" ::: "memory")
#define CP_WAIT(n)  asm volatile("cp.async.wait_group %0;\n" :: "n"(n) : "memory")

__device__ __forceinline__ void ldsm4(uint32_t* r, const void* p)
{
    uint32_t a = (uint32_t)__cvta_generic_to_shared(p);
    asm volatile("ldmatrix.sync.aligned.m8n8.x4.shared.b16 {%0,%1,%2,%3}, [%4];"
        : "=r"(r[0]), "=r"(r[1]), "=r"(r[2]), "=r"(r[3]) : "r"(a));
}

// ---------------------------------------------------------------------------
// fp32 -> fp16 hi/lo split, and fp32 -> fp16 single convert
// ---------------------------------------------------------------------------
__global__ __launch_bounds__(256) void split_fp16(
    const float4* __restrict__ in, __half* __restrict__ hi,
    __half* __restrict__ lo)
{
    const size_t i = (size_t)blockIdx.x * 256 + threadIdx.x;
    float4 x = in[i];
    __half h[4], l[4];
    float xs[4] = {x.x, x.y, x.z, x.w};
#pragma unroll
    for (int j = 0; j < 4; j++) {
        h[j] = __float2half_rn(xs[j]);
        l[j] = __float2half_rn(xs[j] - __half2float(h[j]));
    }
    *(uint2*)&hi[i * 4] = *(uint2*)h;
    *(uint2*)&lo[i * 4] = *(uint2*)l;
}

__global__ __launch_bounds__(256) void conv_fp16(
    const float4* __restrict__ in, __half* __restrict__ out)
{
    const size_t i = (size_t)blockIdx.x * 256 + threadIdx.x;
    float4 x = in[i];
    __half h[4] = {__float2half_rn(x.x), __float2half_rn(x.y),
                   __float2half_rn(x.z), __float2half_rn(x.w)};
    *(uint2*)&out[i * 4] = *(uint2*)h;
}

// ---------------------------------------------------------------------------
// mma.m16n8k16 fp16 wrapper (fp32 accumulate)
// ---------------------------------------------------------------------------
__device__ __forceinline__ void mma16816(float* c, const uint32_t* a, const uint32_t* b)
{
    asm volatile(
        "mma.sync.aligned.m16n8k16.row.col.f32.f16.f16.f32 "
        "{%0,%1,%2,%3}, {%4,%5,%6,%7}, {%8,%9}, {%0,%1,%2,%3};"
        : "+f"(c[0]), "+f"(c[1]), "+f"(c[2]), "+f"(c[3])
        : "r"(a[0]), "r"(a[1]), "r"(a[2]), "r"(a[3]), "r"(b[0]), "r"(b[1]));
}

__device__ __forceinline__ uint32_t pack_hilo(float x, float y, uint32_t& lo)
{
    __half hx = __float2half_rn(x), hy = __float2half_rn(y);
    __half lx = __float2half_rn(x - __half2float(hx));
    __half ly = __float2half_rn(y - __half2float(hy));
    __half2 h2 = __halves2half2(hx, hy);
    __half2 l2 = __halves2half2(lx, ly);
    lo = *(uint32_t*)&l2;
    return *(uint32_t*)&h2;
}

// ---------------------------------------------------------------------------
// fp16-split tensor-core GEMM: C[M,N] = A[M,K] @ B[N,K]^T   (~1.4e-4 accurate)
// A as hi/lo fp16 (2 MMAs), B single fp16. BK=32, 2-stage cp.async,
// one sync/iter, 2 CTAs/SM. Block 128x128, 256 threads (32x64 warp tile).
// ---------------------------------------------------------------------------
constexpr int GPAD = 40;                      // smem row pitch (fp16): 80B, ldsm conflict-free
constexpr int GSTG = 128 * GPAD;              // fp16 per matrix per stage (5120)
constexpr int GEMM_SMEM = 2 * 3 * GSTG * 2;   // 61440 bytes

__global__ __launch_bounds__(256, 2) void gemm_fp16x2(
    const __half* __restrict__ Ah, const __half* __restrict__ Al,
    const __half* __restrict__ Bf,
    float* __restrict__ C, int M, int N, int K)
{
    extern __shared__ __half sb[];

    const int tid = threadIdx.x;
    const int bm = blockIdx.y * 128;
    const int bn = blockIdx.x * 128;
    const int lane = tid & 31;
    const int wid  = tid >> 5;
    const int wm = (wid & 3) * 32;
    const int wn = (wid >> 2) * 64;
    const int grp = lane >> 2;
    const int tig = lane & 3;

    const int lrow  = lane & 15;
    const int lcoff = (lane >> 4) * 8;
    const int brow  = (lane & 7) + ((lane >> 4) << 3);
    const int bcoff = ((lane >> 3) & 1) * 8;

    uint32_t soff[2];
    int grow[2], gcol[2];
#pragma unroll
    for (int j = 0; j < 2; j++) {
        int c = tid + j * 256;
        grow[j] = c >> 2;
        gcol[j] = (c & 3) * 8;
        soff[j] = (uint32_t)(grow[j] * GPAD + gcol[j]);
    }

    float acc[2][8][4];
#pragma unroll
    for (int mt = 0; mt < 2; mt++)
#pragma unroll
        for (int nt = 0; nt < 8; nt++)
#pragma unroll
            for (int e = 0; e < 4; e++) acc[mt][nt][e] = 0.f;

    uint32_t sbase = (uint32_t)__cvta_generic_to_shared(sb);
    const int nk = K / 32;

#pragma unroll
    for (int j = 0; j < 2; j++) {
        cp16(sbase + (0 * GSTG + soff[j]) * 2, Ah + (size_t)(bm + grow[j]) * K + gcol[j]);
        cp16(sbase + (1 * GSTG + soff[j]) * 2, Al + (size_t)(bm + grow[j]) * K + gcol[j]);
        cp16(sbase + (2 * GSTG + soff[j]) * 2, Bf + (size_t)(bn + grow[j]) * K + gcol[j]);
    }
    CP_COMMIT();

    for (int i = 0; i < nk; i++) {
        const __half* cur = sb + (size_t)(i & 1) * 3 * GSTG;

        CP_WAIT(0);
        __syncthreads();

        if (i + 1 < nk) {
            const uint32_t nxt = sbase + (uint32_t)(((i + 1) & 1) * 3 * GSTG) * 2;
            const int k0 = (i + 1) * 32;
#pragma unroll
            for (int j = 0; j < 2; j++) {
                cp16(nxt + (0 * GSTG + soff[j]) * 2, Ah + (size_t)(bm + grow[j]) * K + k0 + gcol[j]);
                cp16(nxt + (1 * GSTG + soff[j]) * 2, Al + (size_t)(bm + grow[j]) * K + k0 + gcol[j]);
                cp16(nxt + (2 * GSTG + soff[j]) * 2, Bf + (size_t)(bn + grow[j]) * K + k0 + gcol[j]);
            }
            CP_COMMIT();
        }

        const __half* sAh = cur;
        const __half* sAl = cur + 1 * GSTG;
        const __half* sB  = cur + 2 * GSTG;

#pragma unroll
        for (int kk = 0; kk < 32; kk += 16) {
            uint32_t afh[2][4], afl[2][4];
            const int acol = kk + lcoff;
            ldsm4(afh[0], &sAh[(wm + lrow     ) * GPAD + acol]);
            ldsm4(afh[1], &sAh[(wm + 16 + lrow) * GPAD + acol]);
            ldsm4(afl[0], &sAl[(wm + lrow     ) * GPAD + acol]);
            ldsm4(afl[1], &sAl[(wm + 16 + lrow) * GPAD + acol]);
#pragma unroll
            for (int np = 0; np < 4; np++) {
                const int br = wn + np * 16 + brow;
                const int bc = kk + bcoff;
                uint32_t bh[4];
                ldsm4(bh, &sB[br * GPAD + bc]);
                mma16816(acc[0][2 * np    ], afh[0], bh);
                mma16816(acc[1][2 * np    ], afh[1], bh);
                mma16816(acc[0][2 * np + 1], afh[0], bh + 2);
                mma16816(acc[1][2 * np + 1], afh[1], bh + 2);
                mma16816(acc[0][2 * np    ], afl[0], bh);
                mma16816(acc[1][2 * np    ], afl[1], bh);
                mma16816(acc[0][2 * np + 1], afl[0], bh + 2);
                mma16816(acc[1][2 * np + 1], afl[1], bh + 2);
            }
        }
    }

#pragma unroll
    for (int mt = 0; mt < 2; mt++) {
        const int row = bm + wm + mt * 16 + grp;
#pragma unroll
        for (int nt = 0; nt < 8; nt++) {
            const int col = bn + wn + nt * 8 + tig * 2;
            *(float2*)&C[(size_t)row * N + col]       = make_float2(acc[mt][nt][0], acc[mt][nt][1]);
            *(float2*)&C[(size_t)(row + 8) * N + col] = make_float2(acc[mt][nt][2], acc[mt][nt][3]);
        }
    }
}

// ---------------------------------------------------------------------------
// RMSNorm + RoPE for Q: reads qkv fp32, writes fp16 hi/lo to (b,H,s,D),
// pre-scaled by 1/sqrt(D). One warp per row.
// ---------------------------------------------------------------------------
__global__ __launch_bounds__(256) void norm_rope_q(
    const float* __restrict__ qkv,
    __half* __restrict__ oh, __half* __restrict__ ol,
    const float* __restrict__ cs, const float* __restrict__ sn,
    const float* __restrict__ gamma)
{
    const int warp = (blockIdx.x * 256 + threadIdx.x) >> 5;
    const int lane = threadIdx.x & 31;
    const int h  = warp % NH;
    const int bs = warp / NH;
    const int sp = bs % SEQ;
    const int bi = bs / SEQ;

    const float* x = qkv + (size_t)bs * NQKV + h * HD;
    float e0 = x[lane], e1 = x[lane + 32], e2 = x[lane + 64], e3 = x[lane + 96];

    float ssq = e0 * e0 + e1 * e1 + e2 * e2 + e3 * e3;
#pragma unroll
    for (int o = 16; o; o >>= 1) ssq += __shfl_xor_sync(0xffffffffu, ssq, o);
    const float r = rsqrtf(ssq * (1.0f / HD) + 1e-6f);

    e0 *= r * gamma[lane];      e1 *= r * gamma[lane + 32];
    e2 *= r * gamma[lane + 64]; e3 *= r * gamma[lane + 96];

    const float* cp = cs + (size_t)bs * HD;
    const float* sg = sn + (size_t)bs * HD;
    float o4[4];
    o4[0] = (e0 * cp[lane]      - e2 * sg[lane])      * SM_SCALE;
    o4[1] = (e1 * cp[lane + 32] - e3 * sg[lane + 32]) * SM_SCALE;
    o4[2] = (e2 * cp[lane + 64] + e0 * sg[lane + 64]) * SM_SCALE;
    o4[3] = (e3 * cp[lane + 96] + e1 * sg[lane + 96]) * SM_SCALE;

    const size_t ob = (((size_t)bi * NH + h) * SEQ + sp) * HD;
#pragma unroll
    for (int j = 0; j < 4; j++) {
        __half hv = __float2half_rn(o4[j]);
        oh[ob + lane + 32 * j] = hv;
        ol[ob + lane + 32 * j] = __float2half_rn(o4[j] - __half2float(hv));
    }
}

// ---------------------------------------------------------------------------
// RMSNorm + RoPE for K: writes fp32 (b,KV,s,D) into d_out AND single fp16.
// ---------------------------------------------------------------------------
__global__ __launch_bounds__(256) void norm_rope_k(
    const float* __restrict__ qkv, float* __restrict__ kout,
    __half* __restrict__ of,
    const float* __restrict__ cs, const float* __restrict__ sn,
    const float* __restrict__ gamma)
{
    const int warp = (blockIdx.x * 256 + threadIdx.x) >> 5;
    const int lane = threadIdx.x & 31;
    const int h  = warp % NKV;
    const int bs = warp / NKV;
    const int sp = bs % SEQ;
    const int bi = bs / SEQ;

    const float* x = qkv + (size_t)bs * NQKV + KOFF + h * HD;
    float e0 = x[lane], e1 = x[lane + 32], e2 = x[lane + 64], e3 = x[lane + 96];

    float ssq = e0 * e0 + e1 * e1 + e2 * e2 + e3 * e3;
#pragma unroll
    for (int o = 16; o; o >>= 1) ssq += __shfl_xor_sync(0xffffffffu, ssq, o);
    const float r = rsqrtf(ssq * (1.0f / HD) + 1e-6f);

    e0 *= r * gamma[lane];      e1 *= r * gamma[lane + 32];
    e2 *= r * gamma[lane + 64]; e3 *= r * gamma[lane + 96];

    const float* cp = cs + (size_t)bs * HD;
    const float* sg = sn + (size_t)bs * HD;
    float o4[4];
    o4[0] = e0 * cp[lane]      - e2 * sg[lane];
    o4[1] = e1 * cp[lane + 32] - e3 * sg[lane + 32];
    o4[2] = e2 * cp[lane + 64] + e0 * sg[lane + 64];
    o4[3] = e3 * cp[lane + 96] + e1 * sg[lane + 96];

    const size_t ob = (((size_t)bi * NKV + h) * SEQ + sp) * HD;
#pragma unroll
    for (int j = 0; j < 4; j++) {
        kout[ob + lane + 32 * j] = o4[j];
        of[ob + lane + 32 * j] = __float2half_rn(o4[j]);
    }
}

// ---------------------------------------------------------------------------
// V transpose (fp32): qkv V region -> (b,KV,s,D) in d_out
// ---------------------------------------------------------------------------
__global__ __launch_bounds__(256) void v_transpose(
    const float4* __restrict__ qkv4, float4* __restrict__ out)
{
    const size_t i = (size_t)blockIdx.x * 256 + threadIdx.x;
    const int d4 = (int)(i & 31);
    const int kh = (int)((i >> 5) & (NKV - 1));
    const int sp = (int)((i >> 8) & (SEQ - 1));
    const int bi = (int)(i >> 19);
    const size_t src = ((size_t)(bi * SEQ + sp) * NQKV + VOFF + kh * HD) / 4 + d4;
    const size_t dst = (((size_t)bi * NKV + kh) * SEQ + sp) * 32 + d4;
    out[dst] = qkv4[src];
}

// ---------------------------------------------------------------------------
// V transpose + convert (fp16): qkv V region -> (b,KV,D,s) single fp16
// ---------------------------------------------------------------------------
__global__ void vtrans_f16(
    const float* __restrict__ qkv, __half* __restrict__ vf)
{
    __shared__ float t[32][33];
    const int s0 = blockIdx.x * 32, d0 = blockIdx.y * 32;
    const int bz = blockIdx.z;                 // bi*NKV + kh
    const int bi = bz / NKV, kh = bz % NKV;
    const int tx = threadIdx.x, ty = threadIdx.y;

#pragma unroll
    for (int j = 0; j < 4; j++) {
        int s = s0 + ty + j * 8;
        t[ty + j * 8][tx] =
            qkv[(size_t)(bi * SEQ + s) * NQKV + VOFF + kh * HD + d0 + tx];
    }
    __syncthreads();
#pragma unroll
    for (int j = 0; j < 4; j++) {
        int d = d0 + ty + j * 8;
        size_t idx = ((size_t)bz * HD + d) * SEQ + s0 + tx;
        vf[idx] = __float2half_rn(t[tx][ty + j * 8]);
    }
}

// ---------------------------------------------------------------------------
// Tensor-core causal flash attention, fp16 2-MMA scheme.
// Q hi/lo fp16; K, V single fp16. BM=128, BN=64, 256 threads.
// K/V tiles double-buffered via cp.async.
// ---------------------------------------------------------------------------
constexpr int FQP = 136;  // pitch (fp16) for Q/K tiles
constexpr int FVP = 72;   // pitch (fp16) for Vt tiles
constexpr int FKV = 64 * FQP + 128 * FVP;            // KV stage elems (17920)
constexpr int FLASH_SMEM = (2 * 128 * FQP + 2 * FKV) * 2;  // 141312 B

__global__ __launch_bounds__(256, 1) void flash_mma(
    const __half* __restrict__ Qh, const __half* __restrict__ Ql,
    const __half* __restrict__ Kf, const __half* __restrict__ Vf,
    __half* __restrict__ Oh, __half* __restrict__ Ol)
{
    extern __shared__ __half sm[];
    __half* sQh = sm;
    __half* sQl = sQh + 128 * FQP;
    __half* sKV = sQl + 128 * FQP;    // 2 stages of [K | V]

    const int qtile = blockIdx.x;
    const int h     = blockIdx.y;
    const int bi    = blockIdx.z;
    const int kh    = h / GQ;
    const int tid   = threadIdx.x;
    const int lane  = tid & 31;
    const int wid   = tid >> 5;
    const int grp   = lane >> 2;
    const int tig   = lane & 3;
    const int q0    = qtile * 128;

    const int lrow  = lane & 15;
    const int lcoff = (lane >> 4) * 8;
    const int brow  = (lane & 7) + ((lane >> 4) << 3);
    const int bcoff = ((lane >> 3) & 1) * 8;

    const __half* kg = Kf + (((size_t)bi * NKV + kh) * SEQ) * HD;
    const __half* vg = Vf + (((size_t)bi * NKV + kh) * HD) * SEQ;
    const uint32_t skv = (uint32_t)__cvta_generic_to_shared(sKV);

    // per-thread cp.async geometry: K 64x16 chunks (4/thread), V 128x8 (4/thread)
    int kr[4], kc[4], vr[4], vc[4];
    uint32_t kso[4], vso[4];
#pragma unroll
    for (int j = 0; j < 4; j++) {
        int c = tid + j * 256;
        kr[j] = c >> 4; kc[j] = (c & 15) * 8;
        kso[j] = (uint32_t)(kr[j] * FQP + kc[j]);
        vr[j] = c >> 3; vc[j] = (c & 7) * 8;
        vso[j] = (uint32_t)(vr[j] * FVP + vc[j]);
    }

    auto issue_kv = [&](int s, int k0) {
        const uint32_t st = skv + (uint32_t)(s * FKV) * 2;
#pragma unroll
        for (int j = 0; j < 4; j++) {
            cp16(st + kso[j] * 2,                  kg + (size_t)(k0 + kr[j]) * HD + kc[j]);
            cp16(st + (64 * FQP + vso[j]) * 2,     vg + (size_t)vr[j] * SEQ + k0 + vc[j]);
        }
        CP_COMMIT();
    };

    // Q tile load (128 x 128, hi+lo)
    {
        const __half* qgh = Qh + (((size_t)bi * NH + h) * SEQ + q0) * HD;
        const __half* qgl = Ql + (((size_t)bi * NH + h) * SEQ + q0) * HD;
        for (int i = tid; i < 128 * 16; i += 256) {
            int r = i >> 4, c = (i & 15) * 8;
            *(uint4*)&sQh[r * FQP + c] = *(const uint4*)&qgh[(size_t)r * HD + c];
            *(uint4*)&sQl[r * FQP + c] = *(const uint4*)&qgl[(size_t)r * HD + c];
        }
    }

    float o[16][4];
#pragma unroll
    for (int nt = 0; nt < 16; nt++)
#pragma unroll
        for (int e = 0; e < 4; e++) o[nt][e] = 0.f;
    float m0 = -1e30f, m1 = -1e30f, l0 = 0.f, l1 = 0.f;

    const int ntiles = 2 * qtile + 2;

    issue_kv(0, 0);   // prologue

    for (int t = 0; t < ntiles; ++t) {
        const int k0 = t * 64;
        const __half* cur = sKV + (size_t)(t & 1) * FKV;
        const __half* sK = cur;
        const __half* sV = cur + 64 * FQP;

        CP_WAIT(0);
        __syncthreads();

        if (t + 1 < ntiles) issue_kv((t + 1) & 1, (t + 1) * 64);

        float s[8][4];
#pragma unroll
        for (int nt = 0; nt < 8; nt++)
#pragma unroll
            for (int e = 0; e < 4; e++) s[nt][e] = 0.f;

#pragma unroll
        for (int kk = 0; kk < 128; kk += 16) {
            uint32_t ah[4], al[4];
            const int acol = kk + lcoff;
            ldsm4(ah, &sQh[(wid * 16 + lrow) * FQP + acol]);
            ldsm4(al, &sQl[(wid * 16 + lrow) * FQP + acol]);
#pragma unroll
            for (int np = 0; np < 4; np++) {
                const int br = np * 16 + brow;
                const int bc = kk + bcoff;
                uint32_t bh[4];
                ldsm4(bh, &sK[br * FQP + bc]);
                mma16816(s[2 * np    ], ah, bh);
                mma16816(s[2 * np + 1], ah, bh + 2);
                mma16816(s[2 * np    ], al, bh);
                mma16816(s[2 * np + 1], al, bh + 2);
            }
        }

        if (t >= ntiles - 2) {   // causal mask (last two tiles span the diagonal)
            const int r0 = q0 + wid * 16 + grp;
#pragma unroll
            for (int nt = 0; nt < 8; nt++) {
                const int c = k0 + nt * 8 + tig * 2;
                if (c     > r0)     s[nt][0] = -1e30f;
                if (c + 1 > r0)     s[nt][1] = -1e30f;
                if (c     > r0 + 8) s[nt][2] = -1e30f;
                if (c + 1 > r0 + 8) s[nt][3] = -1e30f;
            }
        }

        float mx0 = -1e30f, mx1 = -1e30f;
#pragma unroll
        for (int nt = 0; nt < 8; nt++) {
            mx0 = fmaxf(mx0, fmaxf(s[nt][0], s[nt][1]));
            mx1 = fmaxf(mx1, fmaxf(s[nt][2], s[nt][3]));
        }
        mx0 = fmaxf(mx0, __shfl_xor_sync(0xffffffffu, mx0, 1));
        mx0 = fmaxf(mx0, __shfl_xor_sync(0xffffffffu, mx0, 2));
        mx1 = fmaxf(mx1, __shfl_xor_sync(0xffffffffu, mx1, 1));
        mx1 = fmaxf(mx1, __shfl_xor_sync(0xffffffffu, mx1, 2));

        const float nm0 = fmaxf(m0, mx0);
        const float nm1 = fmaxf(m1, mx1);
        const float a0 = __expf(m0 - nm0);
        const float a1 = __expf(m1 - nm1);
        m0 = nm0; m1 = nm1;

        float rs0 = 0.f, rs1 = 0.f;
#pragma unroll
        for (int nt = 0; nt < 8; nt++) {
            s[nt][0] = __expf(s[nt][0] - m0);
            s[nt][1] = __expf(s[nt][1] - m0);
            s[nt][2] = __expf(s[nt][2] - m1);
            s[nt][3] = __expf(s[nt][3] - m1);
            rs0 += s[nt][0] + s[nt][1];
            rs1 += s[nt][2] + s[nt][3];
        }
        rs0 += __shfl_xor_sync(0xffffffffu, rs0, 1);
        rs0 += __shfl_xor_sync(0xffffffffu, rs0, 2);
        rs1 += __shfl_xor_sync(0xffffffffu, rs1, 1);
        rs1 += __shfl_xor_sync(0xffffffffu, rs1, 2);
        l0 = l0 * a0 + rs0;
        l1 = l1 * a1 + rs1;

#pragma unroll
        for (int nt = 0; nt < 16; nt++) {
            o[nt][0] *= a0; o[nt][1] *= a0;
            o[nt][2] *= a1; o[nt][3] *= a1;
        }

#pragma unroll
        for (int ks = 0; ks < 4; ks++) {
            uint32_t ph[4], pl[4];
            ph[0] = pack_hilo(s[2 * ks][0],     s[2 * ks][1],     pl[0]);
            ph[1] = pack_hilo(s[2 * ks][2],     s[2 * ks][3],     pl[1]);
            ph[2] = pack_hilo(s[2 * ks + 1][0], s[2 * ks + 1][1], pl[2]);
            ph[3] = pack_hilo(s[2 * ks + 1][2], s[2 * ks + 1][3], pl[3]);
            const int bc = ks * 16 + bcoff;
#pragma unroll
            for (int np = 0; np < 8; np++) {
                const int br = np * 16 + brow;
                uint32_t vh4[4];
                ldsm4(vh4, &sV[br * FVP + bc]);
                mma16816(o[2 * np    ], ph, vh4);
                mma16816(o[2 * np + 1], ph, vh4 + 2);
                mma16816(o[2 * np    ], pl, vh4);
                mma16816(o[2 * np + 1], pl, vh4 + 2);
            }
        }
    }

    const float i0 = 1.0f / l0;
    const float i1 = 1.0f / l1;
    const size_t row0 = (size_t)bi * SEQ + q0 + wid * 16 + grp;
    const size_t row1 = row0 + 8;
    const int colb = h * HD + tig * 2;
#pragma unroll
    for (int nt = 0; nt < 16; nt++) {
        uint32_t lo;
        uint32_t hi = pack_hilo(o[nt][0] * i0, o[nt][1] * i0, lo);
        *(uint32_t*)&Oh[row0 * (NH * HD) + colb + nt * 8] = hi;
        *(uint32_t*)&Ol[row0 * (NH * HD) + colb + nt * 8] = lo;
        hi = pack_hilo(o[nt][2] * i1, o[nt][3] * i1, lo);
        *(uint32_t*)&Oh[row1 * (NH * HD) + colb + nt * 8] = hi;
        *(uint32_t*)&Ol[row1 * (NH * HD) + colb + nt * 8] = lo;
    }
}

// ---------------------------------------------------------------------------
// kernel_launch
// ---------------------------------------------------------------------------
extern "C" void kernel_launch(void* const* d_in, const int* in_sizes, int n_in,
                              void* d_out, int out_size)
{
    const float* hidden = (const float*)d_in[0];
    const float* cosb   = (const float*)d_in[1];
    const float* sinb   = (const float*)d_in[2];
    const float* wq     = (const float*)d_in[3];
    const float* wk     = (const float*)d_in[4];
    const float* wv     = (const float*)d_in[5];
    const float* wo     = (const float*)d_in[6];
    const float* qg     = (const float*)d_in[7];
    const float* kg     = (const float*)d_in[8];

    float* out  = (float*)d_out;
    float* kout = out  + (size_t)NB * SEQ * HDIM;
    float* vout = kout + (size_t)NB * NKV * SEQ * HD;

    __half *hidh, *hidl, *wqkvf, *wof, *aoh, *aol, *qh, *ql, *kf, *vf;
    float *qkv;
    cudaGetSymbolAddress((void**)&hidh,  g_hid_h);
    cudaGetSymbolAddress((void**)&hidl,  g_hid_l);
    cudaGetSymbolAddress((void**)&wqkvf, g_wqkv);
    cudaGetSymbolAddress((void**)&wof,   g_wo);
    cudaGetSymbolAddress((void**)&aoh,   g_ao_h);
    cudaGetSymbolAddress((void**)&aol,   g_ao_l);
    cudaGetSymbolAddress((void**)&qkv,   g_qkv);
    cudaGetSymbolAddress((void**)&qh,    g_qh);
    cudaGetSymbolAddress((void**)&ql,    g_ql);
    cudaGetSymbolAddress((void**)&kf,    g_kf);
    cudaGetSymbolAddress((void**)&vf,    g_vf);

    cudaFuncSetAttribute(flash_mma, cudaFuncAttributeMaxDynamicSharedMemorySize, FLASH_SMEM);
    cudaFuncSetAttribute(gemm_fp16x2, cudaFuncAttributeMaxDynamicSharedMemorySize, GEMM_SMEM);

    // fp32 -> fp16 conversions
    const size_t nHid = (size_t)MROWS * HDIM;
    const size_t nWq  = (size_t)NH  * HD * HDIM;
    const size_t nWk  = (size_t)NKV * HD * HDIM;
    split_fp16<<<(int)(nHid / 1024), 256>>>((const float4*)hidden, hidh, hidl);
    conv_fp16<<<(int)(nWq / 1024), 256>>>((const float4*)wq, wqkvf);
    conv_fp16<<<(int)(nWk / 1024), 256>>>((const float4*)wk, wqkvf + nWq);
    conv_fp16<<<(int)(nWk / 1024), 256>>>((const float4*)wv, wqkvf + nWq + nWk);
    conv_fp16<<<(int)(nWq / 1024), 256>>>((const float4*)wo, wof);

    // Fused QKV projection
    gemm_fp16x2<<<dim3(NQKV / 128, MROWS / 128), 256, GEMM_SMEM>>>(
        hidh, hidl, wqkvf, qkv, MROWS, NQKV, HDIM);

    // RMSNorm + RoPE -> fp16 operands (+ fp32 K into d_out)
    norm_rope_q<<<(MROWS * NH ) / 8, 256>>>(qkv, qh, ql, cosb, sinb, qg);
    norm_rope_k<<<(MROWS * NKV) / 8, 256>>>(qkv, kout, kf, cosb, sinb, kg);

    // V: fp32 into d_out's new_v; single fp16 transposed (b,KV,D,s)
    v_transpose<<<(NB * SEQ * NKV * HD / 4) / 256, 256>>>((const float4*)qkv, (float4*)vout);
    vtrans_f16<<<dim3(SEQ / 32, HD / 32, NB * NKV), dim3(32, 8)>>>(qkv, vf);

    // Tensor-core causal GQA flash attention -> fp16 hi/lo O
    flash_mma<<<dim3(SEQ / 128, NH, NB), 256, FLASH_SMEM>>>(
        qh, ql, kf, vf, aoh, aol);

    // Output projection
    gemm_fp16x2<<<dim3(HDIM / 128, MROWS / 128), 256, GEMM_SMEM>>>(
        aoh, aol, wof, out, MROWS, HDIM, NH * HD);
}

// round 13
// speedup vs baseline: 1.8874x; 1.0507x over previous
#include <cuda_runtime.h>
#include <cuda_fp16.h>
#include <cstdint>

// Problem constants
constexpr int NB   = 2;      // batch
constexpr int SEQ  = 2048;   // sequence
constexpr int HDIM = 2560;   // hidden
constexpr int NH   = 32;     // q heads
constexpr int NKV  = 8;      // kv heads
constexpr int HD   = 128;    // head dim
constexpr int GQ   = NH / NKV;
constexpr int MROWS = NB * SEQ;            // 4096
constexpr int NQKV  = (NH + 2 * NKV) * HD; // 6144
constexpr int KOFF  = NH * HD;             // 4096
constexpr int VOFF  = (NH + NKV) * HD;     // 5120
constexpr float SM_SCALE = 0.08838834764831845f;  // 1/sqrt(128)

// ---------------- device scratch (no allocation allowed) ----------------
__device__ __half g_hid_h [(size_t)MROWS * HDIM];
__device__ __half g_hid_l [(size_t)MROWS * HDIM];
__device__ __half g_wqkv  [(size_t)NQKV * HDIM];        // single fp16
__device__ __half g_wo    [(size_t)HDIM * NH * HD];     // single fp16
__device__ __half g_ao_h  [(size_t)MROWS * NH * HD];
__device__ __half g_ao_l  [(size_t)MROWS * NH * HD];
__device__ float g_qkv[(size_t)MROWS * NQKV];           // 96MB
// fp16 attention operands
__device__ __half g_qh[(size_t)NB * NH  * SEQ * HD];    // (b,H,s,D), pre-scaled, hi
__device__ __half g_ql[(size_t)NB * NH  * SEQ * HD];    // lo
__device__ __half g_kf[(size_t)NB * NKV * SEQ * HD];    // (b,KV,s,D) single
__device__ __half g_vf[(size_t)NB * NKV * HD * SEQ];    // (b,KV,D,s) transposed single

// ---------------------------------------------------------------------------
// cp.async / ldmatrix helpers
// ---------------------------------------------------------------------------
__device__ __forceinline__ void cp16(uint32_t smem, const void* gmem)
{
    asm volatile("cp.async.cg.shared.global [%0], [%1], 16;\n" :: "r"(smem), "l"(gmem));
}
#define CP_COMMIT() asm volatile("cp.async.commit_group;\n" ::: "memory")
#define CP_WAIT(n)  asm volatile("cp.async.wait_group %0;\n" :: "n"(n) : "memory")

__device__ __forceinline__ void ldsm4(uint32_t* r, const void* p)
{
    uint32_t a = (uint32_t)__cvta_generic_to_shared(p);
    asm volatile("ldmatrix.sync.aligned.m8n8.x4.shared.b16 {%0,%1,%2,%3}, [%4];"
        : "=r"(r[0]), "=r"(r[1]), "=r"(r[2]), "=r"(r[3]) : "r"(a));
}

// ---------------------------------------------------------------------------
// fp32 -> fp16 hi/lo split, and fp32 -> fp16 single convert
// ---------------------------------------------------------------------------
__global__ __launch_bounds__(256) void split_fp16(
    const float4* __restrict__ in, __half* __restrict__ hi,
    __half* __restrict__ lo)
{
    const size_t i = (size_t)blockIdx.x * 256 + threadIdx.x;
    float4 x = in[i];
    __half h[4], l[4];
    float xs[4] = {x.x, x.y, x.z, x.w};
#pragma unroll
    for (int j = 0; j < 4; j++) {
        h[j] = __float2half_rn(xs[j]);
        l[j] = __float2half_rn(xs[j] - __half2float(h[j]));
    }
    *(uint2*)&hi[i * 4] = *(uint2*)h;
    *(uint2*)&lo[i * 4] = *(uint2*)l;
}

__global__ __launch_bounds__(256) void conv_fp16(
    const float4* __restrict__ in, __half* __restrict__ out)
{
    const size_t i = (size_t)blockIdx.x * 256 + threadIdx.x;
    float4 x = in[i];
    __half h[4] = {__float2half_rn(x.x), __float2half_rn(x.y),
                   __float2half_rn(x.z), __float2half_rn(x.w)};
    *(uint2*)&out[i * 4] = *(uint2*)h;
}

// ---------------------------------------------------------------------------
// mma.m16n8k16 fp16 wrapper (fp32 accumulate)
// ---------------------------------------------------------------------------
__device__ __forceinline__ void mma16816(float* c, const uint32_t* a, const uint32_t* b)
{
    asm volatile(
        "mma.sync.aligned.m16n8k16.row.col.f32.f16.f16.f32 "
        "{%0,%1,%2,%3}, {%4,%5,%6,%7}, {%8,%9}, {%0,%1,%2,%3};"
        : "+f"(c[0]), "+f"(c[1]), "+f"(c[2]), "+f"(c[3])
        : "r"(a[0]), "r"(a[1]), "r"(a[2]), "r"(a[3]), "r"(b[0]), "r"(b[1]));
}

__device__ __forceinline__ uint32_t pack_hilo(float x, float y, uint32_t& lo)
{
    __half hx = __float2half_rn(x), hy = __float2half_rn(y);
    __half lx = __float2half_rn(x - __half2float(hx));
    __half ly = __float2half_rn(y - __half2float(hy));
    __half2 h2 = __halves2half2(hx, hy);
    __half2 l2 = __halves2half2(lx, ly);
    lo = *(uint32_t*)&l2;
    return *(uint32_t*)&h2;
}

__device__ __forceinline__ uint32_t pack2f16(float x, float y)
{
    __half2 h2 = __halves2half2(__float2half_rn(x), __float2half_rn(y));
    return *(uint32_t*)&h2;
}

// ---------------------------------------------------------------------------
// fp16-split tensor-core GEMM: C[M,N] = A[M,K] @ B[N,K]^T   (~1.4e-4 accurate)
// A as hi/lo fp16 (2 MMAs), B single fp16. BK=32, 2-stage cp.async,
// one sync/iter, 2 CTAs/SM. Block 128x128, 256 threads (32x64 warp tile).
// ---------------------------------------------------------------------------
constexpr int GPAD = 40;                      // smem row pitch (fp16): 80B, ldsm conflict-free
constexpr int GSTG = 128 * GPAD;              // fp16 per matrix per stage (5120)
constexpr int GEMM_SMEM = 2 * 3 * GSTG * 2;   // 61440 bytes

__global__ __launch_bounds__(256, 2) void gemm_fp16x2(
    const __half* __restrict__ Ah, const __half* __restrict__ Al,
    const __half* __restrict__ Bf,
    float* __restrict__ C, int M, int N, int K)
{
    extern __shared__ __half sb[];

    const int tid = threadIdx.x;
    const int bm = blockIdx.y * 128;
    const int bn = blockIdx.x * 128;
    const int lane = tid & 31;
    const int wid  = tid >> 5;
    const int wm = (wid & 3) * 32;
    const int wn = (wid >> 2) * 64;
    const int grp = lane >> 2;
    const int tig = lane & 3;

    const int lrow  = lane & 15;
    const int lcoff = (lane >> 4) * 8;
    const int brow  = (lane & 7) + ((lane >> 4) << 3);
    const int bcoff = ((lane >> 3) & 1) * 8;

    uint32_t soff[2];
    int grow[2], gcol[2];
#pragma unroll
    for (int j = 0; j < 2; j++) {
        int c = tid + j * 256;
        grow[j] = c >> 2;
        gcol[j] = (c & 3) * 8;
        soff[j] = (uint32_t)(grow[j] * GPAD + gcol[j]);
    }

    float acc[2][8][4];
#pragma unroll
    for (int mt = 0; mt < 2; mt++)
#pragma unroll
        for (int nt = 0; nt < 8; nt++)
#pragma unroll
            for (int e = 0; e < 4; e++) acc[mt][nt][e] = 0.f;

    uint32_t sbase = (uint32_t)__cvta_generic_to_shared(sb);
    const int nk = K / 32;

#pragma unroll
    for (int j = 0; j < 2; j++) {
        cp16(sbase + (0 * GSTG + soff[j]) * 2, Ah + (size_t)(bm + grow[j]) * K + gcol[j]);
        cp16(sbase + (1 * GSTG + soff[j]) * 2, Al + (size_t)(bm + grow[j]) * K + gcol[j]);
        cp16(sbase + (2 * GSTG + soff[j]) * 2, Bf + (size_t)(bn + grow[j]) * K + gcol[j]);
    }
    CP_COMMIT();

    for (int i = 0; i < nk; i++) {
        const __half* cur = sb + (size_t)(i & 1) * 3 * GSTG;

        CP_WAIT(0);
        __syncthreads();

        if (i + 1 < nk) {
            const uint32_t nxt = sbase + (uint32_t)(((i + 1) & 1) * 3 * GSTG) * 2;
            const int k0 = (i + 1) * 32;
#pragma unroll
            for (int j = 0; j < 2; j++) {
                cp16(nxt + (0 * GSTG + soff[j]) * 2, Ah + (size_t)(bm + grow[j]) * K + k0 + gcol[j]);
                cp16(nxt + (1 * GSTG + soff[j]) * 2, Al + (size_t)(bm + grow[j]) * K + k0 + gcol[j]);
                cp16(nxt + (2 * GSTG + soff[j]) * 2, Bf + (size_t)(bn + grow[j]) * K + k0 + gcol[j]);
            }
            CP_COMMIT();
        }

        const __half* sAh = cur;
        const __half* sAl = cur + 1 * GSTG;
        const __half* sB  = cur + 2 * GSTG;

#pragma unroll
        for (int kk = 0; kk < 32; kk += 16) {
            uint32_t afh[2][4], afl[2][4];
            const int acol = kk + lcoff;
            ldsm4(afh[0], &sAh[(wm + lrow     ) * GPAD + acol]);
            ldsm4(afh[1], &sAh[(wm + 16 + lrow) * GPAD + acol]);
            ldsm4(afl[0], &sAl[(wm + lrow     ) * GPAD + acol]);
            ldsm4(afl[1], &sAl[(wm + 16 + lrow) * GPAD + acol]);
#pragma unroll
            for (int np = 0; np < 4; np++) {
                const int br = wn + np * 16 + brow;
                const int bc = kk + bcoff;
                uint32_t bh[4];
                ldsm4(bh, &sB[br * GPAD + bc]);
                mma16816(acc[0][2 * np    ], afh[0], bh);
                mma16816(acc[1][2 * np    ], afh[1], bh);
                mma16816(acc[0][2 * np + 1], afh[0], bh + 2);
                mma16816(acc[1][2 * np + 1], afh[1], bh + 2);
                mma16816(acc[0][2 * np    ], afl[0], bh);
                mma16816(acc[1][2 * np    ], afl[1], bh);
                mma16816(acc[0][2 * np + 1], afl[0], bh + 2);
                mma16816(acc[1][2 * np + 1], afl[1], bh + 2);
            }
        }
    }

#pragma unroll
    for (int mt = 0; mt < 2; mt++) {
        const int row = bm + wm + mt * 16 + grp;
#pragma unroll
        for (int nt = 0; nt < 8; nt++) {
            const int col = bn + wn + nt * 8 + tig * 2;
            *(float2*)&C[(size_t)row * N + col]       = make_float2(acc[mt][nt][0], acc[mt][nt][1]);
            *(float2*)&C[(size_t)(row + 8) * N + col] = make_float2(acc[mt][nt][2], acc[mt][nt][3]);
        }
    }
}

// ---------------------------------------------------------------------------
// RMSNorm + RoPE for Q: reads qkv fp32, writes fp16 hi/lo to (b,H,s,D),
// pre-scaled by 1/sqrt(D). One warp per row.
// ---------------------------------------------------------------------------
__global__ __launch_bounds__(256) void norm_rope_q(
    const float* __restrict__ qkv,
    __half* __restrict__ oh, __half* __restrict__ ol,
    const float* __restrict__ cs, const float* __restrict__ sn,
    const float* __restrict__ gamma)
{
    const int warp = (blockIdx.x * 256 + threadIdx.x) >> 5;
    const int lane = threadIdx.x & 31;
    const int h  = warp % NH;
    const int bs = warp / NH;
    const int sp = bs % SEQ;
    const int bi = bs / SEQ;

    const float* x = qkv + (size_t)bs * NQKV + h * HD;
    float e0 = x[lane], e1 = x[lane + 32], e2 = x[lane + 64], e3 = x[lane + 96];

    float ssq = e0 * e0 + e1 * e1 + e2 * e2 + e3 * e3;
#pragma unroll
    for (int o = 16; o; o >>= 1) ssq += __shfl_xor_sync(0xffffffffu, ssq, o);
    const float r = rsqrtf(ssq * (1.0f / HD) + 1e-6f);

    e0 *= r * gamma[lane];      e1 *= r * gamma[lane + 32];
    e2 *= r * gamma[lane + 64]; e3 *= r * gamma[lane + 96];

    const float* cp = cs + (size_t)bs * HD;
    const float* sg = sn + (size_t)bs * HD;
    float o4[4];
    o4[0] = (e0 * cp[lane]      - e2 * sg[lane])      * SM_SCALE;
    o4[1] = (e1 * cp[lane + 32] - e3 * sg[lane + 32]) * SM_SCALE;
    o4[2] = (e2 * cp[lane + 64] + e0 * sg[lane + 64]) * SM_SCALE;
    o4[3] = (e3 * cp[lane + 96] + e1 * sg[lane + 96]) * SM_SCALE;

    const size_t ob = (((size_t)bi * NH + h) * SEQ + sp) * HD;
#pragma unroll
    for (int j = 0; j < 4; j++) {
        __half hv = __float2half_rn(o4[j]);
        oh[ob + lane + 32 * j] = hv;
        ol[ob + lane + 32 * j] = __float2half_rn(o4[j] - __half2float(hv));
    }
}

// ---------------------------------------------------------------------------
// RMSNorm + RoPE for K: writes fp32 (b,KV,s,D) into d_out AND single fp16.
// ---------------------------------------------------------------------------
__global__ __launch_bounds__(256) void norm_rope_k(
    const float* __restrict__ qkv, float* __restrict__ kout,
    __half* __restrict__ of,
    const float* __restrict__ cs, const float* __restrict__ sn,
    const float* __restrict__ gamma)
{
    const int warp = (blockIdx.x * 256 + threadIdx.x) >> 5;
    const int lane = threadIdx.x & 31;
    const int h  = warp % NKV;
    const int bs = warp / NKV;
    const int sp = bs % SEQ;
    const int bi = bs / SEQ;

    const float* x = qkv + (size_t)bs * NQKV + KOFF + h * HD;
    float e0 = x[lane], e1 = x[lane + 32], e2 = x[lane + 64], e3 = x[lane + 96];

    float ssq = e0 * e0 + e1 * e1 + e2 * e2 + e3 * e3;
#pragma unroll
    for (int o = 16; o; o >>= 1) ssq += __shfl_xor_sync(0xffffffffu, ssq, o);
    const float r = rsqrtf(ssq * (1.0f / HD) + 1e-6f);

    e0 *= r * gamma[lane];      e1 *= r * gamma[lane + 32];
    e2 *= r * gamma[lane + 64]; e3 *= r * gamma[lane + 96];

    const float* cp = cs + (size_t)bs * HD;
    const float* sg = sn + (size_t)bs * HD;
    float o4[4];
    o4[0] = e0 * cp[lane]      - e2 * sg[lane];
    o4[1] = e1 * cp[lane + 32] - e3 * sg[lane + 32];
    o4[2] = e2 * cp[lane + 64] + e0 * sg[lane + 64];
    o4[3] = e3 * cp[lane + 96] + e1 * sg[lane + 96];

    const size_t ob = (((size_t)bi * NKV + h) * SEQ + sp) * HD;
#pragma unroll
    for (int j = 0; j < 4; j++) {
        kout[ob + lane + 32 * j] = o4[j];
        of[ob + lane + 32 * j] = __float2half_rn(o4[j]);
    }
}

// ---------------------------------------------------------------------------
// V: one pass. Reads qkv V region, writes fp32 (b,KV,s,D) to d_out AND
// fp16 transposed (b,KV,D,s).
// ---------------------------------------------------------------------------
__global__ void vtrans_fused(
    const float* __restrict__ qkv, float* __restrict__ vout,
    __half* __restrict__ vf)
{
    __shared__ float t[32][33];
    const int s0 = blockIdx.x * 32, d0 = blockIdx.y * 32;
    const int bz = blockIdx.z;                 // bi*NKV + kh
    const int bi = bz / NKV, kh = bz % NKV;
    const int tx = threadIdx.x, ty = threadIdx.y;

#pragma unroll
    for (int j = 0; j < 4; j++) {
        int s = s0 + ty + j * 8;
        float v = qkv[(size_t)(bi * SEQ + s) * NQKV + VOFF + kh * HD + d0 + tx];
        t[ty + j * 8][tx] = v;
        vout[((size_t)bz * SEQ + s) * HD + d0 + tx] = v;   // fp32 (b,KV,s,D)
    }
    __syncthreads();
#pragma unroll
    for (int j = 0; j < 4; j++) {
        int d = d0 + ty + j * 8;
        size_t idx = ((size_t)bz * HD + d) * SEQ + s0 + tx;
        vf[idx] = __float2half_rn(t[tx][ty + j * 8]);
    }
}

// ---------------------------------------------------------------------------
// Tensor-core causal flash attention, fp16 scheme:
// S = (Qh + Ql) @ K  (2 MMAs);  O += P @ V  (1 MMA, P single fp16).
// BM=128, BN=64, 256 threads; K/V double-buffered via cp.async.
// ---------------------------------------------------------------------------
constexpr int FQP = 136;  // pitch (fp16) for Q/K tiles
constexpr int FVP = 72;   // pitch (fp16) for Vt tiles
constexpr int FKV = 64 * FQP + 128 * FVP;            // KV stage elems (17920)
constexpr int FLASH_SMEM = (2 * 128 * FQP + 2 * FKV) * 2;  // 141312 B

__global__ __launch_bounds__(256, 1) void flash_mma(
    const __half* __restrict__ Qh, const __half* __restrict__ Ql,
    const __half* __restrict__ Kf, const __half* __restrict__ Vf,
    __half* __restrict__ Oh, __half* __restrict__ Ol)
{
    extern __shared__ __half sm[];
    __half* sQh = sm;
    __half* sQl = sQh + 128 * FQP;
    __half* sKV = sQl + 128 * FQP;    // 2 stages of [K | V]

    const int qtile = blockIdx.x;
    const int h     = blockIdx.y;
    const int bi    = blockIdx.z;
    const int kh    = h / GQ;
    const int tid   = threadIdx.x;
    const int lane  = tid & 31;
    const int wid   = tid >> 5;
    const int grp   = lane >> 2;
    const int tig   = lane & 3;
    const int q0    = qtile * 128;

    const int lrow  = lane & 15;
    const int lcoff = (lane >> 4) * 8;
    const int brow  = (lane & 7) + ((lane >> 4) << 3);
    const int bcoff = ((lane >> 3) & 1) * 8;

    const __half* kg = Kf + (((size_t)bi * NKV + kh) * SEQ) * HD;
    const __half* vg = Vf + (((size_t)bi * NKV + kh) * HD) * SEQ;
    const uint32_t skv = (uint32_t)__cvta_generic_to_shared(sKV);

    int kr[4], kc[4], vr[4], vc[4];
    uint32_t kso[4], vso[4];
#pragma unroll
    for (int j = 0; j < 4; j++) {
        int c = tid + j * 256;
        kr[j] = c >> 4; kc[j] = (c & 15) * 8;
        kso[j] = (uint32_t)(kr[j] * FQP + kc[j]);
        vr[j] = c >> 3; vc[j] = (c & 7) * 8;
        vso[j] = (uint32_t)(vr[j] * FVP + vc[j]);
    }

    auto issue_kv = [&](int s, int k0) {
        const uint32_t st = skv + (uint32_t)(s * FKV) * 2;
#pragma unroll
        for (int j = 0; j < 4; j++) {
            cp16(st + kso[j] * 2,                  kg + (size_t)(k0 + kr[j]) * HD + kc[j]);
            cp16(st + (64 * FQP + vso[j]) * 2,     vg + (size_t)vr[j] * SEQ + k0 + vc[j]);
        }
        CP_COMMIT();
    };

    // Q tile load (128 x 128, hi+lo)
    {
        const __half* qgh = Qh + (((size_t)bi * NH + h) * SEQ + q0) * HD;
        const __half* qgl = Ql + (((size_t)bi * NH + h) * SEQ + q0) * HD;
        for (int i = tid; i < 128 * 16; i += 256) {
            int r = i >> 4, c = (i & 15) * 8;
            *(uint4*)&sQh[r * FQP + c] = *(const uint4*)&qgh[(size_t)r * HD + c];
            *(uint4*)&sQl[r * FQP + c] = *(const uint4*)&qgl[(size_t)r * HD + c];
        }
    }

    float o[16][4];
#pragma unroll
    for (int nt = 0; nt < 16; nt++)
#pragma unroll
        for (int e = 0; e < 4; e++) o[nt][e] = 0.f;
    float m0 = -1e30f, m1 = -1e30f, l0 = 0.f, l1 = 0.f;

    const int ntiles = 2 * qtile + 2;

    issue_kv(0, 0);   // prologue

    for (int t = 0; t < ntiles; ++t) {
        const int k0 = t * 64;
        const __half* cur = sKV + (size_t)(t & 1) * FKV;
        const __half* sK = cur;
        const __half* sV = cur + 64 * FQP;

        CP_WAIT(0);
        __syncthreads();

        if (t + 1 < ntiles) issue_kv((t + 1) & 1, (t + 1) * 64);

        float s[8][4];
#pragma unroll
        for (int nt = 0; nt < 8; nt++)
#pragma unroll
            for (int e = 0; e < 4; e++) s[nt][e] = 0.f;

#pragma unroll
        for (int kk = 0; kk < 128; kk += 16) {
            uint32_t ah[4], al[4];
            const int acol = kk + lcoff;
            ldsm4(ah, &sQh[(wid * 16 + lrow) * FQP + acol]);
            ldsm4(al, &sQl[(wid * 16 + lrow) * FQP + acol]);
#pragma unroll
            for (int np = 0; np < 4; np++) {
                const int br = np * 16 + brow;
                const int bc = kk + bcoff;
                uint32_t bh[4];
                ldsm4(bh, &sK[br * FQP + bc]);
                mma16816(s[2 * np    ], ah, bh);
                mma16816(s[2 * np + 1], ah, bh + 2);
                mma16816(s[2 * np    ], al, bh);
                mma16816(s[2 * np + 1], al, bh + 2);
            }
        }

        if (t >= ntiles - 2) {   // causal mask (last two tiles span the diagonal)
            const int r0 = q0 + wid * 16 + grp;
#pragma unroll
            for (int nt = 0; nt < 8; nt++) {
                const int c = k0 + nt * 8 + tig * 2;
                if (c     > r0)     s[nt][0] = -1e30f;
                if (c + 1 > r0)     s[nt][1] = -1e30f;
                if (c     > r0 + 8) s[nt][2] = -1e30f;
                if (c + 1 > r0 + 8) s[nt][3] = -1e30f;
            }
        }

        float mx0 = -1e30f, mx1 = -1e30f;
#pragma unroll
        for (int nt = 0; nt < 8; nt++) {
            mx0 = fmaxf(mx0, fmaxf(s[nt][0], s[nt][1]));
            mx1 = fmaxf(mx1, fmaxf(s[nt][2], s[nt][3]));
        }
        mx0 = fmaxf(mx0, __shfl_xor_sync(0xffffffffu, mx0, 1));
        mx0 = fmaxf(mx0, __shfl_xor_sync(0xffffffffu, mx0, 2));
        mx1 = fmaxf(mx1, __shfl_xor_sync(0xffffffffu, mx1, 1));
        mx1 = fmaxf(mx1, __shfl_xor_sync(0xffffffffu, mx1, 2));

        const float nm0 = fmaxf(m0, mx0);
        const float nm1 = fmaxf(m1, mx1);
        const float a0 = __expf(m0 - nm0);
        const float a1 = __expf(m1 - nm1);
        m0 = nm0; m1 = nm1;

        float rs0 = 0.f, rs1 = 0.f;
#pragma unroll
        for (int nt = 0; nt < 8; nt++) {
            s[nt][0] = __expf(s[nt][0] - m0);
            s[nt][1] = __expf(s[nt][1] - m0);
            s[nt][2] = __expf(s[nt][2] - m1);
            s[nt][3] = __expf(s[nt][3] - m1);
            rs0 += s[nt][0] + s[nt][1];
            rs1 += s[nt][2] + s[nt][3];
        }
        rs0 += __shfl_xor_sync(0xffffffffu, rs0, 1);
        rs0 += __shfl_xor_sync(0xffffffffu, rs0, 2);
        rs1 += __shfl_xor_sync(0xffffffffu, rs1, 1);
        rs1 += __shfl_xor_sync(0xffffffffu, rs1, 2);
        l0 = l0 * a0 + rs0;
        l1 = l1 * a1 + rs1;

#pragma unroll
        for (int nt = 0; nt < 16; nt++) {
            o[nt][0] *= a0; o[nt][1] *= a0;
            o[nt][2] *= a1; o[nt][3] *= a1;
        }

        // O += P @ V  (P single fp16: 1 MMA per V fragment)
#pragma unroll
        for (int ks = 0; ks < 4; ks++) {
            uint32_t ph[4];
            ph[0] = pack2f16(s[2 * ks][0],     s[2 * ks][1]);
            ph[1] = pack2f16(s[2 * ks][2],     s[2 * ks][3]);
            ph[2] = pack2f16(s[2 * ks + 1][0], s[2 * ks + 1][1]);
            ph[3] = pack2f16(s[2 * ks + 1][2], s[2 * ks + 1][3]);
            const int bc = ks * 16 + bcoff;
#pragma unroll
            for (int np = 0; np < 8; np++) {
                const int br = np * 16 + brow;
                uint32_t vh4[4];
                ldsm4(vh4, &sV[br * FVP + bc]);
                mma16816(o[2 * np    ], ph, vh4);
                mma16816(o[2 * np + 1], ph, vh4 + 2);
            }
        }
    }

    const float i0 = 1.0f / l0;
    const float i1 = 1.0f / l1;
    const size_t row0 = (size_t)bi * SEQ + q0 + wid * 16 + grp;
    const size_t row1 = row0 + 8;
    const int colb = h * HD + tig * 2;
#pragma unroll
    for (int nt = 0; nt < 16; nt++) {
        uint32_t lo;
        uint32_t hi = pack_hilo(o[nt][0] * i0, o[nt][1] * i0, lo);
        *(uint32_t*)&Oh[row0 * (NH * HD) + colb + nt * 8] = hi;
        *(uint32_t*)&Ol[row0 * (NH * HD) + colb + nt * 8] = lo;
        hi = pack_hilo(o[nt][2] * i1, o[nt][3] * i1, lo);
        *(uint32_t*)&Oh[row1 * (NH * HD) + colb + nt * 8] = hi;
        *(uint32_t*)&Ol[row1 * (NH * HD) + colb + nt * 8] = lo;
    }
}

// ---------------------------------------------------------------------------
// kernel_launch
// ---------------------------------------------------------------------------
extern "C" void kernel_launch(void* const* d_in, const int* in_sizes, int n_in,
                              void* d_out, int out_size)
{
    const float* hidden = (const float*)d_in[0];
    const float* cosb   = (const float*)d_in[1];
    const float* sinb   = (const float*)d_in[2];
    const float* wq     = (const float*)d_in[3];
    const float* wk     = (const float*)d_in[4];
    const float* wv     = (const float*)d_in[5];
    const float* wo     = (const float*)d_in[6];
    const float* qg     = (const float*)d_in[7];
    const float* kg     = (const float*)d_in[8];

    float* out  = (float*)d_out;
    float* kout = out  + (size_t)NB * SEQ * HDIM;
    float* vout = kout + (size_t)NB * NKV * SEQ * HD;

    __half *hidh, *hidl, *wqkvf, *wof, *aoh, *aol, *qh, *ql, *kf, *vf;
    float *qkv;
    cudaGetSymbolAddress((void**)&hidh,  g_hid_h);
    cudaGetSymbolAddress((void**)&hidl,  g_hid_l);
    cudaGetSymbolAddress((void**)&wqkvf, g_wqkv);
    cudaGetSymbolAddress((void**)&wof,   g_wo);
    cudaGetSymbolAddress((void**)&aoh,   g_ao_h);
    cudaGetSymbolAddress((void**)&aol,   g_ao_l);
    cudaGetSymbolAddress((void**)&qkv,   g_qkv);
    cudaGetSymbolAddress((void**)&qh,    g_qh);
    cudaGetSymbolAddress((void**)&ql,    g_ql);
    cudaGetSymbolAddress((void**)&kf,    g_kf);
    cudaGetSymbolAddress((void**)&vf,    g_vf);

    cudaFuncSetAttribute(flash_mma, cudaFuncAttributeMaxDynamicSharedMemorySize, FLASH_SMEM);
    cudaFuncSetAttribute(gemm_fp16x2, cudaFuncAttributeMaxDynamicSharedMemorySize, GEMM_SMEM);

    // fp32 -> fp16 conversions
    const size_t nHid = (size_t)MROWS * HDIM;
    const size_t nWq  = (size_t)NH  * HD * HDIM;
    const size_t nWk  = (size_t)NKV * HD * HDIM;
    split_fp16<<<(int)(nHid / 1024), 256>>>((const float4*)hidden, hidh, hidl);
    conv_fp16<<<(int)(nWq / 1024), 256>>>((const float4*)wq, wqkvf);
    conv_fp16<<<(int)(nWk / 1024), 256>>>((const float4*)wk, wqkvf + nWq);
    conv_fp16<<<(int)(nWk / 1024), 256>>>((const float4*)wv, wqkvf + nWq + nWk);
    conv_fp16<<<(int)(nWq / 1024), 256>>>((const float4*)wo, wof);

    // Fused QKV projection
    gemm_fp16x2<<<dim3(NQKV / 128, MROWS / 128), 256, GEMM_SMEM>>>(
        hidh, hidl, wqkvf, qkv, MROWS, NQKV, HDIM);

    // RMSNorm + RoPE -> fp16 operands (+ fp32 K into d_out)
    norm_rope_q<<<(MROWS * NH ) / 8, 256>>>(qkv, qh, ql, cosb, sinb, qg);
    norm_rope_k<<<(MROWS * NKV) / 8, 256>>>(qkv, kout, kf, cosb, sinb, kg);

    // V: fp32 into d_out's new_v AND fp16 transposed, single pass
    vtrans_fused<<<dim3(SEQ / 32, HD / 32, NB * NKV), dim3(32, 8)>>>(qkv, vout, vf);

    // Tensor-core causal GQA flash attention -> fp16 hi/lo O
    flash_mma<<<dim3(SEQ / 128, NH, NB), 256, FLASH_SMEM>>>(
        qh, ql, kf, vf, aoh, aol);

    // Output projection
    gemm_fp16x2<<<dim3(HDIM / 128, MROWS / 128), 256, GEMM_SMEM>>>(
        aoh, aol, wof, out, MROWS, HDIM, NH * HD);
}

// round 14
// speedup vs baseline: 2.1526x; 1.1405x over previous
#include <cuda_runtime.h>
#include <cuda_fp16.h>
#include <cstdint>

// Problem constants
constexpr int NB   = 2;      // batch
constexpr int SEQ  = 2048;   // sequence
constexpr int HDIM = 2560;   // hidden
constexpr int NH   = 32;     // q heads
constexpr int NKV  = 8;      // kv heads
constexpr int HD   = 128;    // head dim
constexpr int GQ   = NH / NKV;
constexpr int MROWS = NB * SEQ;            // 4096
constexpr int NQKV  = (NH + 2 * NKV) * HD; // 6144
constexpr int KOFF  = NH * HD;             // 4096
constexpr int VOFF  = (NH + NKV) * HD;     // 5120
constexpr float SM_SCALE = 0.08838834764831845f;  // 1/sqrt(128)

// ---------------- device scratch (no allocation allowed) ----------------
__device__ __half g_hid_h [(size_t)MROWS * HDIM];
__device__ __half g_hid_l [(size_t)MROWS * HDIM];
__device__ __half g_wqkv  [(size_t)NQKV * HDIM];        // single fp16
__device__ __half g_wo    [(size_t)HDIM * NH * HD];     // single fp16
__device__ __half g_ao    [(size_t)MROWS * NH * HD];    // attention out, single fp16
__device__ float g_qkv[(size_t)MROWS * NQKV];           // 96MB
// fp16 attention operands
__device__ __half g_qh[(size_t)NB * NH  * SEQ * HD];    // (b,H,s,D), pre-scaled, hi
__device__ __half g_ql[(size_t)NB * NH  * SEQ * HD];    // lo
__device__ __half g_kf[(size_t)NB * NKV * SEQ * HD];    // (b,KV,s,D) single
__device__ __half g_vf[(size_t)NB * NKV * HD * SEQ];    // (b,KV,D,s) transposed single

// ---------------------------------------------------------------------------
// cp.async / ldmatrix helpers
// ---------------------------------------------------------------------------
__device__ __forceinline__ void cp16(uint32_t smem, const void* gmem)
{
    asm volatile("cp.async.cg.shared.global [%0], [%1], 16;\n" :: "r"(smem), "l"(gmem));
}
#define CP_COMMIT() asm volatile("cp.async.commit_group;\n" ::: "memory")
#define CP_WAIT(n)  asm volatile("cp.async.wait_group %0;\n" :: "n"(n) : "memory")

__device__ __forceinline__ void ldsm4(uint32_t* r, const void* p)
{
    uint32_t a = (uint32_t)__cvta_generic_to_shared(p);
    asm volatile("ldmatrix.sync.aligned.m8n8.x4.shared.b16 {%0,%1,%2,%3}, [%4];"
        : "=r"(r[0]), "=r"(r[1]), "=r"(r[2]), "=r"(r[3]) : "r"(a));
}

// ---------------------------------------------------------------------------
// fp32 -> fp16 hi/lo split, and fp32 -> fp16 single convert
// ---------------------------------------------------------------------------
__global__ __launch_bounds__(256) void split_fp16(
    const float4* __restrict__ in, __half* __restrict__ hi,
    __half* __restrict__ lo)
{
    const size_t i = (size_t)blockIdx.x * 256 + threadIdx.x;
    float4 x = in[i];
    __half h[4], l[4];
    float xs[4] = {x.x, x.y, x.z, x.w};
#pragma unroll
    for (int j = 0; j < 4; j++) {
        h[j] = __float2half_rn(xs[j]);
        l[j] = __float2half_rn(xs[j] - __half2float(h[j]));
    }
    *(uint2*)&hi[i * 4] = *(uint2*)h;
    *(uint2*)&lo[i * 4] = *(uint2*)l;
}

__global__ __launch_bounds__(256) void conv_fp16(
    const float4* __restrict__ in, __half* __restrict__ out)
{
    const size_t i = (size_t)blockIdx.x * 256 + threadIdx.x;
    float4 x = in[i];
    __half h[4] = {__float2half_rn(x.x), __float2half_rn(x.y),
                   __float2half_rn(x.z), __float2half_rn(x.w)};
    *(uint2*)&out[i * 4] = *(uint2*)h;
}

// ---------------------------------------------------------------------------
// mma.m16n8k16 fp16 wrapper (fp32 accumulate)
// ---------------------------------------------------------------------------
__device__ __forceinline__ void mma16816(float* c, const uint32_t* a, const uint32_t* b)
{
    asm volatile(
        "mma.sync.aligned.m16n8k16.row.col.f32.f16.f16.f32 "
        "{%0,%1,%2,%3}, {%4,%5,%6,%7}, {%8,%9}, {%0,%1,%2,%3};"
        : "+f"(c[0]), "+f"(c[1]), "+f"(c[2]), "+f"(c[3])
        : "r"(a[0]), "r"(a[1]), "r"(a[2]), "r"(a[3]), "r"(b[0]), "r"(b[1]));
}

__device__ __forceinline__ uint32_t pack_hilo(float x, float y, uint32_t& lo)
{
    __half hx = __float2half_rn(x), hy = __float2half_rn(y);
    __half lx = __float2half_rn(x - __half2float(hx));
    __half ly = __float2half_rn(y - __half2float(hy));
    __half2 h2 = __halves2half2(hx, hy);
    __half2 l2 = __halves2half2(lx, ly);
    lo = *(uint32_t*)&l2;
    return *(uint32_t*)&h2;
}

__device__ __forceinline__ uint32_t pack2f16(float x, float y)
{
    __half2 h2 = __halves2half2(__float2half_rn(x), __float2half_rn(y));
    return *(uint32_t*)&h2;
}

// ---------------------------------------------------------------------------
// fp16-split tensor-core GEMM: C = A @ B^T, A hi/lo (2 MMAs), B single.
// BK=32, 2-stage cp.async, one sync/iter, 2 CTAs/SM. Block 128x128.
// ---------------------------------------------------------------------------
constexpr int GPAD = 40;                      // smem row pitch (fp16): 80B, ldsm conflict-free
constexpr int GSTG = 128 * GPAD;              // fp16 per matrix per stage (5120)
constexpr int GEMM_SMEM = 2 * 3 * GSTG * 2;   // 61440 bytes

__global__ __launch_bounds__(256, 2) void gemm_fp16x2(
    const __half* __restrict__ Ah, const __half* __restrict__ Al,
    const __half* __restrict__ Bf,
    float* __restrict__ C, int M, int N, int K)
{
    extern __shared__ __half sb[];

    const int tid = threadIdx.x;
    const int bm = blockIdx.y * 128;
    const int bn = blockIdx.x * 128;
    const int lane = tid & 31;
    const int wid  = tid >> 5;
    const int wm = (wid & 3) * 32;
    const int wn = (wid >> 2) * 64;
    const int grp = lane >> 2;
    const int tig = lane & 3;

    const int lrow  = lane & 15;
    const int lcoff = (lane >> 4) * 8;
    const int brow  = (lane & 7) + ((lane >> 4) << 3);
    const int bcoff = ((lane >> 3) & 1) * 8;

    uint32_t soff[2];
    int grow[2], gcol[2];
#pragma unroll
    for (int j = 0; j < 2; j++) {
        int c = tid + j * 256;
        grow[j] = c >> 2;
        gcol[j] = (c & 3) * 8;
        soff[j] = (uint32_t)(grow[j] * GPAD + gcol[j]);
    }

    float acc[2][8][4];
#pragma unroll
    for (int mt = 0; mt < 2; mt++)
#pragma unroll
        for (int nt = 0; nt < 8; nt++)
#pragma unroll
            for (int e = 0; e < 4; e++) acc[mt][nt][e] = 0.f;

    uint32_t sbase = (uint32_t)__cvta_generic_to_shared(sb);
    const int nk = K / 32;

#pragma unroll
    for (int j = 0; j < 2; j++) {
        cp16(sbase + (0 * GSTG + soff[j]) * 2, Ah + (size_t)(bm + grow[j]) * K + gcol[j]);
        cp16(sbase + (1 * GSTG + soff[j]) * 2, Al + (size_t)(bm + grow[j]) * K + gcol[j]);
        cp16(sbase + (2 * GSTG + soff[j]) * 2, Bf + (size_t)(bn + grow[j]) * K + gcol[j]);
    }
    CP_COMMIT();

    for (int i = 0; i < nk; i++) {
        const __half* cur = sb + (size_t)(i & 1) * 3 * GSTG;

        CP_WAIT(0);
        __syncthreads();

        if (i + 1 < nk) {
            const uint32_t nxt = sbase + (uint32_t)(((i + 1) & 1) * 3 * GSTG) * 2;
            const int k0 = (i + 1) * 32;
#pragma unroll
            for (int j = 0; j < 2; j++) {
                cp16(nxt + (0 * GSTG + soff[j]) * 2, Ah + (size_t)(bm + grow[j]) * K + k0 + gcol[j]);
                cp16(nxt + (1 * GSTG + soff[j]) * 2, Al + (size_t)(bm + grow[j]) * K + k0 + gcol[j]);
                cp16(nxt + (2 * GSTG + soff[j]) * 2, Bf + (size_t)(bn + grow[j]) * K + k0 + gcol[j]);
            }
            CP_COMMIT();
        }

        const __half* sAh = cur;
        const __half* sAl = cur + 1 * GSTG;
        const __half* sB  = cur + 2 * GSTG;

#pragma unroll
        for (int kk = 0; kk < 32; kk += 16) {
            uint32_t afh[2][4], afl[2][4];
            const int acol = kk + lcoff;
            ldsm4(afh[0], &sAh[(wm + lrow     ) * GPAD + acol]);
            ldsm4(afh[1], &sAh[(wm + 16 + lrow) * GPAD + acol]);
            ldsm4(afl[0], &sAl[(wm + lrow     ) * GPAD + acol]);
            ldsm4(afl[1], &sAl[(wm + 16 + lrow) * GPAD + acol]);
#pragma unroll
            for (int np = 0; np < 4; np++) {
                const int br = wn + np * 16 + brow;
                const int bc = kk + bcoff;
                uint32_t bh[4];
                ldsm4(bh, &sB[br * GPAD + bc]);
                mma16816(acc[0][2 * np    ], afh[0], bh);
                mma16816(acc[1][2 * np    ], afh[1], bh);
                mma16816(acc[0][2 * np + 1], afh[0], bh + 2);
                mma16816(acc[1][2 * np + 1], afh[1], bh + 2);
                mma16816(acc[0][2 * np    ], afl[0], bh);
                mma16816(acc[1][2 * np    ], afl[1], bh);
                mma16816(acc[0][2 * np + 1], afl[0], bh + 2);
                mma16816(acc[1][2 * np + 1], afl[1], bh + 2);
            }
        }
    }

#pragma unroll
    for (int mt = 0; mt < 2; mt++) {
        const int row = bm + wm + mt * 16 + grp;
#pragma unroll
        for (int nt = 0; nt < 8; nt++) {
            const int col = bn + wn + nt * 8 + tig * 2;
            *(float2*)&C[(size_t)row * N + col]       = make_float2(acc[mt][nt][0], acc[mt][nt][1]);
            *(float2*)&C[(size_t)(row + 8) * N + col] = make_float2(acc[mt][nt][2], acc[mt][nt][3]);
        }
    }
}

// ---------------------------------------------------------------------------
// plain fp16 GEMM: C = A @ B^T, both single fp16 (1 MMA).  For O-proj.
// Same pipeline skeleton, 2 matrices per stage.
// ---------------------------------------------------------------------------
constexpr int G1_SMEM = 2 * 2 * GSTG * 2;   // 40960 bytes

__global__ __launch_bounds__(256, 2) void gemm_fp16x1(
    const __half* __restrict__ Af, const __half* __restrict__ Bf,
    float* __restrict__ C, int M, int N, int K)
{
    extern __shared__ __half sb[];

    const int tid = threadIdx.x;
    const int bm = blockIdx.y * 128;
    const int bn = blockIdx.x * 128;
    const int lane = tid & 31;
    const int wid  = tid >> 5;
    const int wm = (wid & 3) * 32;
    const int wn = (wid >> 2) * 64;
    const int grp = lane >> 2;
    const int tig = lane & 3;

    const int lrow  = lane & 15;
    const int lcoff = (lane >> 4) * 8;
    const int brow  = (lane & 7) + ((lane >> 4) << 3);
    const int bcoff = ((lane >> 3) & 1) * 8;

    uint32_t soff[2];
    int grow[2], gcol[2];
#pragma unroll
    for (int j = 0; j < 2; j++) {
        int c = tid + j * 256;
        grow[j] = c >> 2;
        gcol[j] = (c & 3) * 8;
        soff[j] = (uint32_t)(grow[j] * GPAD + gcol[j]);
    }

    float acc[2][8][4];
#pragma unroll
    for (int mt = 0; mt < 2; mt++)
#pragma unroll
        for (int nt = 0; nt < 8; nt++)
#pragma unroll
            for (int e = 0; e < 4; e++) acc[mt][nt][e] = 0.f;

    uint32_t sbase = (uint32_t)__cvta_generic_to_shared(sb);
    const int nk = K / 32;

#pragma unroll
    for (int j = 0; j < 2; j++) {
        cp16(sbase + (0 * GSTG + soff[j]) * 2, Af + (size_t)(bm + grow[j]) * K + gcol[j]);
        cp16(sbase + (1 * GSTG + soff[j]) * 2, Bf + (size_t)(bn + grow[j]) * K + gcol[j]);
    }
    CP_COMMIT();

    for (int i = 0; i < nk; i++) {
        const __half* cur = sb + (size_t)(i & 1) * 2 * GSTG;

        CP_WAIT(0);
        __syncthreads();

        if (i + 1 < nk) {
            const uint32_t nxt = sbase + (uint32_t)(((i + 1) & 1) * 2 * GSTG) * 2;
            const int k0 = (i + 1) * 32;
#pragma unroll
            for (int j = 0; j < 2; j++) {
                cp16(nxt + (0 * GSTG + soff[j]) * 2, Af + (size_t)(bm + grow[j]) * K + k0 + gcol[j]);
                cp16(nxt + (1 * GSTG + soff[j]) * 2, Bf + (size_t)(bn + grow[j]) * K + k0 + gcol[j]);
            }
            CP_COMMIT();
        }

        const __half* sA = cur;
        const __half* sB = cur + GSTG;

#pragma unroll
        for (int kk = 0; kk < 32; kk += 16) {
            uint32_t af[2][4];
            const int acol = kk + lcoff;
            ldsm4(af[0], &sA[(wm + lrow     ) * GPAD + acol]);
            ldsm4(af[1], &sA[(wm + 16 + lrow) * GPAD + acol]);
#pragma unroll
            for (int np = 0; np < 4; np++) {
                const int br = wn + np * 16 + brow;
                const int bc = kk + bcoff;
                uint32_t bh[4];
                ldsm4(bh, &sB[br * GPAD + bc]);
                mma16816(acc[0][2 * np    ], af[0], bh);
                mma16816(acc[1][2 * np    ], af[1], bh);
                mma16816(acc[0][2 * np + 1], af[0], bh + 2);
                mma16816(acc[1][2 * np + 1], af[1], bh + 2);
            }
        }
    }

#pragma unroll
    for (int mt = 0; mt < 2; mt++) {
        const int row = bm + wm + mt * 16 + grp;
#pragma unroll
        for (int nt = 0; nt < 8; nt++) {
            const int col = bn + wn + nt * 8 + tig * 2;
            *(float2*)&C[(size_t)row * N + col]       = make_float2(acc[mt][nt][0], acc[mt][nt][1]);
            *(float2*)&C[(size_t)(row + 8) * N + col] = make_float2(acc[mt][nt][2], acc[mt][nt][3]);
        }
    }
}

// ---------------------------------------------------------------------------
// RMSNorm + RoPE for Q: reads qkv fp32, writes fp16 hi/lo to (b,H,s,D),
// pre-scaled by 1/sqrt(D). One warp per row.
// ---------------------------------------------------------------------------
__global__ __launch_bounds__(256) void norm_rope_q(
    const float* __restrict__ qkv,
    __half* __restrict__ oh, __half* __restrict__ ol,
    const float* __restrict__ cs, const float* __restrict__ sn,
    const float* __restrict__ gamma)
{
    const int warp = (blockIdx.x * 256 + threadIdx.x) >> 5;
    const int lane = threadIdx.x & 31;
    const int h  = warp % NH;
    const int bs = warp / NH;
    const int sp = bs % SEQ;
    const int bi = bs / SEQ;

    const float* x = qkv + (size_t)bs * NQKV + h * HD;
    float e0 = x[lane], e1 = x[lane + 32], e2 = x[lane + 64], e3 = x[lane + 96];

    float ssq = e0 * e0 + e1 * e1 + e2 * e2 + e3 * e3;
#pragma unroll
    for (int o = 16; o; o >>= 1) ssq += __shfl_xor_sync(0xffffffffu, ssq, o);
    const float r = rsqrtf(ssq * (1.0f / HD) + 1e-6f);

    e0 *= r * gamma[lane];      e1 *= r * gamma[lane + 32];
    e2 *= r * gamma[lane + 64]; e3 *= r * gamma[lane + 96];

    const float* cp = cs + (size_t)bs * HD;
    const float* sg = sn + (size_t)bs * HD;
    float o4[4];
    o4[0] = (e0 * cp[lane]      - e2 * sg[lane])      * SM_SCALE;
    o4[1] = (e1 * cp[lane + 32] - e3 * sg[lane + 32]) * SM_SCALE;
    o4[2] = (e2 * cp[lane + 64] + e0 * sg[lane + 64]) * SM_SCALE;
    o4[3] = (e3 * cp[lane + 96] + e1 * sg[lane + 96]) * SM_SCALE;

    const size_t ob = (((size_t)bi * NH + h) * SEQ + sp) * HD;
#pragma unroll
    for (int j = 0; j < 4; j++) {
        __half hv = __float2half_rn(o4[j]);
        oh[ob + lane + 32 * j] = hv;
        ol[ob + lane + 32 * j] = __float2half_rn(o4[j] - __half2float(hv));
    }
}

// ---------------------------------------------------------------------------
// RMSNorm + RoPE for K: writes fp32 (b,KV,s,D) into d_out AND single fp16.
// ---------------------------------------------------------------------------
__global__ __launch_bounds__(256) void norm_rope_k(
    const float* __restrict__ qkv, float* __restrict__ kout,
    __half* __restrict__ of,
    const float* __restrict__ cs, const float* __restrict__ sn,
    const float* __restrict__ gamma)
{
    const int warp = (blockIdx.x * 256 + threadIdx.x) >> 5;
    const int lane = threadIdx.x & 31;
    const int h  = warp % NKV;
    const int bs = warp / NKV;
    const int sp = bs % SEQ;
    const int bi = bs / SEQ;

    const float* x = qkv + (size_t)bs * NQKV + KOFF + h * HD;
    float e0 = x[lane], e1 = x[lane + 32], e2 = x[lane + 64], e3 = x[lane + 96];

    float ssq = e0 * e0 + e1 * e1 + e2 * e2 + e3 * e3;
#pragma unroll
    for (int o = 16; o; o >>= 1) ssq += __shfl_xor_sync(0xffffffffu, ssq, o);
    const float r = rsqrtf(ssq * (1.0f / HD) + 1e-6f);

    e0 *= r * gamma[lane];      e1 *= r * gamma[lane + 32];
    e2 *= r * gamma[lane + 64]; e3 *= r * gamma[lane + 96];

    const float* cp = cs + (size_t)bs * HD;
    const float* sg = sn + (size_t)bs * HD;
    float o4[4];
    o4[0] = e0 * cp[lane]      - e2 * sg[lane];
    o4[1] = e1 * cp[lane + 32] - e3 * sg[lane + 32];
    o4[2] = e2 * cp[lane + 64] + e0 * sg[lane + 64];
    o4[3] = e3 * cp[lane + 96] + e1 * sg[lane + 96];

    const size_t ob = (((size_t)bi * NKV + h) * SEQ + sp) * HD;
#pragma unroll
    for (int j = 0; j < 4; j++) {
        kout[ob + lane + 32 * j] = o4[j];
        of[ob + lane + 32 * j] = __float2half_rn(o4[j]);
    }
}

// ---------------------------------------------------------------------------
// V: one pass. Reads qkv V region, writes fp32 (b,KV,s,D) to d_out AND
// fp16 transposed (b,KV,D,s).
// ---------------------------------------------------------------------------
__global__ void vtrans_fused(
    const float* __restrict__ qkv, float* __restrict__ vout,
    __half* __restrict__ vf)
{
    __shared__ float t[32][33];
    const int s0 = blockIdx.x * 32, d0 = blockIdx.y * 32;
    const int bz = blockIdx.z;                 // bi*NKV + kh
    const int bi = bz / NKV, kh = bz % NKV;
    const int tx = threadIdx.x, ty = threadIdx.y;

#pragma unroll
    for (int j = 0; j < 4; j++) {
        int s = s0 + ty + j * 8;
        float v = qkv[(size_t)(bi * SEQ + s) * NQKV + VOFF + kh * HD + d0 + tx];
        t[ty + j * 8][tx] = v;
        vout[((size_t)bz * SEQ + s) * HD + d0 + tx] = v;   // fp32 (b,KV,s,D)
    }
    __syncthreads();
#pragma unroll
    for (int j = 0; j < 4; j++) {
        int d = d0 + ty + j * 8;
        size_t idx = ((size_t)bz * HD + d) * SEQ + s0 + tx;
        vf[idx] = __float2half_rn(t[tx][ty + j * 8]);
    }
}

// ---------------------------------------------------------------------------
// Tensor-core causal flash attention, fp16 scheme:
// S = (Qh + Ql) @ K  (2 MMAs);  O += P @ V  (1 MMA).  Output single fp16.
// BM=128, BN=64, 256 threads; K/V double-buffered via cp.async.
// ---------------------------------------------------------------------------
constexpr int FQP = 136;  // pitch (fp16) for Q/K tiles
constexpr int FVP = 72;   // pitch (fp16) for Vt tiles
constexpr int FKV = 64 * FQP + 128 * FVP;            // KV stage elems (17920)
constexpr int FLASH_SMEM = (2 * 128 * FQP + 2 * FKV) * 2;  // 141312 B

__global__ __launch_bounds__(256, 1) void flash_mma(
    const __half* __restrict__ Qh, const __half* __restrict__ Ql,
    const __half* __restrict__ Kf, const __half* __restrict__ Vf,
    __half* __restrict__ Oa)
{
    extern __shared__ __half sm[];
    __half* sQh = sm;
    __half* sQl = sQh + 128 * FQP;
    __half* sKV = sQl + 128 * FQP;    // 2 stages of [K | V]

    const int qtile = blockIdx.x;
    const int h     = blockIdx.y;
    const int bi    = blockIdx.z;
    const int kh    = h / GQ;
    const int tid   = threadIdx.x;
    const int lane  = tid & 31;
    const int wid   = tid >> 5;
    const int grp   = lane >> 2;
    const int tig   = lane & 3;
    const int q0    = qtile * 128;

    const int lrow  = lane & 15;
    const int lcoff = (lane >> 4) * 8;
    const int brow  = (lane & 7) + ((lane >> 4) << 3);
    const int bcoff = ((lane >> 3) & 1) * 8;

    const __half* kg = Kf + (((size_t)bi * NKV + kh) * SEQ) * HD;
    const __half* vg = Vf + (((size_t)bi * NKV + kh) * HD) * SEQ;
    const uint32_t skv = (uint32_t)__cvta_generic_to_shared(sKV);

    int kr[4], kc[4], vr[4], vc[4];
    uint32_t kso[4], vso[4];
#pragma unroll
    for (int j = 0; j < 4; j++) {
        int c = tid + j * 256;
        kr[j] = c >> 4; kc[j] = (c & 15) * 8;
        kso[j] = (uint32_t)(kr[j] * FQP + kc[j]);
        vr[j] = c >> 3; vc[j] = (c & 7) * 8;
        vso[j] = (uint32_t)(vr[j] * FVP + vc[j]);
    }

    auto issue_kv = [&](int s, int k0) {
        const uint32_t st = skv + (uint32_t)(s * FKV) * 2;
#pragma unroll
        for (int j = 0; j < 4; j++) {
            cp16(st + kso[j] * 2,                  kg + (size_t)(k0 + kr[j]) * HD + kc[j]);
            cp16(st + (64 * FQP + vso[j]) * 2,     vg + (size_t)vr[j] * SEQ + k0 + vc[j]);
        }
        CP_COMMIT();
    };

    // Q tile load (128 x 128, hi+lo)
    {
        const __half* qgh = Qh + (((size_t)bi * NH + h) * SEQ + q0) * HD;
        const __half* qgl = Ql + (((size_t)bi * NH + h) * SEQ + q0) * HD;
        for (int i = tid; i < 128 * 16; i += 256) {
            int r = i >> 4, c = (i & 15) * 8;
            *(uint4*)&sQh[r * FQP + c] = *(const uint4*)&qgh[(size_t)r * HD + c];
            *(uint4*)&sQl[r * FQP + c] = *(const uint4*)&qgl[(size_t)r * HD + c];
        }
    }

    float o[16][4];
#pragma unroll
    for (int nt = 0; nt < 16; nt++)
#pragma unroll
        for (int e = 0; e < 4; e++) o[nt][e] = 0.f;
    float m0 = -1e30f, m1 = -1e30f, l0 = 0.f, l1 = 0.f;

    const int ntiles = 2 * qtile + 2;

    issue_kv(0, 0);   // prologue

    for (int t = 0; t < ntiles; ++t) {
        const int k0 = t * 64;
        const __half* cur = sKV + (size_t)(t & 1) * FKV;
        const __half* sK = cur;
        const __half* sV = cur + 64 * FQP;

        CP_WAIT(0);
        __syncthreads();

        if (t + 1 < ntiles) issue_kv((t + 1) & 1, (t + 1) * 64);

        float s[8][4];
#pragma unroll
        for (int nt = 0; nt < 8; nt++)
#pragma unroll
            for (int e = 0; e < 4; e++) s[nt][e] = 0.f;

#pragma unroll
        for (int kk = 0; kk < 128; kk += 16) {
            uint32_t ah[4], al[4];
            const int acol = kk + lcoff;
            ldsm4(ah, &sQh[(wid * 16 + lrow) * FQP + acol]);
            ldsm4(al, &sQl[(wid * 16 + lrow) * FQP + acol]);
#pragma unroll
            for (int np = 0; np < 4; np++) {
                const int br = np * 16 + brow;
                const int bc = kk + bcoff;
                uint32_t bh[4];
                ldsm4(bh, &sK[br * FQP + bc]);
                mma16816(s[2 * np    ], ah, bh);
                mma16816(s[2 * np + 1], ah, bh + 2);
                mma16816(s[2 * np    ], al, bh);
                mma16816(s[2 * np + 1], al, bh + 2);
            }
        }

        if (t >= ntiles - 2) {   // causal mask (last two tiles span the diagonal)
            const int r0 = q0 + wid * 16 + grp;
#pragma unroll
            for (int nt = 0; nt < 8; nt++) {
                const int c = k0 + nt * 8 + tig * 2;
                if (c     > r0)     s[nt][0] = -1e30f;
                if (c + 1 > r0)     s[nt][1] = -1e30f;
                if (c     > r0 + 8) s[nt][2] = -1e30f;
                if (c + 1 > r0 + 8) s[nt][3] = -1e30f;
            }
        }

        float mx0 = -1e30f, mx1 = -1e30f;
#pragma unroll
        for (int nt = 0; nt < 8; nt++) {
            mx0 = fmaxf(mx0, fmaxf(s[nt][0], s[nt][1]));
            mx1 = fmaxf(mx1, fmaxf(s[nt][2], s[nt][3]));
        }
        mx0 = fmaxf(mx0, __shfl_xor_sync(0xffffffffu, mx0, 1));
        mx0 = fmaxf(mx0, __shfl_xor_sync(0xffffffffu, mx0, 2));
        mx1 = fmaxf(mx1, __shfl_xor_sync(0xffffffffu, mx1, 1));
        mx1 = fmaxf(mx1, __shfl_xor_sync(0xffffffffu, mx1, 2));

        const float nm0 = fmaxf(m0, mx0);
        const float nm1 = fmaxf(m1, mx1);
        const float a0 = __expf(m0 - nm0);
        const float a1 = __expf(m1 - nm1);
        m0 = nm0; m1 = nm1;

        float rs0 = 0.f, rs1 = 0.f;
#pragma unroll
        for (int nt = 0; nt < 8; nt++) {
            s[nt][0] = __expf(s[nt][0] - m0);
            s[nt][1] = __expf(s[nt][1] - m0);
            s[nt][2] = __expf(s[nt][2] - m1);
            s[nt][3] = __expf(s[nt][3] - m1);
            rs0 += s[nt][0] + s[nt][1];
            rs1 += s[nt][2] + s[nt][3];
        }
        rs0 += __shfl_xor_sync(0xffffffffu, rs0, 1);
        rs0 += __shfl_xor_sync(0xffffffffu, rs0, 2);
        rs1 += __shfl_xor_sync(0xffffffffu, rs1, 1);
        rs1 += __shfl_xor_sync(0xffffffffu, rs1, 2);
        l0 = l0 * a0 + rs0;
        l1 = l1 * a1 + rs1;

#pragma unroll
        for (int nt = 0; nt < 16; nt++) {
            o[nt][0] *= a0; o[nt][1] *= a0;
            o[nt][2] *= a1; o[nt][3] *= a1;
        }

        // O += P @ V  (P single fp16)
#pragma unroll
        for (int ks = 0; ks < 4; ks++) {
            uint32_t ph[4];
            ph[0] = pack2f16(s[2 * ks][0],     s[2 * ks][1]);
            ph[1] = pack2f16(s[2 * ks][2],     s[2 * ks][3]);
            ph[2] = pack2f16(s[2 * ks + 1][0], s[2 * ks + 1][1]);
            ph[3] = pack2f16(s[2 * ks + 1][2], s[2 * ks + 1][3]);
            const int bc = ks * 16 + bcoff;
#pragma unroll
            for (int np = 0; np < 8; np++) {
                const int br = np * 16 + brow;
                uint32_t vh4[4];
                ldsm4(vh4, &sV[br * FVP + bc]);
                mma16816(o[2 * np    ], ph, vh4);
                mma16816(o[2 * np + 1], ph, vh4 + 2);
            }
        }
    }

    // epilogue: normalize and write single fp16 (b*s, H*D)
    const float i0 = 1.0f / l0;
    const float i1 = 1.0f / l1;
    const size_t row0 = (size_t)bi * SEQ + q0 + wid * 16 + grp;
    const size_t row1 = row0 + 8;
    const int colb = h * HD + tig * 2;
#pragma unroll
    for (int nt = 0; nt < 16; nt++) {
        *(uint32_t*)&Oa[row0 * (NH * HD) + colb + nt * 8] =
            pack2f16(o[nt][0] * i0, o[nt][1] * i0);
        *(uint32_t*)&Oa[row1 * (NH * HD) + colb + nt * 8] =
            pack2f16(o[nt][2] * i1, o[nt][3] * i1);
    }
}

// ---------------------------------------------------------------------------
// kernel_launch
// ---------------------------------------------------------------------------
extern "C" void kernel_launch(void* const* d_in, const int* in_sizes, int n_in,
                              void* d_out, int out_size)
{
    const float* hidden = (const float*)d_in[0];
    const float* cosb   = (const float*)d_in[1];
    const float* sinb   = (const float*)d_in[2];
    const float* wq     = (const float*)d_in[3];
    const float* wk     = (const float*)d_in[4];
    const float* wv     = (const float*)d_in[5];
    const float* wo     = (const float*)d_in[6];
    const float* qg     = (const float*)d_in[7];
    const float* kg     = (const float*)d_in[8];

    float* out  = (float*)d_out;
    float* kout = out  + (size_t)NB * SEQ * HDIM;
    float* vout = kout + (size_t)NB * NKV * SEQ * HD;

    __half *hidh, *hidl, *wqkvf, *wof, *ao, *qh, *ql, *kf, *vf;
    float *qkv;
    cudaGetSymbolAddress((void**)&hidh,  g_hid_h);
    cudaGetSymbolAddress((void**)&hidl,  g_hid_l);
    cudaGetSymbolAddress((void**)&wqkvf, g_wqkv);
    cudaGetSymbolAddress((void**)&wof,   g_wo);
    cudaGetSymbolAddress((void**)&ao,    g_ao);
    cudaGetSymbolAddress((void**)&qkv,   g_qkv);
    cudaGetSymbolAddress((void**)&qh,    g_qh);
    cudaGetSymbolAddress((void**)&ql,    g_ql);
    cudaGetSymbolAddress((void**)&kf,    g_kf);
    cudaGetSymbolAddress((void**)&vf,    g_vf);

    cudaFuncSetAttribute(flash_mma, cudaFuncAttributeMaxDynamicSharedMemorySize, FLASH_SMEM);
    cudaFuncSetAttribute(gemm_fp16x2, cudaFuncAttributeMaxDynamicSharedMemorySize, GEMM_SMEM);
    cudaFuncSetAttribute(gemm_fp16x1, cudaFuncAttributeMaxDynamicSharedMemorySize, G1_SMEM);

    // fp32 -> fp16 conversions
    const size_t nHid = (size_t)MROWS * HDIM;
    const size_t nWq  = (size_t)NH  * HD * HDIM;
    const size_t nWk  = (size_t)NKV * HD * HDIM;
    split_fp16<<<(int)(nHid / 1024), 256>>>((const float4*)hidden, hidh, hidl);
    conv_fp16<<<(int)(nWq / 1024), 256>>>((const float4*)wq, wqkvf);
    conv_fp16<<<(int)(nWk / 1024), 256>>>((const float4*)wk, wqkvf + nWq);
    conv_fp16<<<(int)(nWk / 1024), 256>>>((const float4*)wv, wqkvf + nWq + nWk);
    conv_fp16<<<(int)(nWq / 1024), 256>>>((const float4*)wo, wof);

    // Fused QKV projection (A hi/lo, B single)
    gemm_fp16x2<<<dim3(NQKV / 128, MROWS / 128), 256, GEMM_SMEM>>>(
        hidh, hidl, wqkvf, qkv, MROWS, NQKV, HDIM);

    // RMSNorm + RoPE -> fp16 operands (+ fp32 K into d_out)
    norm_rope_q<<<(MROWS * NH ) / 8, 256>>>(qkv, qh, ql, cosb, sinb, qg);
    norm_rope_k<<<(MROWS * NKV) / 8, 256>>>(qkv, kout, kf, cosb, sinb, kg);

    // V: fp32 into d_out's new_v AND fp16 transposed, single pass
    vtrans_fused<<<dim3(SEQ / 32, HD / 32, NB * NKV), dim3(32, 8)>>>(qkv, vout, vf);

    // Tensor-core causal GQA flash attention -> single fp16 O
    flash_mma<<<dim3(SEQ / 128, NH, NB), 256, FLASH_SMEM>>>(
        qh, ql, kf, vf, ao);

    // Output projection (both single fp16, 1 MMA)
    gemm_fp16x1<<<dim3(HDIM / 128, MROWS / 128), 256, G1_SMEM>>>(
        ao, wof, out, MROWS, HDIM, NH * HD);
}

// round 15
// speedup vs baseline: 2.2596x; 1.0497x over previous
#include <cuda_runtime.h>
#include <cuda_fp16.h>
#include <cstdint>

// Problem constants
constexpr int NB   = 2;      // batch
constexpr int SEQ  = 2048;   // sequence
constexpr int HDIM = 2560;   // hidden
constexpr int NH   = 32;     // q heads
constexpr int NKV  = 8;      // kv heads
constexpr int HD   = 128;    // head dim
constexpr int GQ   = NH / NKV;
constexpr int MROWS = NB * SEQ;            // 4096
constexpr int NQKV  = (NH + 2 * NKV) * HD; // 6144
constexpr int KOFF  = NH * HD;             // 4096
constexpr int VOFF  = (NH + NKV) * HD;     // 5120
constexpr float SM_SCALE = 0.08838834764831845f;  // 1/sqrt(128)

// ---------------- device scratch (no allocation allowed) ----------------
__device__ __half g_hid_h [(size_t)MROWS * HDIM];
__device__ __half g_hid_l [(size_t)MROWS * HDIM];
__device__ __half g_wqkv  [(size_t)NQKV * HDIM];        // single fp16
__device__ __half g_wo    [(size_t)HDIM * NH * HD];     // single fp16
__device__ __half g_ao    [(size_t)MROWS * NH * HD];    // attention out, single fp16
__device__ float g_qkv[(size_t)MROWS * NQKV];           // 96MB
// fp16 attention operands (all single precision now except hidden)
__device__ __half g_qf[(size_t)NB * NH  * SEQ * HD];    // (b,H,s,D), pre-scaled
__device__ __half g_kf[(size_t)NB * NKV * SEQ * HD];    // (b,KV,s,D)
__device__ __half g_vf[(size_t)NB * NKV * HD * SEQ];    // (b,KV,D,s) transposed

// ---------------------------------------------------------------------------
// cp.async / ldmatrix helpers
// ---------------------------------------------------------------------------
__device__ __forceinline__ void cp16(uint32_t smem, const void* gmem)
{
    asm volatile("cp.async.cg.shared.global [%0], [%1], 16;\n" :: "r"(smem), "l"(gmem));
}
#define CP_COMMIT() asm volatile("cp.async.commit_group;\n" ::: "memory")
#define CP_WAIT(n)  asm volatile("cp.async.wait_group %0;\n" :: "n"(n) : "memory")

__device__ __forceinline__ void ldsm4(uint32_t* r, const void* p)
{
    uint32_t a = (uint32_t)__cvta_generic_to_shared(p);
    asm volatile("ldmatrix.sync.aligned.m8n8.x4.shared.b16 {%0,%1,%2,%3}, [%4];"
        : "=r"(r[0]), "=r"(r[1]), "=r"(r[2]), "=r"(r[3]) : "r"(a));
}

// ---------------------------------------------------------------------------
// fp32 -> fp16 hi/lo split, and fp32 -> fp16 single convert
// ---------------------------------------------------------------------------
__global__ __launch_bounds__(256) void split_fp16(
    const float4* __restrict__ in, __half* __restrict__ hi,
    __half* __restrict__ lo)
{
    const size_t i = (size_t)blockIdx.x * 256 + threadIdx.x;
    float4 x = in[i];
    __half h[4], l[4];
    float xs[4] = {x.x, x.y, x.z, x.w};
#pragma unroll
    for (int j = 0; j < 4; j++) {
        h[j] = __float2half_rn(xs[j]);
        l[j] = __float2half_rn(xs[j] - __half2float(h[j]));
    }
    *(uint2*)&hi[i * 4] = *(uint2*)h;
    *(uint2*)&lo[i * 4] = *(uint2*)l;
}

__global__ __launch_bounds__(256) void conv_fp16(
    const float4* __restrict__ in, __half* __restrict__ out)
{
    const size_t i = (size_t)blockIdx.x * 256 + threadIdx.x;
    float4 x = in[i];
    __half h[4] = {__float2half_rn(x.x), __float2half_rn(x.y),
                   __float2half_rn(x.z), __float2half_rn(x.w)};
    *(uint2*)&out[i * 4] = *(uint2*)h;
}

// ---------------------------------------------------------------------------
// mma.m16n8k16 fp16 wrapper (fp32 accumulate)
// ---------------------------------------------------------------------------
__device__ __forceinline__ void mma16816(float* c, const uint32_t* a, const uint32_t* b)
{
    asm volatile(
        "mma.sync.aligned.m16n8k16.row.col.f32.f16.f16.f32 "
        "{%0,%1,%2,%3}, {%4,%5,%6,%7}, {%8,%9}, {%0,%1,%2,%3};"
        : "+f"(c[0]), "+f"(c[1]), "+f"(c[2]), "+f"(c[3])
        : "r"(a[0]), "r"(a[1]), "r"(a[2]), "r"(a[3]), "r"(b[0]), "r"(b[1]));
}

__device__ __forceinline__ uint32_t pack2f16(float x, float y)
{
    __half2 h2 = __halves2half2(__float2half_rn(x), __float2half_rn(y));
    return *(uint32_t*)&h2;
}

// ---------------------------------------------------------------------------
// fp16-split tensor-core GEMM: C = A @ B^T, A hi/lo (2 MMAs), B single.
// BK=32, 2-stage cp.async, one sync/iter, 2 CTAs/SM. Block 128x128.
// ---------------------------------------------------------------------------
constexpr int GPAD = 40;                      // smem row pitch (fp16): 80B, ldsm conflict-free
constexpr int GSTG = 128 * GPAD;              // fp16 per matrix per stage (5120)
constexpr int GEMM_SMEM = 2 * 3 * GSTG * 2;   // 61440 bytes

__global__ __launch_bounds__(256, 2) void gemm_fp16x2(
    const __half* __restrict__ Ah, const __half* __restrict__ Al,
    const __half* __restrict__ Bf,
    float* __restrict__ C, int M, int N, int K)
{
    extern __shared__ __half sb[];

    const int tid = threadIdx.x;
    const int bm = blockIdx.y * 128;
    const int bn = blockIdx.x * 128;
    const int lane = tid & 31;
    const int wid  = tid >> 5;
    const int wm = (wid & 3) * 32;
    const int wn = (wid >> 2) * 64;
    const int grp = lane >> 2;
    const int tig = lane & 3;

    const int lrow  = lane & 15;
    const int lcoff = (lane >> 4) * 8;
    const int brow  = (lane & 7) + ((lane >> 4) << 3);
    const int bcoff = ((lane >> 3) & 1) * 8;

    uint32_t soff[2];
    int grow[2], gcol[2];
#pragma unroll
    for (int j = 0; j < 2; j++) {
        int c = tid + j * 256;
        grow[j] = c >> 2;
        gcol[j] = (c & 3) * 8;
        soff[j] = (uint32_t)(grow[j] * GPAD + gcol[j]);
    }

    float acc[2][8][4];
#pragma unroll
    for (int mt = 0; mt < 2; mt++)
#pragma unroll
        for (int nt = 0; nt < 8; nt++)
#pragma unroll
            for (int e = 0; e < 4; e++) acc[mt][nt][e] = 0.f;

    uint32_t sbase = (uint32_t)__cvta_generic_to_shared(sb);
    const int nk = K / 32;

#pragma unroll
    for (int j = 0; j < 2; j++) {
        cp16(sbase + (0 * GSTG + soff[j]) * 2, Ah + (size_t)(bm + grow[j]) * K + gcol[j]);
        cp16(sbase + (1 * GSTG + soff[j]) * 2, Al + (size_t)(bm + grow[j]) * K + gcol[j]);
        cp16(sbase + (2 * GSTG + soff[j]) * 2, Bf + (size_t)(bn + grow[j]) * K + gcol[j]);
    }
    CP_COMMIT();

    for (int i = 0; i < nk; i++) {
        const __half* cur = sb + (size_t)(i & 1) * 3 * GSTG;

        CP_WAIT(0);
        __syncthreads();

        if (i + 1 < nk) {
            const uint32_t nxt = sbase + (uint32_t)(((i + 1) & 1) * 3 * GSTG) * 2;
            const int k0 = (i + 1) * 32;
#pragma unroll
            for (int j = 0; j < 2; j++) {
                cp16(nxt + (0 * GSTG + soff[j]) * 2, Ah + (size_t)(bm + grow[j]) * K + k0 + gcol[j]);
                cp16(nxt + (1 * GSTG + soff[j]) * 2, Al + (size_t)(bm + grow[j]) * K + k0 + gcol[j]);
                cp16(nxt + (2 * GSTG + soff[j]) * 2, Bf + (size_t)(bn + grow[j]) * K + k0 + gcol[j]);
            }
            CP_COMMIT();
        }

        const __half* sAh = cur;
        const __half* sAl = cur + 1 * GSTG;
        const __half* sB  = cur + 2 * GSTG;

#pragma unroll
        for (int kk = 0; kk < 32; kk += 16) {
            uint32_t afh[2][4], afl[2][4];
            const int acol = kk + lcoff;
            ldsm4(afh[0], &sAh[(wm + lrow     ) * GPAD + acol]);
            ldsm4(afh[1], &sAh[(wm + 16 + lrow) * GPAD + acol]);
            ldsm4(afl[0], &sAl[(wm + lrow     ) * GPAD + acol]);
            ldsm4(afl[1], &sAl[(wm + 16 + lrow) * GPAD + acol]);
#pragma unroll
            for (int np = 0; np < 4; np++) {
                const int br = wn + np * 16 + brow;
                const int bc = kk + bcoff;
                uint32_t bh[4];
                ldsm4(bh, &sB[br * GPAD + bc]);
                mma16816(acc[0][2 * np    ], afh[0], bh);
                mma16816(acc[1][2 * np    ], afh[1], bh);
                mma16816(acc[0][2 * np + 1], afh[0], bh + 2);
                mma16816(acc[1][2 * np + 1], afh[1], bh + 2);
                mma16816(acc[0][2 * np    ], afl[0], bh);
                mma16816(acc[1][2 * np    ], afl[1], bh);
                mma16816(acc[0][2 * np + 1], afl[0], bh + 2);
                mma16816(acc[1][2 * np + 1], afl[1], bh + 2);
            }
        }
    }

#pragma unroll
    for (int mt = 0; mt < 2; mt++) {
        const int row = bm + wm + mt * 16 + grp;
#pragma unroll
        for (int nt = 0; nt < 8; nt++) {
            const int col = bn + wn + nt * 8 + tig * 2;
            *(float2*)&C[(size_t)row * N + col]       = make_float2(acc[mt][nt][0], acc[mt][nt][1]);
            *(float2*)&C[(size_t)(row + 8) * N + col] = make_float2(acc[mt][nt][2], acc[mt][nt][3]);
        }
    }
}

// ---------------------------------------------------------------------------
// plain fp16 GEMM: C = A @ B^T, both single fp16 (1 MMA).  For O-proj.
// ---------------------------------------------------------------------------
constexpr int G1_SMEM = 2 * 2 * GSTG * 2;   // 40960 bytes

__global__ __launch_bounds__(256, 2) void gemm_fp16x1(
    const __half* __restrict__ Af, const __half* __restrict__ Bf,
    float* __restrict__ C, int M, int N, int K)
{
    extern __shared__ __half sb[];

    const int tid = threadIdx.x;
    const int bm = blockIdx.y * 128;
    const int bn = blockIdx.x * 128;
    const int lane = tid & 31;
    const int wid  = tid >> 5;
    const int wm = (wid & 3) * 32;
    const int wn = (wid >> 2) * 64;
    const int grp = lane >> 2;
    const int tig = lane & 3;

    const int lrow  = lane & 15;
    const int lcoff = (lane >> 4) * 8;
    const int brow  = (lane & 7) + ((lane >> 4) << 3);
    const int bcoff = ((lane >> 3) & 1) * 8;

    uint32_t soff[2];
    int grow[2], gcol[2];
#pragma unroll
    for (int j = 0; j < 2; j++) {
        int c = tid + j * 256;
        grow[j] = c >> 2;
        gcol[j] = (c & 3) * 8;
        soff[j] = (uint32_t)(grow[j] * GPAD + gcol[j]);
    }

    float acc[2][8][4];
#pragma unroll
    for (int mt = 0; mt < 2; mt++)
#pragma unroll
        for (int nt = 0; nt < 8; nt++)
#pragma unroll
            for (int e = 0; e < 4; e++) acc[mt][nt][e] = 0.f;

    uint32_t sbase = (uint32_t)__cvta_generic_to_shared(sb);
    const int nk = K / 32;

#pragma unroll
    for (int j = 0; j < 2; j++) {
        cp16(sbase + (0 * GSTG + soff[j]) * 2, Af + (size_t)(bm + grow[j]) * K + gcol[j]);
        cp16(sbase + (1 * GSTG + soff[j]) * 2, Bf + (size_t)(bn + grow[j]) * K + gcol[j]);
    }
    CP_COMMIT();

    for (int i = 0; i < nk; i++) {
        const __half* cur = sb + (size_t)(i & 1) * 2 * GSTG;

        CP_WAIT(0);
        __syncthreads();

        if (i + 1 < nk) {
            const uint32_t nxt = sbase + (uint32_t)(((i + 1) & 1) * 2 * GSTG) * 2;
            const int k0 = (i + 1) * 32;
#pragma unroll
            for (int j = 0; j < 2; j++) {
                cp16(nxt + (0 * GSTG + soff[j]) * 2, Af + (size_t)(bm + grow[j]) * K + k0 + gcol[j]);
                cp16(nxt + (1 * GSTG + soff[j]) * 2, Bf + (size_t)(bn + grow[j]) * K + k0 + gcol[j]);
            }
            CP_COMMIT();
        }

        const __half* sA = cur;
        const __half* sB = cur + GSTG;

#pragma unroll
        for (int kk = 0; kk < 32; kk += 16) {
            uint32_t af[2][4];
            const int acol = kk + lcoff;
            ldsm4(af[0], &sA[(wm + lrow     ) * GPAD + acol]);
            ldsm4(af[1], &sA[(wm + 16 + lrow) * GPAD + acol]);
#pragma unroll
            for (int np = 0; np < 4; np++) {
                const int br = wn + np * 16 + brow;
                const int bc = kk + bcoff;
                uint32_t bh[4];
                ldsm4(bh, &sB[br * GPAD + bc]);
                mma16816(acc[0][2 * np    ], af[0], bh);
                mma16816(acc[1][2 * np    ], af[1], bh);
                mma16816(acc[0][2 * np + 1], af[0], bh + 2);
                mma16816(acc[1][2 * np + 1], af[1], bh + 2);
            }
        }
    }

#pragma unroll
    for (int mt = 0; mt < 2; mt++) {
        const int row = bm + wm + mt * 16 + grp;
#pragma unroll
        for (int nt = 0; nt < 8; nt++) {
            const int col = bn + wn + nt * 8 + tig * 2;
            *(float2*)&C[(size_t)row * N + col]       = make_float2(acc[mt][nt][0], acc[mt][nt][1]);
            *(float2*)&C[(size_t)(row + 8) * N + col] = make_float2(acc[mt][nt][2], acc[mt][nt][3]);
        }
    }
}

// ---------------------------------------------------------------------------
// RMSNorm + RoPE for Q: reads qkv fp32, writes single fp16 to (b,H,s,D),
// pre-scaled by 1/sqrt(D). One warp per row.
// ---------------------------------------------------------------------------
__global__ __launch_bounds__(256) void norm_rope_q(
    const float* __restrict__ qkv, __half* __restrict__ of,
    const float* __restrict__ cs, const float* __restrict__ sn,
    const float* __restrict__ gamma)
{
    const int warp = (blockIdx.x * 256 + threadIdx.x) >> 5;
    const int lane = threadIdx.x & 31;
    const int h  = warp % NH;
    const int bs = warp / NH;
    const int sp = bs % SEQ;
    const int bi = bs / SEQ;

    const float* x = qkv + (size_t)bs * NQKV + h * HD;
    float e0 = x[lane], e1 = x[lane + 32], e2 = x[lane + 64], e3 = x[lane + 96];

    float ssq = e0 * e0 + e1 * e1 + e2 * e2 + e3 * e3;
#pragma unroll
    for (int o = 16; o; o >>= 1) ssq += __shfl_xor_sync(0xffffffffu, ssq, o);
    const float r = rsqrtf(ssq * (1.0f / HD) + 1e-6f);

    e0 *= r * gamma[lane];      e1 *= r * gamma[lane + 32];
    e2 *= r * gamma[lane + 64]; e3 *= r * gamma[lane + 96];

    const float* cp = cs + (size_t)bs * HD;
    const float* sg = sn + (size_t)bs * HD;
    float o4[4];
    o4[0] = (e0 * cp[lane]      - e2 * sg[lane])      * SM_SCALE;
    o4[1] = (e1 * cp[lane + 32] - e3 * sg[lane + 32]) * SM_SCALE;
    o4[2] = (e2 * cp[lane + 64] + e0 * sg[lane + 64]) * SM_SCALE;
    o4[3] = (e3 * cp[lane + 96] + e1 * sg[lane + 96]) * SM_SCALE;

    const size_t ob = (((size_t)bi * NH + h) * SEQ + sp) * HD;
#pragma unroll
    for (int j = 0; j < 4; j++)
        of[ob + lane + 32 * j] = __float2half_rn(o4[j]);
}

// ---------------------------------------------------------------------------
// RMSNorm + RoPE for K: writes fp32 (b,KV,s,D) into d_out AND single fp16.
// ---------------------------------------------------------------------------
__global__ __launch_bounds__(256) void norm_rope_k(
    const float* __restrict__ qkv, float* __restrict__ kout,
    __half* __restrict__ of,
    const float* __restrict__ cs, const float* __restrict__ sn,
    const float* __restrict__ gamma)
{
    const int warp = (blockIdx.x * 256 + threadIdx.x) >> 5;
    const int lane = threadIdx.x & 31;
    const int h  = warp % NKV;
    const int bs = warp / NKV;
    const int sp = bs % SEQ;
    const int bi = bs / SEQ;

    const float* x = qkv + (size_t)bs * NQKV + KOFF + h * HD;
    float e0 = x[lane], e1 = x[lane + 32], e2 = x[lane + 64], e3 = x[lane + 96];

    float ssq = e0 * e0 + e1 * e1 + e2 * e2 + e3 * e3;
#pragma unroll
    for (int o = 16; o; o >>= 1) ssq += __shfl_xor_sync(0xffffffffu, ssq, o);
    const float r = rsqrtf(ssq * (1.0f / HD) + 1e-6f);

    e0 *= r * gamma[lane];      e1 *= r * gamma[lane + 32];
    e2 *= r * gamma[lane + 64]; e3 *= r * gamma[lane + 96];

    const float* cp = cs + (size_t)bs * HD;
    const float* sg = sn + (size_t)bs * HD;
    float o4[4];
    o4[0] = e0 * cp[lane]      - e2 * sg[lane];
    o4[1] = e1 * cp[lane + 32] - e3 * sg[lane + 32];
    o4[2] = e2 * cp[lane + 64] + e0 * sg[lane + 64];
    o4[3] = e3 * cp[lane + 96] + e1 * sg[lane + 96];

    const size_t ob = (((size_t)bi * NKV + h) * SEQ + sp) * HD;
#pragma unroll
    for (int j = 0; j < 4; j++) {
        kout[ob + lane + 32 * j] = o4[j];
        of[ob + lane + 32 * j] = __float2half_rn(o4[j]);
    }
}

// ---------------------------------------------------------------------------
// V: one pass. Reads qkv V region, writes fp32 (b,KV,s,D) to d_out AND
// fp16 transposed (b,KV,D,s).
// ---------------------------------------------------------------------------
__global__ void vtrans_fused(
    const float* __restrict__ qkv, float* __restrict__ vout,
    __half* __restrict__ vf)
{
    __shared__ float t[32][33];
    const int s0 = blockIdx.x * 32, d0 = blockIdx.y * 32;
    const int bz = blockIdx.z;                 // bi*NKV + kh
    const int bi = bz / NKV, kh = bz % NKV;
    const int tx = threadIdx.x, ty = threadIdx.y;

#pragma unroll
    for (int j = 0; j < 4; j++) {
        int s = s0 + ty + j * 8;
        float v = qkv[(size_t)(bi * SEQ + s) * NQKV + VOFF + kh * HD + d0 + tx];
        t[ty + j * 8][tx] = v;
        vout[((size_t)bz * SEQ + s) * HD + d0 + tx] = v;   // fp32 (b,KV,s,D)
    }
    __syncthreads();
#pragma unroll
    for (int j = 0; j < 4; j++) {
        int d = d0 + ty + j * 8;
        size_t idx = ((size_t)bz * HD + d) * SEQ + s0 + tx;
        vf[idx] = __float2half_rn(t[tx][ty + j * 8]);
    }
}

// ---------------------------------------------------------------------------
// Tensor-core causal flash attention, all single fp16 (1 MMA per fragment).
// BM=128, BN=64, 256 threads, 2 CTAs/SM; K/V double-buffered via cp.async.
// ---------------------------------------------------------------------------
constexpr int FQP = 136;  // pitch (fp16) for Q/K tiles
constexpr int FVP = 72;   // pitch (fp16) for Vt tiles
constexpr int FKV = 64 * FQP + 128 * FVP;            // KV stage elems (17920)
constexpr int FLASH_SMEM = (128 * FQP + 2 * FKV) * 2;  // 106496 B

__global__ __launch_bounds__(256, 2) void flash_mma(
    const __half* __restrict__ Qf,
    const __half* __restrict__ Kf, const __half* __restrict__ Vf,
    __half* __restrict__ Oa)
{
    extern __shared__ __half sm[];
    __half* sQ  = sm;
    __half* sKV = sQ + 128 * FQP;    // 2 stages of [K | V]

    const int qtile = blockIdx.x;
    const int h     = blockIdx.y;
    const int bi    = blockIdx.z;
    const int kh    = h / GQ;
    const int tid   = threadIdx.x;
    const int lane  = tid & 31;
    const int wid   = tid >> 5;
    const int grp   = lane >> 2;
    const int tig   = lane & 3;
    const int q0    = qtile * 128;

    const int lrow  = lane & 15;
    const int lcoff = (lane >> 4) * 8;
    const int brow  = (lane & 7) + ((lane >> 4) << 3);
    const int bcoff = ((lane >> 3) & 1) * 8;

    const __half* kg = Kf + (((size_t)bi * NKV + kh) * SEQ) * HD;
    const __half* vg = Vf + (((size_t)bi * NKV + kh) * HD) * SEQ;
    const uint32_t skv = (uint32_t)__cvta_generic_to_shared(sKV);

    int kr[4], kc[4], vr[4], vc[4];
    uint32_t kso[4], vso[4];
#pragma unroll
    for (int j = 0; j < 4; j++) {
        int c = tid + j * 256;
        kr[j] = c >> 4; kc[j] = (c & 15) * 8;
        kso[j] = (uint32_t)(kr[j] * FQP + kc[j]);
        vr[j] = c >> 3; vc[j] = (c & 7) * 8;
        vso[j] = (uint32_t)(vr[j] * FVP + vc[j]);
    }

    auto issue_kv = [&](int s, int k0) {
        const uint32_t st = skv + (uint32_t)(s * FKV) * 2;
#pragma unroll
        for (int j = 0; j < 4; j++) {
            cp16(st + kso[j] * 2,                  kg + (size_t)(k0 + kr[j]) * HD + kc[j]);
            cp16(st + (64 * FQP + vso[j]) * 2,     vg + (size_t)vr[j] * SEQ + k0 + vc[j]);
        }
        CP_COMMIT();
    };

    // Q tile load (128 x 128, single fp16)
    {
        const __half* qg = Qf + (((size_t)bi * NH + h) * SEQ + q0) * HD;
        for (int i = tid; i < 128 * 16; i += 256) {
            int r = i >> 4, c = (i & 15) * 8;
            *(uint4*)&sQ[r * FQP + c] = *(const uint4*)&qg[(size_t)r * HD + c];
        }
    }

    float o[16][4];
#pragma unroll
    for (int nt = 0; nt < 16; nt++)
#pragma unroll
        for (int e = 0; e < 4; e++) o[nt][e] = 0.f;
    float m0 = -1e30f, m1 = -1e30f, l0 = 0.f, l1 = 0.f;

    const int ntiles = 2 * qtile + 2;

    issue_kv(0, 0);   // prologue

    for (int t = 0; t < ntiles; ++t) {
        const int k0 = t * 64;
        const __half* cur = sKV + (size_t)(t & 1) * FKV;
        const __half* sK = cur;
        const __half* sV = cur + 64 * FQP;

        CP_WAIT(0);
        __syncthreads();

        if (t + 1 < ntiles) issue_kv((t + 1) & 1, (t + 1) * 64);

        float s[8][4];
#pragma unroll
        for (int nt = 0; nt < 8; nt++)
#pragma unroll
            for (int e = 0; e < 4; e++) s[nt][e] = 0.f;

#pragma unroll
        for (int kk = 0; kk < 128; kk += 16) {
            uint32_t af[4];
            const int acol = kk + lcoff;
            ldsm4(af, &sQ[(wid * 16 + lrow) * FQP + acol]);
#pragma unroll
            for (int np = 0; np < 4; np++) {
                const int br = np * 16 + brow;
                const int bc = kk + bcoff;
                uint32_t bh[4];
                ldsm4(bh, &sK[br * FQP + bc]);
                mma16816(s[2 * np    ], af, bh);
                mma16816(s[2 * np + 1], af, bh + 2);
            }
        }

        if (t >= ntiles - 2) {   // causal mask (last two tiles span the diagonal)
            const int r0 = q0 + wid * 16 + grp;
#pragma unroll
            for (int nt = 0; nt < 8; nt++) {
                const int c = k0 + nt * 8 + tig * 2;
                if (c     > r0)     s[nt][0] = -1e30f;
                if (c + 1 > r0)     s[nt][1] = -1e30f;
                if (c     > r0 + 8) s[nt][2] = -1e30f;
                if (c + 1 > r0 + 8) s[nt][3] = -1e30f;
            }
        }

        float mx0 = -1e30f, mx1 = -1e30f;
#pragma unroll
        for (int nt = 0; nt < 8; nt++) {
            mx0 = fmaxf(mx0, fmaxf(s[nt][0], s[nt][1]));
            mx1 = fmaxf(mx1, fmaxf(s[nt][2], s[nt][3]));
        }
        mx0 = fmaxf(mx0, __shfl_xor_sync(0xffffffffu, mx0, 1));
        mx0 = fmaxf(mx0, __shfl_xor_sync(0xffffffffu, mx0, 2));
        mx1 = fmaxf(mx1, __shfl_xor_sync(0xffffffffu, mx1, 1));
        mx1 = fmaxf(mx1, __shfl_xor_sync(0xffffffffu, mx1, 2));

        const float nm0 = fmaxf(m0, mx0);
        const float nm1 = fmaxf(m1, mx1);
        const float a0 = __expf(m0 - nm0);
        const float a1 = __expf(m1 - nm1);
        m0 = nm0; m1 = nm1;

        float rs0 = 0.f, rs1 = 0.f;
#pragma unroll
        for (int nt = 0; nt < 8; nt++) {
            s[nt][0] = __expf(s[nt][0] - m0);
            s[nt][1] = __expf(s[nt][1] - m0);
            s[nt][2] = __expf(s[nt][2] - m1);
            s[nt][3] = __expf(s[nt][3] - m1);
            rs0 += s[nt][0] + s[nt][1];
            rs1 += s[nt][2] + s[nt][3];
        }
        rs0 += __shfl_xor_sync(0xffffffffu, rs0, 1);
        rs0 += __shfl_xor_sync(0xffffffffu, rs0, 2);
        rs1 += __shfl_xor_sync(0xffffffffu, rs1, 1);
        rs1 += __shfl_xor_sync(0xffffffffu, rs1, 2);
        l0 = l0 * a0 + rs0;
        l1 = l1 * a1 + rs1;

#pragma unroll
        for (int nt = 0; nt < 16; nt++) {
            o[nt][0] *= a0; o[nt][1] *= a0;
            o[nt][2] *= a1; o[nt][3] *= a1;
        }

        // O += P @ V  (P single fp16)
#pragma unroll
        for (int ks = 0; ks < 4; ks++) {
            uint32_t ph[4];
            ph[0] = pack2f16(s[2 * ks][0],     s[2 * ks][1]);
            ph[1] = pack2f16(s[2 * ks][2],     s[2 * ks][3]);
            ph[2] = pack2f16(s[2 * ks + 1][0], s[2 * ks + 1][1]);
            ph[3] = pack2f16(s[2 * ks + 1][2], s[2 * ks + 1][3]);
            const int bc = ks * 16 + bcoff;
#pragma unroll
            for (int np = 0; np < 8; np++) {
                const int br = np * 16 + brow;
                uint32_t vh4[4];
                ldsm4(vh4, &sV[br * FVP + bc]);
                mma16816(o[2 * np    ], ph, vh4);
                mma16816(o[2 * np + 1], ph, vh4 + 2);
            }
        }
    }

    // epilogue: normalize and write single fp16 (b*s, H*D)
    const float i0 = 1.0f / l0;
    const float i1 = 1.0f / l1;
    const size_t row0 = (size_t)bi * SEQ + q0 + wid * 16 + grp;
    const size_t row1 = row0 + 8;
    const int colb = h * HD + tig * 2;
#pragma unroll
    for (int nt = 0; nt < 16; nt++) {
        *(uint32_t*)&Oa[row0 * (NH * HD) + colb + nt * 8] =
            pack2f16(o[nt][0] * i0, o[nt][1] * i0);
        *(uint32_t*)&Oa[row1 * (NH * HD) + colb + nt * 8] =
            pack2f16(o[nt][2] * i1, o[nt][3] * i1);
    }
}

// ---------------------------------------------------------------------------
// kernel_launch
// ---------------------------------------------------------------------------
extern "C" void kernel_launch(void* const* d_in, const int* in_sizes, int n_in,
                              void* d_out, int out_size)
{
    const float* hidden = (const float*)d_in[0];
    const float* cosb   = (const float*)d_in[1];
    const float* sinb   = (const float*)d_in[2];
    const float* wq     = (const float*)d_in[3];
    const float* wk     = (const float*)d_in[4];
    const float* wv     = (const float*)d_in[5];
    const float* wo     = (const float*)d_in[6];
    const float* qg     = (const float*)d_in[7];
    const float* kg     = (const float*)d_in[8];

    float* out  = (float*)d_out;
    float* kout = out  + (size_t)NB * SEQ * HDIM;
    float* vout = kout + (size_t)NB * NKV * SEQ * HD;

    __half *hidh, *hidl, *wqkvf, *wof, *ao, *qf, *kf, *vf;
    float *qkv;
    cudaGetSymbolAddress((void**)&hidh,  g_hid_h);
    cudaGetSymbolAddress((void**)&hidl,  g_hid_l);
    cudaGetSymbolAddress((void**)&wqkvf, g_wqkv);
    cudaGetSymbolAddress((void**)&wof,   g_wo);
    cudaGetSymbolAddress((void**)&ao,    g_ao);
    cudaGetSymbolAddress((void**)&qkv,   g_qkv);
    cudaGetSymbolAddress((void**)&qf,    g_qf);
    cudaGetSymbolAddress((void**)&kf,    g_kf);
    cudaGetSymbolAddress((void**)&vf,    g_vf);

    cudaFuncSetAttribute(flash_mma, cudaFuncAttributeMaxDynamicSharedMemorySize, FLASH_SMEM);
    cudaFuncSetAttribute(gemm_fp16x2, cudaFuncAttributeMaxDynamicSharedMemorySize, GEMM_SMEM);
    cudaFuncSetAttribute(gemm_fp16x1, cudaFuncAttributeMaxDynamicSharedMemorySize, G1_SMEM);

    // fp32 -> fp16 conversions
    const size_t nHid = (size_t)MROWS * HDIM;
    const size_t nWq  = (size_t)NH  * HD * HDIM;
    const size_t nWk  = (size_t)NKV * HD * HDIM;
    split_fp16<<<(int)(nHid / 1024), 256>>>((const float4*)hidden, hidh, hidl);
    conv_fp16<<<(int)(nWq / 1024), 256>>>((const float4*)wq, wqkvf);
    conv_fp16<<<(int)(nWk / 1024), 256>>>((const float4*)wk, wqkvf + nWq);
    conv_fp16<<<(int)(nWk / 1024), 256>>>((const float4*)wv, wqkvf + nWq + nWk);
    conv_fp16<<<(int)(nWq / 1024), 256>>>((const float4*)wo, wof);

    // Fused QKV projection (A hi/lo, B single)
    gemm_fp16x2<<<dim3(NQKV / 128, MROWS / 128), 256, GEMM_SMEM>>>(
        hidh, hidl, wqkvf, qkv, MROWS, NQKV, HDIM);

    // RMSNorm + RoPE -> fp16 operands (+ fp32 K into d_out)
    norm_rope_q<<<(MROWS * NH ) / 8, 256>>>(qkv, qf, cosb, sinb, qg);
    norm_rope_k<<<(MROWS * NKV) / 8, 256>>>(qkv, kout, kf, cosb, sinb, kg);

    // V: fp32 into d_out's new_v AND fp16 transposed, single pass
    vtrans_fused<<<dim3(SEQ / 32, HD / 32, NB * NKV), dim3(32, 8)>>>(qkv, vout, vf);

    // Tensor-core causal GQA flash attention (all single fp16) -> fp16 O
    flash_mma<<<dim3(SEQ / 128, NH, NB), 256, FLASH_SMEM>>>(qf, kf, vf, ao);

    // Output projection (both single fp16, 1 MMA)
    gemm_fp16x1<<<dim3(HDIM / 128, MROWS / 128), 256, G1_SMEM>>>(
        ao, wof, out, MROWS, HDIM, NH * HD);
}

// round 16
// speedup vs baseline: 2.8264x; 1.2508x over previous
#include <cuda_runtime.h>
#include <cuda_fp16.h>
#include <cstdint>

// Problem constants
constexpr int NB   = 2;      // batch
constexpr int SEQ  = 2048;   // sequence
constexpr int HDIM = 2560;   // hidden
constexpr int NH   = 32;     // q heads
constexpr int NKV  = 8;      // kv heads
constexpr int HD   = 128;    // head dim
constexpr int GQ   = NH / NKV;
constexpr int MROWS = NB * SEQ;            // 4096
constexpr int NQKV  = (NH + 2 * NKV) * HD; // 6144
constexpr int KOFF  = NH * HD;             // 4096
constexpr int VOFF  = (NH + NKV) * HD;     // 5120
constexpr float SM_SCALE = 0.08838834764831845f;  // 1/sqrt(128)

// ---------------- device scratch (no allocation allowed) ----------------
__device__ __half g_hid   [(size_t)MROWS * HDIM];       // single fp16
__device__ __half g_wqkv  [(size_t)NQKV * HDIM];        // single fp16
__device__ __half g_wo    [(size_t)HDIM * NH * HD];     // single fp16
__device__ __half g_ao    [(size_t)MROWS * NH * HD];    // attention out, single fp16
__device__ float g_qkv[(size_t)MROWS * NQKV];           // 96MB
// fp16 attention operands
__device__ __half g_qf[(size_t)NB * NH  * SEQ * HD];    // (b,H,s,D), pre-scaled
__device__ __half g_kf[(size_t)NB * NKV * SEQ * HD];    // (b,KV,s,D)
__device__ __half g_vf[(size_t)NB * NKV * HD * SEQ];    // (b,KV,D,s) transposed

// ---------------------------------------------------------------------------
// cp.async / ldmatrix helpers
// ---------------------------------------------------------------------------
__device__ __forceinline__ void cp16(uint32_t smem, const void* gmem)
{
    asm volatile("cp.async.cg.shared.global [%0], [%1], 16;\n" :: "r"(smem), "l"(gmem));
}
#define CP_COMMIT() asm volatile("cp.async.commit_group;\n" ::: "memory")
#define CP_WAIT(n)  asm volatile("cp.async.wait_group %0;\n" :: "n"(n) : "memory")

__device__ __forceinline__ void ldsm4(uint32_t* r, const void* p)
{
    uint32_t a = (uint32_t)__cvta_generic_to_shared(p);
    asm volatile("ldmatrix.sync.aligned.m8n8.x4.shared.b16 {%0,%1,%2,%3}, [%4];"
        : "=r"(r[0]), "=r"(r[1]), "=r"(r[2]), "=r"(r[3]) : "r"(a));
}

// ---------------------------------------------------------------------------
// fp32 -> fp16 single convert
// ---------------------------------------------------------------------------
__global__ __launch_bounds__(256) void conv_fp16(
    const float4* __restrict__ in, __half* __restrict__ out)
{
    const size_t i = (size_t)blockIdx.x * 256 + threadIdx.x;
    float4 x = in[i];
    __half h[4] = {__float2half_rn(x.x), __float2half_rn(x.y),
                   __float2half_rn(x.z), __float2half_rn(x.w)};
    *(uint2*)&out[i * 4] = *(uint2*)h;
}

// ---------------------------------------------------------------------------
// mma.m16n8k16 fp16 wrapper (fp32 accumulate)
// ---------------------------------------------------------------------------
__device__ __forceinline__ void mma16816(float* c, const uint32_t* a, const uint32_t* b)
{
    asm volatile(
        "mma.sync.aligned.m16n8k16.row.col.f32.f16.f16.f32 "
        "{%0,%1,%2,%3}, {%4,%5,%6,%7}, {%8,%9}, {%0,%1,%2,%3};"
        : "+f"(c[0]), "+f"(c[1]), "+f"(c[2]), "+f"(c[3])
        : "r"(a[0]), "r"(a[1]), "r"(a[2]), "r"(a[3]), "r"(b[0]), "r"(b[1]));
}

__device__ __forceinline__ uint32_t pack2f16(float x, float y)
{
    __half2 h2 = __halves2half2(__float2half_rn(x), __float2half_rn(y));
    return *(uint32_t*)&h2;
}

// ---------------------------------------------------------------------------
// plain fp16 GEMM: C = A @ B^T, both single fp16 (1 MMA per fragment).
// BK=32, 2-stage cp.async, one sync/iter, 2 CTAs/SM. Block 128x128.
// ---------------------------------------------------------------------------
constexpr int GPAD = 40;                      // smem row pitch (fp16): 80B, ldsm conflict-free
constexpr int GSTG = 128 * GPAD;              // fp16 per matrix per stage (5120)
constexpr int G1_SMEM = 2 * 2 * GSTG * 2;     // 40960 bytes

__global__ __launch_bounds__(256, 2) void gemm_fp16x1(
    const __half* __restrict__ Af, const __half* __restrict__ Bf,
    float* __restrict__ C, int M, int N, int K)
{
    extern __shared__ __half sb[];

    const int tid = threadIdx.x;
    const int bm = blockIdx.y * 128;
    const int bn = blockIdx.x * 128;
    const int lane = tid & 31;
    const int wid  = tid >> 5;
    const int wm = (wid & 3) * 32;
    const int wn = (wid >> 2) * 64;
    const int grp = lane >> 2;
    const int tig = lane & 3;

    const int lrow  = lane & 15;
    const int lcoff = (lane >> 4) * 8;
    const int brow  = (lane & 7) + ((lane >> 4) << 3);
    const int bcoff = ((lane >> 3) & 1) * 8;

    uint32_t soff[2];
    int grow[2], gcol[2];
#pragma unroll
    for (int j = 0; j < 2; j++) {
        int c = tid + j * 256;
        grow[j] = c >> 2;
        gcol[j] = (c & 3) * 8;
        soff[j] = (uint32_t)(grow[j] * GPAD + gcol[j]);
    }

    float acc[2][8][4];
#pragma unroll
    for (int mt = 0; mt < 2; mt++)
#pragma unroll
        for (int nt = 0; nt < 8; nt++)
#pragma unroll
            for (int e = 0; e < 4; e++) acc[mt][nt][e] = 0.f;

    uint32_t sbase = (uint32_t)__cvta_generic_to_shared(sb);
    const int nk = K / 32;

#pragma unroll
    for (int j = 0; j < 2; j++) {
        cp16(sbase + (0 * GSTG + soff[j]) * 2, Af + (size_t)(bm + grow[j]) * K + gcol[j]);
        cp16(sbase + (1 * GSTG + soff[j]) * 2, Bf + (size_t)(bn + grow[j]) * K + gcol[j]);
    }
    CP_COMMIT();

    for (int i = 0; i < nk; i++) {
        const __half* cur = sb + (size_t)(i & 1) * 2 * GSTG;

        CP_WAIT(0);
        __syncthreads();

        if (i + 1 < nk) {
            const uint32_t nxt = sbase + (uint32_t)(((i + 1) & 1) * 2 * GSTG) * 2;
            const int k0 = (i + 1) * 32;
#pragma unroll
            for (int j = 0; j < 2; j++) {
                cp16(nxt + (0 * GSTG + soff[j]) * 2, Af + (size_t)(bm + grow[j]) * K + k0 + gcol[j]);
                cp16(nxt + (1 * GSTG + soff[j]) * 2, Bf + (size_t)(bn + grow[j]) * K + k0 + gcol[j]);
            }
            CP_COMMIT();
        }

        const __half* sA = cur;
        const __half* sB = cur + GSTG;

#pragma unroll
        for (int kk = 0; kk < 32; kk += 16) {
            uint32_t af[2][4];
            const int acol = kk + lcoff;
            ldsm4(af[0], &sA[(wm + lrow     ) * GPAD + acol]);
            ldsm4(af[1], &sA[(wm + 16 + lrow) * GPAD + acol]);
#pragma unroll
            for (int np = 0; np < 4; np++) {
                const int br = wn + np * 16 + brow;
                const int bc = kk + bcoff;
                uint32_t bh[4];
                ldsm4(bh, &sB[br * GPAD + bc]);
                mma16816(acc[0][2 * np    ], af[0], bh);
                mma16816(acc[1][2 * np    ], af[1], bh);
                mma16816(acc[0][2 * np + 1], af[0], bh + 2);
                mma16816(acc[1][2 * np + 1], af[1], bh + 2);
            }
        }
    }

#pragma unroll
    for (int mt = 0; mt < 2; mt++) {
        const int row = bm + wm + mt * 16 + grp;
#pragma unroll
        for (int nt = 0; nt < 8; nt++) {
            const int col = bn + wn + nt * 8 + tig * 2;
            *(float2*)&C[(size_t)row * N + col]       = make_float2(acc[mt][nt][0], acc[mt][nt][1]);
            *(float2*)&C[(size_t)(row + 8) * N + col] = make_float2(acc[mt][nt][2], acc[mt][nt][3]);
        }
    }
}

// ---------------------------------------------------------------------------
// RMSNorm + RoPE for Q: reads qkv fp32, writes single fp16 to (b,H,s,D),
// pre-scaled by 1/sqrt(D). One warp per row.
// ---------------------------------------------------------------------------
__global__ __launch_bounds__(256) void norm_rope_q(
    const float* __restrict__ qkv, __half* __restrict__ of,
    const float* __restrict__ cs, const float* __restrict__ sn,
    const float* __restrict__ gamma)
{
    const int warp = (blockIdx.x * 256 + threadIdx.x) >> 5;
    const int lane = threadIdx.x & 31;
    const int h  = warp % NH;
    const int bs = warp / NH;
    const int sp = bs % SEQ;
    const int bi = bs / SEQ;

    const float* x = qkv + (size_t)bs * NQKV + h * HD;
    float e0 = x[lane], e1 = x[lane + 32], e2 = x[lane + 64], e3 = x[lane + 96];

    float ssq = e0 * e0 + e1 * e1 + e2 * e2 + e3 * e3;
#pragma unroll
    for (int o = 16; o; o >>= 1) ssq += __shfl_xor_sync(0xffffffffu, ssq, o);
    const float r = rsqrtf(ssq * (1.0f / HD) + 1e-6f);

    e0 *= r * gamma[lane];      e1 *= r * gamma[lane + 32];
    e2 *= r * gamma[lane + 64]; e3 *= r * gamma[lane + 96];

    const float* cp = cs + (size_t)bs * HD;
    const float* sg = sn + (size_t)bs * HD;
    float o4[4];
    o4[0] = (e0 * cp[lane]      - e2 * sg[lane])      * SM_SCALE;
    o4[1] = (e1 * cp[lane + 32] - e3 * sg[lane + 32]) * SM_SCALE;
    o4[2] = (e2 * cp[lane + 64] + e0 * sg[lane + 64]) * SM_SCALE;
    o4[3] = (e3 * cp[lane + 96] + e1 * sg[lane + 96]) * SM_SCALE;

    const size_t ob = (((size_t)bi * NH + h) * SEQ + sp) * HD;
#pragma unroll
    for (int j = 0; j < 4; j++)
        of[ob + lane + 32 * j] = __float2half_rn(o4[j]);
}

// ---------------------------------------------------------------------------
// RMSNorm + RoPE for K: writes fp32 (b,KV,s,D) into d_out AND single fp16.
// ---------------------------------------------------------------------------
__global__ __launch_bounds__(256) void norm_rope_k(
    const float* __restrict__ qkv, float* __restrict__ kout,
    __half* __restrict__ of,
    const float* __restrict__ cs, const float* __restrict__ sn,
    const float* __restrict__ gamma)
{
    const int warp = (blockIdx.x * 256 + threadIdx.x) >> 5;
    const int lane = threadIdx.x & 31;
    const int h  = warp % NKV;
    const int bs = warp / NKV;
    const int sp = bs % SEQ;
    const int bi = bs / SEQ;

    const float* x = qkv + (size_t)bs * NQKV + KOFF + h * HD;
    float e0 = x[lane], e1 = x[lane + 32], e2 = x[lane + 64], e3 = x[lane + 96];

    float ssq = e0 * e0 + e1 * e1 + e2 * e2 + e3 * e3;
#pragma unroll
    for (int o = 16; o; o >>= 1) ssq += __shfl_xor_sync(0xffffffffu, ssq, o);
    const float r = rsqrtf(ssq * (1.0f / HD) + 1e-6f);

    e0 *= r * gamma[lane];      e1 *= r * gamma[lane + 32];
    e2 *= r * gamma[lane + 64]; e3 *= r * gamma[lane + 96];

    const float* cp = cs + (size_t)bs * HD;
    const float* sg = sn + (size_t)bs * HD;
    float o4[4];
    o4[0] = e0 * cp[lane]      - e2 * sg[lane];
    o4[1] = e1 * cp[lane + 32] - e3 * sg[lane + 32];
    o4[2] = e2 * cp[lane + 64] + e0 * sg[lane + 64];
    o4[3] = e3 * cp[lane + 96] + e1 * sg[lane + 96];

    const size_t ob = (((size_t)bi * NKV + h) * SEQ + sp) * HD;
#pragma unroll
    for (int j = 0; j < 4; j++) {
        kout[ob + lane + 32 * j] = o4[j];
        of[ob + lane + 32 * j] = __float2half_rn(o4[j]);
    }
}

// ---------------------------------------------------------------------------
// V: one pass. Reads qkv V region, writes fp32 (b,KV,s,D) to d_out AND
// fp16 transposed (b,KV,D,s).
// ---------------------------------------------------------------------------
__global__ void vtrans_fused(
    const float* __restrict__ qkv, float* __restrict__ vout,
    __half* __restrict__ vf)
{
    __shared__ float t[32][33];
    const int s0 = blockIdx.x * 32, d0 = blockIdx.y * 32;
    const int bz = blockIdx.z;                 // bi*NKV + kh
    const int bi = bz / NKV, kh = bz % NKV;
    const int tx = threadIdx.x, ty = threadIdx.y;

#pragma unroll
    for (int j = 0; j < 4; j++) {
        int s = s0 + ty + j * 8;
        float v = qkv[(size_t)(bi * SEQ + s) * NQKV + VOFF + kh * HD + d0 + tx];
        t[ty + j * 8][tx] = v;
        vout[((size_t)bz * SEQ + s) * HD + d0 + tx] = v;   // fp32 (b,KV,s,D)
    }
    __syncthreads();
#pragma unroll
    for (int j = 0; j < 4; j++) {
        int d = d0 + ty + j * 8;
        size_t idx = ((size_t)bz * HD + d) * SEQ + s0 + tx;
        vf[idx] = __float2half_rn(t[tx][ty + j * 8]);
    }
}

// ---------------------------------------------------------------------------
// Tensor-core causal flash attention, all single fp16 (1 MMA per fragment).
// BM=128, BN=64, 256 threads, 2 CTAs/SM; K/V double-buffered via cp.async.
// ---------------------------------------------------------------------------
constexpr int FQP = 136;  // pitch (fp16) for Q/K tiles
constexpr int FVP = 72;   // pitch (fp16) for Vt tiles
constexpr int FKV = 64 * FQP + 128 * FVP;            // KV stage elems (17920)
constexpr int FLASH_SMEM = (128 * FQP + 2 * FKV) * 2;  // 106496 B

__global__ __launch_bounds__(256, 2) void flash_mma(
    const __half* __restrict__ Qf,
    const __half* __restrict__ Kf, const __half* __restrict__ Vf,
    __half* __restrict__ Oa)
{
    extern __shared__ __half sm[];
    __half* sQ  = sm;
    __half* sKV = sQ + 128 * FQP;    // 2 stages of [K | V]

    const int qtile = blockIdx.x;
    const int h     = blockIdx.y;
    const int bi    = blockIdx.z;
    const int kh    = h / GQ;
    const int tid   = threadIdx.x;
    const int lane  = tid & 31;
    const int wid   = tid >> 5;
    const int grp   = lane >> 2;
    const int tig   = lane & 3;
    const int q0    = qtile * 128;

    const int lrow  = lane & 15;
    const int lcoff = (lane >> 4) * 8;
    const int brow  = (lane & 7) + ((lane >> 4) << 3);
    const int bcoff = ((lane >> 3) & 1) * 8;

    const __half* kg = Kf + (((size_t)bi * NKV + kh) * SEQ) * HD;
    const __half* vg = Vf + (((size_t)bi * NKV + kh) * HD) * SEQ;
    const uint32_t skv = (uint32_t)__cvta_generic_to_shared(sKV);

    int kr[4], kc[4], vr[4], vc[4];
    uint32_t kso[4], vso[4];
#pragma unroll
    for (int j = 0; j < 4; j++) {
        int c = tid + j * 256;
        kr[j] = c >> 4; kc[j] = (c & 15) * 8;
        kso[j] = (uint32_t)(kr[j] * FQP + kc[j]);
        vr[j] = c >> 3; vc[j] = (c & 7) * 8;
        vso[j] = (uint32_t)(vr[j] * FVP + vc[j]);
    }

    auto issue_kv = [&](int s, int k0) {
        const uint32_t st = skv + (uint32_t)(s * FKV) * 2;
#pragma unroll
        for (int j = 0; j < 4; j++) {
            cp16(st + kso[j] * 2,                  kg + (size_t)(k0 + kr[j]) * HD + kc[j]);
            cp16(st + (64 * FQP + vso[j]) * 2,     vg + (size_t)vr[j] * SEQ + k0 + vc[j]);
        }
        CP_COMMIT();
    };

    // Q tile load (128 x 128, single fp16)
    {
        const __half* qg = Qf + (((size_t)bi * NH + h) * SEQ + q0) * HD;
        for (int i = tid; i < 128 * 16; i += 256) {
            int r = i >> 4, c = (i & 15) * 8;
            *(uint4*)&sQ[r * FQP + c] = *(const uint4*)&qg[(size_t)r * HD + c];
        }
    }

    float o[16][4];
#pragma unroll
    for (int nt = 0; nt < 16; nt++)
#pragma unroll
        for (int e = 0; e < 4; e++) o[nt][e] = 0.f;
    float m0 = -1e30f, m1 = -1e30f, l0 = 0.f, l1 = 0.f;

    const int ntiles = 2 * qtile + 2;

    issue_kv(0, 0);   // prologue

    for (int t = 0; t < ntiles; ++t) {
        const int k0 = t * 64;
        const __half* cur = sKV + (size_t)(t & 1) * FKV;
        const __half* sK = cur;
        const __half* sV = cur + 64 * FQP;

        CP_WAIT(0);
        __syncthreads();

        if (t + 1 < ntiles) issue_kv((t + 1) & 1, (t + 1) * 64);

        float s[8][4];
#pragma unroll
        for (int nt = 0; nt < 8; nt++)
#pragma unroll
            for (int e = 0; e < 4; e++) s[nt][e] = 0.f;

#pragma unroll
        for (int kk = 0; kk < 128; kk += 16) {
            uint32_t af[4];
            const int acol = kk + lcoff;
            ldsm4(af, &sQ[(wid * 16 + lrow) * FQP + acol]);
#pragma unroll
            for (int np = 0; np < 4; np++) {
                const int br = np * 16 + brow;
                const int bc = kk + bcoff;
                uint32_t bh[4];
                ldsm4(bh, &sK[br * FQP + bc]);
                mma16816(s[2 * np    ], af, bh);
                mma16816(s[2 * np + 1], af, bh + 2);
            }
        }

        if (t >= ntiles - 2) {   // causal mask (last two tiles span the diagonal)
            const int r0 = q0 + wid * 16 + grp;
#pragma unroll
            for (int nt = 0; nt < 8; nt++) {
                const int c = k0 + nt * 8 + tig * 2;
                if (c     > r0)     s[nt][0] = -1e30f;
                if (c + 1 > r0)     s[nt][1] = -1e30f;
                if (c     > r0 + 8) s[nt][2] = -1e30f;
                if (c + 1 > r0 + 8) s[nt][3] = -1e30f;
            }
        }

        float mx0 = -1e30f, mx1 = -1e30f;
#pragma unroll
        for (int nt = 0; nt < 8; nt++) {
            mx0 = fmaxf(mx0, fmaxf(s[nt][0], s[nt][1]));
            mx1 = fmaxf(mx1, fmaxf(s[nt][2], s[nt][3]));
        }
        mx0 = fmaxf(mx0, __shfl_xor_sync(0xffffffffu, mx0, 1));
        mx0 = fmaxf(mx0, __shfl_xor_sync(0xffffffffu, mx0, 2));
        mx1 = fmaxf(mx1, __shfl_xor_sync(0xffffffffu, mx1, 1));
        mx1 = fmaxf(mx1, __shfl_xor_sync(0xffffffffu, mx1, 2));

        const float nm0 = fmaxf(m0, mx0);
        const float nm1 = fmaxf(m1, mx1);
        const float a0 = __expf(m0 - nm0);
        const float a1 = __expf(m1 - nm1);
        m0 = nm0; m1 = nm1;

        float rs0 = 0.f, rs1 = 0.f;
#pragma unroll
        for (int nt = 0; nt < 8; nt++) {
            s[nt][0] = __expf(s[nt][0] - m0);
            s[nt][1] = __expf(s[nt][1] - m0);
            s[nt][2] = __expf(s[nt][2] - m1);
            s[nt][3] = __expf(s[nt][3] - m1);
            rs0 += s[nt][0] + s[nt][1];
            rs1 += s[nt][2] + s[nt][3];
        }
        rs0 += __shfl_xor_sync(0xffffffffu, rs0, 1);
        rs0 += __shfl_xor_sync(0xffffffffu, rs0, 2);
        rs1 += __shfl_xor_sync(0xffffffffu, rs1, 1);
        rs1 += __shfl_xor_sync(0xffffffffu, rs1, 2);
        l0 = l0 * a0 + rs0;
        l1 = l1 * a1 + rs1;

#pragma unroll
        for (int nt = 0; nt < 16; nt++) {
            o[nt][0] *= a0; o[nt][1] *= a0;
            o[nt][2] *= a1; o[nt][3] *= a1;
        }

        // O += P @ V  (P single fp16)
#pragma unroll
        for (int ks = 0; ks < 4; ks++) {
            uint32_t ph[4];
            ph[0] = pack2f16(s[2 * ks][0],     s[2 * ks][1]);
            ph[1] = pack2f16(s[2 * ks][2],     s[2 * ks][3]);
            ph[2] = pack2f16(s[2 * ks + 1][0], s[2 * ks + 1][1]);
            ph[3] = pack2f16(s[2 * ks + 1][2], s[2 * ks + 1][3]);
            const int bc = ks * 16 + bcoff;
#pragma unroll
            for (int np = 0; np < 8; np++) {
                const int br = np * 16 + brow;
                uint32_t vh4[4];
                ldsm4(vh4, &sV[br * FVP + bc]);
                mma16816(o[2 * np    ], ph, vh4);
                mma16816(o[2 * np + 1], ph, vh4 + 2);
            }
        }
    }

    // epilogue: normalize and write single fp16 (b*s, H*D)
    const float i0 = 1.0f / l0;
    const float i1 = 1.0f / l1;
    const size_t row0 = (size_t)bi * SEQ + q0 + wid * 16 + grp;
    const size_t row1 = row0 + 8;
    const int colb = h * HD + tig * 2;
#pragma unroll
    for (int nt = 0; nt < 16; nt++) {
        *(uint32_t*)&Oa[row0 * (NH * HD) + colb + nt * 8] =
            pack2f16(o[nt][0] * i0, o[nt][1] * i0);
        *(uint32_t*)&Oa[row1 * (NH * HD) + colb + nt * 8] =
            pack2f16(o[nt][2] * i1, o[nt][3] * i1);
    }
}

// ---------------------------------------------------------------------------
// kernel_launch
// ---------------------------------------------------------------------------
extern "C" void kernel_launch(void* const* d_in, const int* in_sizes, int n_in,
                              void* d_out, int out_size)
{
    const float* hidden = (const float*)d_in[0];
    const float* cosb   = (const float*)d_in[1];
    const float* sinb   = (const float*)d_in[2];
    const float* wq     = (const float*)d_in[3];
    const float* wk     = (const float*)d_in[4];
    const float* wv     = (const float*)d_in[5];
    const float* wo     = (const float*)d_in[6];
    const float* qg     = (const float*)d_in[7];
    const float* kg     = (const float*)d_in[8];

    float* out  = (float*)d_out;
    float* kout = out  + (size_t)NB * SEQ * HDIM;
    float* vout = kout + (size_t)NB * NKV * SEQ * HD;

    __half *hidf, *wqkvf, *wof, *ao, *qf, *kf, *vf;
    float *qkv;
    cudaGetSymbolAddress((void**)&hidf,  g_hid);
    cudaGetSymbolAddress((void**)&wqkvf, g_wqkv);
    cudaGetSymbolAddress((void**)&wof,   g_wo);
    cudaGetSymbolAddress((void**)&ao,    g_ao);
    cudaGetSymbolAddress((void**)&qkv,   g_qkv);
    cudaGetSymbolAddress((void**)&qf,    g_qf);
    cudaGetSymbolAddress((void**)&kf,    g_kf);
    cudaGetSymbolAddress((void**)&vf,    g_vf);

    cudaFuncSetAttribute(flash_mma, cudaFuncAttributeMaxDynamicSharedMemorySize, FLASH_SMEM);
    cudaFuncSetAttribute(gemm_fp16x1, cudaFuncAttributeMaxDynamicSharedMemorySize, G1_SMEM);

    // fp32 -> fp16 conversions
    const size_t nHid = (size_t)MROWS * HDIM;
    const size_t nWq  = (size_t)NH  * HD * HDIM;
    const size_t nWk  = (size_t)NKV * HD * HDIM;
    conv_fp16<<<(int)(nHid / 1024), 256>>>((const float4*)hidden, hidf);
    conv_fp16<<<(int)(nWq / 1024), 256>>>((const float4*)wq, wqkvf);
    conv_fp16<<<(int)(nWk / 1024), 256>>>((const float4*)wk, wqkvf + nWq);
    conv_fp16<<<(int)(nWk / 1024), 256>>>((const float4*)wv, wqkvf + nWq + nWk);
    conv_fp16<<<(int)(nWq / 1024), 256>>>((const float4*)wo, wof);

    // Fused QKV projection (single fp16, 1 MMA)
    gemm_fp16x1<<<dim3(NQKV / 128, MROWS / 128), 256, G1_SMEM>>>(
        hidf, wqkvf, qkv, MROWS, NQKV, HDIM);

    // RMSNorm + RoPE -> fp16 operands (+ fp32 K into d_out)
    norm_rope_q<<<(MROWS * NH ) / 8, 256>>>(qkv, qf, cosb, sinb, qg);
    norm_rope_k<<<(MROWS * NKV) / 8, 256>>>(qkv, kout, kf, cosb, sinb, kg);

    // V: fp32 into d_out's new_v AND fp16 transposed, single pass
    vtrans_fused<<<dim3(SEQ / 32, HD / 32, NB * NKV), dim3(32, 8)>>>(qkv, vout, vf);

    // Tensor-core causal GQA flash attention (all single fp16) -> fp16 O
    flash_mma<<<dim3(SEQ / 128, NH, NB), 256, FLASH_SMEM>>>(qf, kf, vf, ao);

    // Output projection (both single fp16, 1 MMA)
    gemm_fp16x1<<<dim3(HDIM / 128, MROWS / 128), 256, G1_SMEM>>>(
        ao, wof, out, MROWS, HDIM, NH * HD);
}

// round 17
// speedup vs baseline: 2.8391x; 1.0045x over previous
#include <cuda_runtime.h>
#include <cuda_fp16.h>
#include <cstdint>

// Problem constants
constexpr int NB   = 2;      // batch
constexpr int SEQ  = 2048;   // sequence
constexpr int HDIM = 2560;   // hidden
constexpr int NH   = 32;     // q heads
constexpr int NKV  = 8;      // kv heads
constexpr int HD   = 128;    // head dim
constexpr int GQ   = NH / NKV;
constexpr int MROWS = NB * SEQ;            // 4096
constexpr int NQKV  = (NH + 2 * NKV) * HD; // 6144
constexpr int KOFF  = NH * HD;             // 4096
constexpr int VOFF  = (NH + NKV) * HD;     // 5120
constexpr float SM_SCALE = 0.08838834764831845f;  // 1/sqrt(128)

// ---------------- device scratch (no allocation allowed) ----------------
__device__ __half g_hid   [(size_t)MROWS * HDIM];       // single fp16
__device__ __half g_wqkv  [(size_t)NQKV * HDIM];        // single fp16
__device__ __half g_wo    [(size_t)HDIM * NH * HD];     // single fp16
__device__ __half g_ao    [(size_t)MROWS * NH * HD];    // attention out, single fp16
__device__ __half g_qkv   [(size_t)MROWS * NQKV];       // qkv intermediate, fp16 (48MB)
// fp16 attention operands
__device__ __half g_qf[(size_t)NB * NH  * SEQ * HD];    // (b,H,s,D), pre-scaled
__device__ __half g_kf[(size_t)NB * NKV * SEQ * HD];    // (b,KV,s,D)
__device__ __half g_vf[(size_t)NB * NKV * HD * SEQ];    // (b,KV,D,s) transposed

// ---------------------------------------------------------------------------
// cp.async / ldmatrix helpers
// ---------------------------------------------------------------------------
__device__ __forceinline__ void cp16(uint32_t smem, const void* gmem)
{
    asm volatile("cp.async.cg.shared.global [%0], [%1], 16;\n" :: "r"(smem), "l"(gmem));
}
#define CP_COMMIT() asm volatile("cp.async.commit_group;\n" ::: "memory")
#define CP_WAIT(n)  asm volatile("cp.async.wait_group %0;\n" :: "n"(n) : "memory")

__device__ __forceinline__ void ldsm4(uint32_t* r, const void* p)
{
    uint32_t a = (uint32_t)__cvta_generic_to_shared(p);
    asm volatile("ldmatrix.sync.aligned.m8n8.x4.shared.b16 {%0,%1,%2,%3}, [%4];"
        : "=r"(r[0]), "=r"(r[1]), "=r"(r[2]), "=r"(r[3]) : "r"(a));
}

// ---------------------------------------------------------------------------
// fp32 -> fp16 single convert
// ---------------------------------------------------------------------------
__global__ __launch_bounds__(256) void conv_fp16(
    const float4* __restrict__ in, __half* __restrict__ out)
{
    const size_t i = (size_t)blockIdx.x * 256 + threadIdx.x;
    float4 x = in[i];
    __half h[4] = {__float2half_rn(x.x), __float2half_rn(x.y),
                   __float2half_rn(x.z), __float2half_rn(x.w)};
    *(uint2*)&out[i * 4] = *(uint2*)h;
}

// ---------------------------------------------------------------------------
// mma.m16n8k16 fp16 wrapper (fp32 accumulate)
// ---------------------------------------------------------------------------
__device__ __forceinline__ void mma16816(float* c, const uint32_t* a, const uint32_t* b)
{
    asm volatile(
        "mma.sync.aligned.m16n8k16.row.col.f32.f16.f16.f32 "
        "{%0,%1,%2,%3}, {%4,%5,%6,%7}, {%8,%9}, {%0,%1,%2,%3};"
        : "+f"(c[0]), "+f"(c[1]), "+f"(c[2]), "+f"(c[3])
        : "r"(a[0]), "r"(a[1]), "r"(a[2]), "r"(a[3]), "r"(b[0]), "r"(b[1]));
}

__device__ __forceinline__ uint32_t pack2f16(float x, float y)
{
    __half2 h2 = __halves2half2(__float2half_rn(x), __float2half_rn(y));
    return *(uint32_t*)&h2;
}

// typed 2-element store (fp32 pair or packed fp16 pair)
__device__ __forceinline__ void store2(float* p, float a, float b)
{
    *(float2*)p = make_float2(a, b);
}
__device__ __forceinline__ void store2(__half* p, float a, float b)
{
    *(uint32_t*)p = pack2f16(a, b);
}

// ---------------------------------------------------------------------------
// plain fp16 GEMM: C = A @ B^T, both single fp16 (1 MMA per fragment).
// BK=32, 2-stage cp.async, one sync/iter, 2 CTAs/SM. Block 128x128.
// Output type templated: fp32 (final out) or fp16 (qkv intermediate).
// ---------------------------------------------------------------------------
constexpr int GPAD = 40;                      // smem row pitch (fp16): 80B, ldsm conflict-free
constexpr int GSTG = 128 * GPAD;              // fp16 per matrix per stage (5120)
constexpr int G1_SMEM = 2 * 2 * GSTG * 2;     // 40960 bytes

template <typename OutT>
__global__ __launch_bounds__(256, 2) void gemm_fp16x1(
    const __half* __restrict__ Af, const __half* __restrict__ Bf,
    OutT* __restrict__ C, int M, int N, int K)
{
    extern __shared__ __half sb[];

    const int tid = threadIdx.x;
    const int bm = blockIdx.y * 128;
    const int bn = blockIdx.x * 128;
    const int lane = tid & 31;
    const int wid  = tid >> 5;
    const int wm = (wid & 3) * 32;
    const int wn = (wid >> 2) * 64;
    const int grp = lane >> 2;
    const int tig = lane & 3;

    const int lrow  = lane & 15;
    const int lcoff = (lane >> 4) * 8;
    const int brow  = (lane & 7) + ((lane >> 4) << 3);
    const int bcoff = ((lane >> 3) & 1) * 8;

    uint32_t soff[2];
    int grow[2], gcol[2];
#pragma unroll
    for (int j = 0; j < 2; j++) {
        int c = tid + j * 256;
        grow[j] = c >> 2;
        gcol[j] = (c & 3) * 8;
        soff[j] = (uint32_t)(grow[j] * GPAD + gcol[j]);
    }

    float acc[2][8][4];
#pragma unroll
    for (int mt = 0; mt < 2; mt++)
#pragma unroll
        for (int nt = 0; nt < 8; nt++)
#pragma unroll
            for (int e = 0; e < 4; e++) acc[mt][nt][e] = 0.f;

    uint32_t sbase = (uint32_t)__cvta_generic_to_shared(sb);
    const int nk = K / 32;

#pragma unroll
    for (int j = 0; j < 2; j++) {
        cp16(sbase + (0 * GSTG + soff[j]) * 2, Af + (size_t)(bm + grow[j]) * K + gcol[j]);
        cp16(sbase + (1 * GSTG + soff[j]) * 2, Bf + (size_t)(bn + grow[j]) * K + gcol[j]);
    }
    CP_COMMIT();

    for (int i = 0; i < nk; i++) {
        const __half* cur = sb + (size_t)(i & 1) * 2 * GSTG;

        CP_WAIT(0);
        __syncthreads();

        if (i + 1 < nk) {
            const uint32_t nxt = sbase + (uint32_t)(((i + 1) & 1) * 2 * GSTG) * 2;
            const int k0 = (i + 1) * 32;
#pragma unroll
            for (int j = 0; j < 2; j++) {
                cp16(nxt + (0 * GSTG + soff[j]) * 2, Af + (size_t)(bm + grow[j]) * K + k0 + gcol[j]);
                cp16(nxt + (1 * GSTG + soff[j]) * 2, Bf + (size_t)(bn + grow[j]) * K + k0 + gcol[j]);
            }
            CP_COMMIT();
        }

        const __half* sA = cur;
        const __half* sB = cur + GSTG;

#pragma unroll
        for (int kk = 0; kk < 32; kk += 16) {
            uint32_t af[2][4];
            const int acol = kk + lcoff;
            ldsm4(af[0], &sA[(wm + lrow     ) * GPAD + acol]);
            ldsm4(af[1], &sA[(wm + 16 + lrow) * GPAD + acol]);
#pragma unroll
            for (int np = 0; np < 4; np++) {
                const int br = wn + np * 16 + brow;
                const int bc = kk + bcoff;
                uint32_t bh[4];
                ldsm4(bh, &sB[br * GPAD + bc]);
                mma16816(acc[0][2 * np    ], af[0], bh);
                mma16816(acc[1][2 * np    ], af[1], bh);
                mma16816(acc[0][2 * np + 1], af[0], bh + 2);
                mma16816(acc[1][2 * np + 1], af[1], bh + 2);
            }
        }
    }

#pragma unroll
    for (int mt = 0; mt < 2; mt++) {
        const int row = bm + wm + mt * 16 + grp;
#pragma unroll
        for (int nt = 0; nt < 8; nt++) {
            const int col = bn + wn + nt * 8 + tig * 2;
            store2(&C[(size_t)row * N + col],       acc[mt][nt][0], acc[mt][nt][1]);
            store2(&C[(size_t)(row + 8) * N + col], acc[mt][nt][2], acc[mt][nt][3]);
        }
    }
}

// ---------------------------------------------------------------------------
// RMSNorm + RoPE for Q: reads qkv fp16, writes single fp16 to (b,H,s,D),
// pre-scaled by 1/sqrt(D). One warp per row.
// ---------------------------------------------------------------------------
__global__ __launch_bounds__(256) void norm_rope_q(
    const __half* __restrict__ qkv, __half* __restrict__ of,
    const float* __restrict__ cs, const float* __restrict__ sn,
    const float* __restrict__ gamma)
{
    const int warp = (blockIdx.x * 256 + threadIdx.x) >> 5;
    const int lane = threadIdx.x & 31;
    const int h  = warp % NH;
    const int bs = warp / NH;

    const __half* x = qkv + (size_t)bs * NQKV + h * HD;
    float e0 = __half2float(x[lane]);
    float e1 = __half2float(x[lane + 32]);
    float e2 = __half2float(x[lane + 64]);
    float e3 = __half2float(x[lane + 96]);

    float ssq = e0 * e0 + e1 * e1 + e2 * e2 + e3 * e3;
#pragma unroll
    for (int o = 16; o; o >>= 1) ssq += __shfl_xor_sync(0xffffffffu, ssq, o);
    const float r = rsqrtf(ssq * (1.0f / HD) + 1e-6f);

    e0 *= r * gamma[lane];      e1 *= r * gamma[lane + 32];
    e2 *= r * gamma[lane + 64]; e3 *= r * gamma[lane + 96];

    const float* cp = cs + (size_t)bs * HD;
    const float* sg = sn + (size_t)bs * HD;
    float o4[4];
    o4[0] = (e0 * cp[lane]      - e2 * sg[lane])      * SM_SCALE;
    o4[1] = (e1 * cp[lane + 32] - e3 * sg[lane + 32]) * SM_SCALE;
    o4[2] = (e2 * cp[lane + 64] + e0 * sg[lane + 64]) * SM_SCALE;
    o4[3] = (e3 * cp[lane + 96] + e1 * sg[lane + 96]) * SM_SCALE;

    const int sp = bs % SEQ;
    const int bi = bs / SEQ;
    const size_t ob = (((size_t)bi * NH + h) * SEQ + sp) * HD;
#pragma unroll
    for (int j = 0; j < 4; j++)
        of[ob + lane + 32 * j] = __float2half_rn(o4[j]);
}

// ---------------------------------------------------------------------------
// RMSNorm + RoPE for K: writes fp32 (b,KV,s,D) into d_out AND single fp16.
// ---------------------------------------------------------------------------
__global__ __launch_bounds__(256) void norm_rope_k(
    const __half* __restrict__ qkv, float* __restrict__ kout,
    __half* __restrict__ of,
    const float* __restrict__ cs, const float* __restrict__ sn,
    const float* __restrict__ gamma)
{
    const int warp = (blockIdx.x * 256 + threadIdx.x) >> 5;
    const int lane = threadIdx.x & 31;
    const int h  = warp % NKV;
    const int bs = warp / NKV;

    const __half* x = qkv + (size_t)bs * NQKV + KOFF + h * HD;
    float e0 = __half2float(x[lane]);
    float e1 = __half2float(x[lane + 32]);
    float e2 = __half2float(x[lane + 64]);
    float e3 = __half2float(x[lane + 96]);

    float ssq = e0 * e0 + e1 * e1 + e2 * e2 + e3 * e3;
#pragma unroll
    for (int o = 16; o; o >>= 1) ssq += __shfl_xor_sync(0xffffffffu, ssq, o);
    const float r = rsqrtf(ssq * (1.0f / HD) + 1e-6f);

    e0 *= r * gamma[lane];      e1 *= r * gamma[lane + 32];
    e2 *= r * gamma[lane + 64]; e3 *= r * gamma[lane + 96];

    const float* cp = cs + (size_t)bs * HD;
    const float* sg = sn + (size_t)bs * HD;
    float o4[4];
    o4[0] = e0 * cp[lane]      - e2 * sg[lane];
    o4[1] = e1 * cp[lane + 32] - e3 * sg[lane + 32];
    o4[2] = e2 * cp[lane + 64] + e0 * sg[lane + 64];
    o4[3] = e3 * cp[lane + 96] + e1 * sg[lane + 96];

    const int sp = bs % SEQ;
    const int bi = bs / SEQ;
    const size_t ob = (((size_t)bi * NKV + h) * SEQ + sp) * HD;
#pragma unroll
    for (int j = 0; j < 4; j++) {
        kout[ob + lane + 32 * j] = o4[j];
        of[ob + lane + 32 * j] = __float2half_rn(o4[j]);
    }
}

// ---------------------------------------------------------------------------
// V: one pass. Reads qkv V region (fp16), writes fp32 (b,KV,s,D) to d_out
// AND fp16 transposed (b,KV,D,s).
// ---------------------------------------------------------------------------
__global__ void vtrans_fused(
    const __half* __restrict__ qkv, float* __restrict__ vout,
    __half* __restrict__ vf)
{
    __shared__ __half t[32][33];
    const int s0 = blockIdx.x * 32, d0 = blockIdx.y * 32;
    const int bz = blockIdx.z;                 // bi*NKV + kh
    const int bi = bz / NKV, kh = bz % NKV;
    const int tx = threadIdx.x, ty = threadIdx.y;

#pragma unroll
    for (int j = 0; j < 4; j++) {
        int s = s0 + ty + j * 8;
        __half v = qkv[(size_t)(bi * SEQ + s) * NQKV + VOFF + kh * HD + d0 + tx];
        t[ty + j * 8][tx] = v;
        vout[((size_t)bz * SEQ + s) * HD + d0 + tx] = __half2float(v);
    }
    __syncthreads();
#pragma unroll
    for (int j = 0; j < 4; j++) {
        int d = d0 + ty + j * 8;
        size_t idx = ((size_t)bz * HD + d) * SEQ + s0 + tx;
        vf[idx] = t[tx][ty + j * 8];
    }
}

// ---------------------------------------------------------------------------
// Tensor-core causal flash attention, all single fp16 (1 MMA per fragment).
// BM=128, BN=64, 256 threads, 2 CTAs/SM; K/V double-buffered via cp.async.
// Heaviest q-tiles scheduled first (reversed blockIdx.x) for tail packing.
// ---------------------------------------------------------------------------
constexpr int FQP = 136;  // pitch (fp16) for Q/K tiles
constexpr int FVP = 72;   // pitch (fp16) for Vt tiles
constexpr int FKV = 64 * FQP + 128 * FVP;            // KV stage elems (17920)
constexpr int FLASH_SMEM = (128 * FQP + 2 * FKV) * 2;  // 106496 B

__global__ __launch_bounds__(256, 2) void flash_mma(
    const __half* __restrict__ Qf,
    const __half* __restrict__ Kf, const __half* __restrict__ Vf,
    __half* __restrict__ Oa)
{
    extern __shared__ __half sm[];
    __half* sQ  = sm;
    __half* sKV = sQ + 128 * FQP;    // 2 stages of [K | V]

    const int qtile = gridDim.x - 1 - blockIdx.x;   // heavy tiles first
    const int h     = blockIdx.y;
    const int bi    = blockIdx.z;
    const int kh    = h / GQ;
    const int tid   = threadIdx.x;
    const int lane  = tid & 31;
    const int wid   = tid >> 5;
    const int grp   = lane >> 2;
    const int tig   = lane & 3;
    const int q0    = qtile * 128;

    const int lrow  = lane & 15;
    const int lcoff = (lane >> 4) * 8;
    const int brow  = (lane & 7) + ((lane >> 4) << 3);
    const int bcoff = ((lane >> 3) & 1) * 8;

    const __half* kg = Kf + (((size_t)bi * NKV + kh) * SEQ) * HD;
    const __half* vg = Vf + (((size_t)bi * NKV + kh) * HD) * SEQ;
    const uint32_t skv = (uint32_t)__cvta_generic_to_shared(sKV);

    int kr[4], kc[4], vr[4], vc[4];
    uint32_t kso[4], vso[4];
#pragma unroll
    for (int j = 0; j < 4; j++) {
        int c = tid + j * 256;
        kr[j] = c >> 4; kc[j] = (c & 15) * 8;
        kso[j] = (uint32_t)(kr[j] * FQP + kc[j]);
        vr[j] = c >> 3; vc[j] = (c & 7) * 8;
        vso[j] = (uint32_t)(vr[j] * FVP + vc[j]);
    }

    auto issue_kv = [&](int s, int k0) {
        const uint32_t st = skv + (uint32_t)(s * FKV) * 2;
#pragma unroll
        for (int j = 0; j < 4; j++) {
            cp16(st + kso[j] * 2,                  kg + (size_t)(k0 + kr[j]) * HD + kc[j]);
            cp16(st + (64 * FQP + vso[j]) * 2,     vg + (size_t)vr[j] * SEQ + k0 + vc[j]);
        }
        CP_COMMIT();
    };

    // Q tile load (128 x 128, single fp16)
    {
        const __half* qg = Qf + (((size_t)bi * NH + h) * SEQ + q0) * HD;
        for (int i = tid; i < 128 * 16; i += 256) {
            int r = i >> 4, c = (i & 15) * 8;
            *(uint4*)&sQ[r * FQP + c] = *(const uint4*)&qg[(size_t)r * HD + c];
        }
    }

    float o[16][4];
#pragma unroll
    for (int nt = 0; nt < 16; nt++)
#pragma unroll
        for (int e = 0; e < 4; e++) o[nt][e] = 0.f;
    float m0 = -1e30f, m1 = -1e30f, l0 = 0.f, l1 = 0.f;

    const int ntiles = 2 * qtile + 2;

    issue_kv(0, 0);   // prologue

    for (int t = 0; t < ntiles; ++t) {
        const int k0 = t * 64;
        const __half* cur = sKV + (size_t)(t & 1) * FKV;
        const __half* sK = cur;
        const __half* sV = cur + 64 * FQP;

        CP_WAIT(0);
        __syncthreads();

        if (t + 1 < ntiles) issue_kv((t + 1) & 1, (t + 1) * 64);

        float s[8][4];
#pragma unroll
        for (int nt = 0; nt < 8; nt++)
#pragma unroll
            for (int e = 0; e < 4; e++) s[nt][e] = 0.f;

#pragma unroll
        for (int kk = 0; kk < 128; kk += 16) {
            uint32_t af[4];
            const int acol = kk + lcoff;
            ldsm4(af, &sQ[(wid * 16 + lrow) * FQP + acol]);
#pragma unroll
            for (int np = 0; np < 4; np++) {
                const int br = np * 16 + brow;
                const int bc = kk + bcoff;
                uint32_t bh[4];
                ldsm4(bh, &sK[br * FQP + bc]);
                mma16816(s[2 * np    ], af, bh);
                mma16816(s[2 * np + 1], af, bh + 2);
            }
        }

        if (t >= ntiles - 2) {   // causal mask (last two tiles span the diagonal)
            const int r0 = q0 + wid * 16 + grp;
#pragma unroll
            for (int nt = 0; nt < 8; nt++) {
                const int c = k0 + nt * 8 + tig * 2;
                if (c     > r0)     s[nt][0] = -1e30f;
                if (c + 1 > r0)     s[nt][1] = -1e30f;
                if (c     > r0 + 8) s[nt][2] = -1e30f;
                if (c + 1 > r0 + 8) s[nt][3] = -1e30f;
            }
        }

        float mx0 = -1e30f, mx1 = -1e30f;
#pragma unroll
        for (int nt = 0; nt < 8; nt++) {
            mx0 = fmaxf(mx0, fmaxf(s[nt][0], s[nt][1]));
            mx1 = fmaxf(mx1, fmaxf(s[nt][2], s[nt][3]));
        }
        mx0 = fmaxf(mx0, __shfl_xor_sync(0xffffffffu, mx0, 1));
        mx0 = fmaxf(mx0, __shfl_xor_sync(0xffffffffu, mx0, 2));
        mx1 = fmaxf(mx1, __shfl_xor_sync(0xffffffffu, mx1, 1));
        mx1 = fmaxf(mx1, __shfl_xor_sync(0xffffffffu, mx1, 2));

        const float nm0 = fmaxf(m0, mx0);
        const float nm1 = fmaxf(m1, mx1);
        const float a0 = __expf(m0 - nm0);
        const float a1 = __expf(m1 - nm1);
        m0 = nm0; m1 = nm1;

        float rs0 = 0.f, rs1 = 0.f;
#pragma unroll
        for (int nt = 0; nt < 8; nt++) {
            s[nt][0] = __expf(s[nt][0] - m0);
            s[nt][1] = __expf(s[nt][1] - m0);
            s[nt][2] = __expf(s[nt][2] - m1);
            s[nt][3] = __expf(s[nt][3] - m1);
            rs0 += s[nt][0] + s[nt][1];
            rs1 += s[nt][2] + s[nt][3];
        }
        rs0 += __shfl_xor_sync(0xffffffffu, rs0, 1);
        rs0 += __shfl_xor_sync(0xffffffffu, rs0, 2);
        rs1 += __shfl_xor_sync(0xffffffffu, rs1, 1);
        rs1 += __shfl_xor_sync(0xffffffffu, rs1, 2);
        l0 = l0 * a0 + rs0;
        l1 = l1 * a1 + rs1;

#pragma unroll
        for (int nt = 0; nt < 16; nt++) {
            o[nt][0] *= a0; o[nt][1] *= a0;
            o[nt][2] *= a1; o[nt][3] *= a1;
        }

        // O += P @ V  (P single fp16)
#pragma unroll
        for (int ks = 0; ks < 4; ks++) {
            uint32_t ph[4];
            ph[0] = pack2f16(s[2 * ks][0],     s[2 * ks][1]);
            ph[1] = pack2f16(s[2 * ks][2],     s[2 * ks][3]);
            ph[2] = pack2f16(s[2 * ks + 1][0], s[2 * ks + 1][1]);
            ph[3] = pack2f16(s[2 * ks + 1][2], s[2 * ks + 1][3]);
            const int bc = ks * 16 + bcoff;
#pragma unroll
            for (int np = 0; np < 8; np++) {
                const int br = np * 16 + brow;
                uint32_t vh4[4];
                ldsm4(vh4, &sV[br * FVP + bc]);
                mma16816(o[2 * np    ], ph, vh4);
                mma16816(o[2 * np + 1], ph, vh4 + 2);
            }
        }
    }

    // epilogue: normalize and write single fp16 (b*s, H*D)
    const float i0 = 1.0f / l0;
    const float i1 = 1.0f / l1;
    const size_t row0 = (size_t)bi * SEQ + q0 + wid * 16 + grp;
    const size_t row1 = row0 + 8;
    const int colb = h * HD + tig * 2;
#pragma unroll
    for (int nt = 0; nt < 16; nt++) {
        *(uint32_t*)&Oa[row0 * (NH * HD) + colb + nt * 8] =
            pack2f16(o[nt][0] * i0, o[nt][1] * i0);
        *(uint32_t*)&Oa[row1 * (NH * HD) + colb + nt * 8] =
            pack2f16(o[nt][2] * i1, o[nt][3] * i1);
    }
}

// ---------------------------------------------------------------------------
// kernel_launch
// ---------------------------------------------------------------------------
extern "C" void kernel_launch(void* const* d_in, const int* in_sizes, int n_in,
                              void* d_out, int out_size)
{
    const float* hidden = (const float*)d_in[0];
    const float* cosb   = (const float*)d_in[1];
    const float* sinb   = (const float*)d_in[2];
    const float* wq     = (const float*)d_in[3];
    const float* wk     = (const float*)d_in[4];
    const float* wv     = (const float*)d_in[5];
    const float* wo     = (const float*)d_in[6];
    const float* qg     = (const float*)d_in[7];
    const float* kg     = (const float*)d_in[8];

    float* out  = (float*)d_out;
    float* kout = out  + (size_t)NB * SEQ * HDIM;
    float* vout = kout + (size_t)NB * NKV * SEQ * HD;

    __half *hidf, *wqkvf, *wof, *ao, *qkv, *qf, *kf, *vf;
    cudaGetSymbolAddress((void**)&hidf,  g_hid);
    cudaGetSymbolAddress((void**)&wqkvf, g_wqkv);
    cudaGetSymbolAddress((void**)&wof,   g_wo);
    cudaGetSymbolAddress((void**)&ao,    g_ao);
    cudaGetSymbolAddress((void**)&qkv,   g_qkv);
    cudaGetSymbolAddress((void**)&qf,    g_qf);
    cudaGetSymbolAddress((void**)&kf,    g_kf);
    cudaGetSymbolAddress((void**)&vf,    g_vf);

    cudaFuncSetAttribute(flash_mma, cudaFuncAttributeMaxDynamicSharedMemorySize, FLASH_SMEM);
    cudaFuncSetAttribute(gemm_fp16x1<float>,  cudaFuncAttributeMaxDynamicSharedMemorySize, G1_SMEM);
    cudaFuncSetAttribute(gemm_fp16x1<__half>, cudaFuncAttributeMaxDynamicSharedMemorySize, G1_SMEM);

    // fp32 -> fp16 conversions
    const size_t nHid = (size_t)MROWS * HDIM;
    const size_t nWq  = (size_t)NH  * HD * HDIM;
    const size_t nWk  = (size_t)NKV * HD * HDIM;
    conv_fp16<<<(int)(nHid / 1024), 256>>>((const float4*)hidden, hidf);
    conv_fp16<<<(int)(nWq / 1024), 256>>>((const float4*)wq, wqkvf);
    conv_fp16<<<(int)(nWk / 1024), 256>>>((const float4*)wk, wqkvf + nWq);
    conv_fp16<<<(int)(nWk / 1024), 256>>>((const float4*)wv, wqkvf + nWq + nWk);
    conv_fp16<<<(int)(nWq / 1024), 256>>>((const float4*)wo, wof);

    // Fused QKV projection -> fp16 qkv intermediate
    gemm_fp16x1<__half><<<dim3(NQKV / 128, MROWS / 128), 256, G1_SMEM>>>(
        hidf, wqkvf, qkv, MROWS, NQKV, HDIM);

    // RMSNorm + RoPE -> fp16 operands (+ fp32 K into d_out)
    norm_rope_q<<<(MROWS * NH ) / 8, 256>>>(qkv, qf, cosb, sinb, qg);
    norm_rope_k<<<(MROWS * NKV) / 8, 256>>>(qkv, kout, kf, cosb, sinb, kg);

    // V: fp32 into d_out's new_v AND fp16 transposed, single pass
    vtrans_fused<<<dim3(SEQ / 32, HD / 32, NB * NKV), dim3(32, 8)>>>(qkv, vout, vf);

    // Tensor-core causal GQA flash attention (all single fp16) -> fp16 O
    flash_mma<<<dim3(SEQ / 128, NH, NB), 256, FLASH_SMEM>>>(qf, kf, vf, ao);

    // Output projection -> fp32 final out
    gemm_fp16x1<float><<<dim3(HDIM / 128, MROWS / 128), 256, G1_SMEM>>>(
        ao, wof, out, MROWS, HDIM, NH * HD);
}